// round 3
// baseline (speedup 1.0000x reference)
#include <cuda_runtime.h>
#include <math.h>
#include <stdint.h>

// Problem dims (fixed by reference)
#define TT 128
#define BB 128
#define SS 128
#define HH 1024
#define EE 512
#define FH 4096   // 4*H

// ---------------------------------------------------------------------------
// Scratch (device globals: allocation-free contract)
// ---------------------------------------------------------------------------
__device__ float g_gin0[(size_t)TT * BB * FH];   // precomputed layer-0 input proj (256 MB)
__device__ float g_gates[BB * FH];
__device__ float g_h0[BB * HH];
__device__ float g_c0[BB * HH];
__device__ float g_h1[BB * HH];
__device__ float g_c1[BB * HH];
__device__ float g_gamma[BB * HH];
__device__ float g_ctx[BB * HH];

__device__ __forceinline__ float sigmoidf_(float x) {
    return 1.0f / (1.0f + __expf(-x));
}

// ---------------------------------------------------------------------------
// Generic dual-source NT GEMM:
//   C[m,n] = sum_k A1[m,k]*B1[n,k]  (+ sum_k A2[m,k]*B2[n,k])
//            (+ bias1[n]) (+ bias2[n]) (+ Cadd[m,n]) ; optional tanh
// A rows optionally gathered through gidx (embedding lookup), source-0 only.
// All dims assumed multiples of tile sizes (true for this problem).
// ---------------------------------------------------------------------------
template <int BM, int BN, int TM, int TN>
__global__ void gemm2_kernel(
    int M, int N,
    const float* __restrict__ A1, int lda1,
    const float* __restrict__ B1, int ldb1, int K1,
    const float* __restrict__ A2, int lda2,
    const float* __restrict__ B2, int ldb2, int K2,
    const float* __restrict__ bias1,
    const float* __restrict__ bias2,
    const float* __restrict__ Cadd, int ldadd,
    float* __restrict__ C, int ldc,
    int act,
    const int* __restrict__ gidx)
{
    constexpr int BK = 16;
    constexpr int NT = (BM / TM) * (BN / TN);

    __shared__ float As[BK][BM];
    __shared__ float Bs[BK][BN];

    const int tid = threadIdx.x;
    const int tx  = tid % (BN / TN);
    const int ty  = tid / (BN / TN);
    const int row0 = blockIdx.y * BM;
    const int col0 = blockIdx.x * BN;

    float acc[TM][TN];
#pragma unroll
    for (int i = 0; i < TM; i++)
#pragma unroll
        for (int j = 0; j < TN; j++) acc[i][j] = 0.0f;

    for (int src = 0; src < 2; ++src) {
        const float* A  = src ? A2 : A1;
        if (A == nullptr) continue;
        const float* Bm = src ? B2 : B1;
        const int lda   = src ? lda2 : lda1;
        const int ldb   = src ? ldb2 : ldb1;
        const int K     = src ? K2 : K1;
        const bool use_gidx = (src == 0) && (gidx != nullptr);

        for (int k0 = 0; k0 < K; k0 += BK) {
            // Load A tile (transposed into As[k][m]); float4 along K.
            for (int id = tid; id < BM * 4; id += NT) {
                const int r  = id >> 2;
                const int kq = id & 3;
                size_t rowoff;
                if (use_gidx) rowoff = (size_t)gidx[row0 + r] * (size_t)lda;
                else          rowoff = (size_t)(row0 + r) * (size_t)lda;
                float4 v = *reinterpret_cast<const float4*>(&A[rowoff + k0 + kq * 4]);
                As[kq * 4 + 0][r] = v.x;
                As[kq * 4 + 1][r] = v.y;
                As[kq * 4 + 2][r] = v.z;
                As[kq * 4 + 3][r] = v.w;
            }
            // Load B tile (W is [N,K] row-major, K contiguous).
            for (int id = tid; id < BN * 4; id += NT) {
                const int r  = id >> 2;
                const int kq = id & 3;
                float4 v = *reinterpret_cast<const float4*>(
                    &Bm[(size_t)(col0 + r) * (size_t)ldb + k0 + kq * 4]);
                Bs[kq * 4 + 0][r] = v.x;
                Bs[kq * 4 + 1][r] = v.y;
                Bs[kq * 4 + 2][r] = v.z;
                Bs[kq * 4 + 3][r] = v.w;
            }
            __syncthreads();

#pragma unroll
            for (int kk = 0; kk < BK; ++kk) {
                float a[TM], b[TN];
#pragma unroll
                for (int i = 0; i < TM; i++) a[i] = As[kk][ty * TM + i];
#pragma unroll
                for (int j = 0; j < TN; j++) b[j] = Bs[kk][tx * TN + j];
#pragma unroll
                for (int i = 0; i < TM; i++)
#pragma unroll
                    for (int j = 0; j < TN; j++)
                        acc[i][j] = fmaf(a[i], b[j], acc[i][j]);
            }
            __syncthreads();
        }
    }

    // Epilogue
#pragma unroll
    for (int i = 0; i < TM; i++) {
        const int r = row0 + ty * TM + i;
#pragma unroll
        for (int j = 0; j < TN; j++) {
            const int cn = col0 + tx * TN + j;
            float v = acc[i][j];
            if (bias1) v += bias1[cn];
            if (bias2) v += bias2[cn];
            if (Cadd)  v += Cadd[(size_t)r * (size_t)ldadd + cn];
            if (act == 1) v = tanhf(v);
            C[(size_t)r * (size_t)ldc + cn] = v;
        }
    }
}

// ---------------------------------------------------------------------------
// LSTM cell elementwise: gates layout [B, 4H] in (i,f,g,o) blocks.
// ---------------------------------------------------------------------------
__global__ void lstm_cell_kernel(const float* __restrict__ gates,
                                 float* __restrict__ h,
                                 float* __restrict__ c)
{
    const int idx = blockIdx.x * blockDim.x + threadIdx.x;  // over B*H
    const int b = idx / HH;
    const int j = idx - b * HH;
    const float* g = gates + (size_t)b * FH;
    const float ig = sigmoidf_(g[j]);
    const float fg = sigmoidf_(g[HH + j]);
    const float gg = tanhf(g[2 * HH + j]);
    const float og = sigmoidf_(g[3 * HH + j]);
    const float cn = fg * c[idx] + ig * gg;
    c[idx] = cn;
    h[idx] = og * tanhf(cn);
}

// ---------------------------------------------------------------------------
// Fused Luong attention: scores -> softmax -> weighted context.
// One block per batch element. contexts is L2-resident (64 MB).
// ---------------------------------------------------------------------------
__global__ void attention_kernel(const float* __restrict__ contexts,
                                 const float* __restrict__ gamma,
                                 float* __restrict__ ctx_out)
{
    __shared__ float sg[HH];
    __shared__ float sw[SS];
    __shared__ float red[8];
    __shared__ float s_stat;

    const int b    = blockIdx.x;
    const int tid  = threadIdx.x;   // 256 threads
    const int lane = tid & 31;
    const int warp = tid >> 5;
    const float* cb = contexts + (size_t)b * SS * HH;

    for (int j = tid; j < HH; j += 256) sg[j] = gamma[(size_t)b * HH + j];
    __syncthreads();

    // scores[s] = dot(contexts[b,s,:], gamma[b,:]), one warp per s
    for (int s = warp; s < SS; s += 8) {
        const float* cr = cb + (size_t)s * HH;
        float sum = 0.0f;
#pragma unroll 4
        for (int j = lane * 4; j < HH; j += 128) {
            float4 v = *reinterpret_cast<const float4*>(&cr[j]);
            sum = fmaf(v.x, sg[j], sum);
            sum = fmaf(v.y, sg[j + 1], sum);
            sum = fmaf(v.z, sg[j + 2], sum);
            sum = fmaf(v.w, sg[j + 3], sum);
        }
#pragma unroll
        for (int off = 16; off; off >>= 1)
            sum += __shfl_xor_sync(0xffffffffu, sum, off);
        if (lane == 0) sw[s] = sum;
    }
    __syncthreads();

    // softmax over S=128
    const float v = (tid < SS) ? sw[tid] : -3.4e38f;
    float m = v;
#pragma unroll
    for (int off = 16; off; off >>= 1)
        m = fmaxf(m, __shfl_xor_sync(0xffffffffu, m, off));
    if (lane == 0) red[warp] = m;
    __syncthreads();
    if (tid == 0) {
        float mm = red[0];
        for (int w2 = 1; w2 < 8; w2++) mm = fmaxf(mm, red[w2]);
        s_stat = mm;
    }
    __syncthreads();
    const float bm = s_stat;
    const float e = (tid < SS) ? __expf(v - bm) : 0.0f;
    float s2 = e;
#pragma unroll
    for (int off = 16; off; off >>= 1)
        s2 += __shfl_xor_sync(0xffffffffu, s2, off);
    if (lane == 0) red[warp] = s2;
    __syncthreads();
    if (tid == 0) {
        float t = 0.0f;
        for (int w2 = 0; w2 < 8; w2++) t += red[w2];
        s_stat = 1.0f / t;
    }
    __syncthreads();
    if (tid < SS) sw[tid] = e * s_stat;
    __syncthreads();

    // ctx[j] = sum_s w[s] * contexts[b,s,j]; thread handles j = tid + q*256
    float acc[4] = {0.0f, 0.0f, 0.0f, 0.0f};
    for (int s = 0; s < SS; s++) {
        const float w = sw[s];
        const float* cr = cb + (size_t)s * HH;
#pragma unroll
        for (int q = 0; q < 4; q++)
            acc[q] = fmaf(w, cr[tid + q * 256], acc[q]);
    }
#pragma unroll
    for (int q = 0; q < 4; q++)
        ctx_out[(size_t)b * HH + tid + q * 256] = acc[q];
}

// ---------------------------------------------------------------------------
// State init / final writeback
// ---------------------------------------------------------------------------
__global__ void init_state_kernel(const float* __restrict__ h0,
                                  const float* __restrict__ c0)
{
    const int idx = blockIdx.x * blockDim.x + threadIdx.x;  // over B*H
    g_h0[idx] = h0[idx];
    g_c0[idx] = c0[idx];
    g_h1[idx] = h0[BB * HH + idx];
    g_c1[idx] = c0[BB * HH + idx];
}

__global__ void write_final_kernel(float* __restrict__ out)
{
    const int idx = blockIdx.x * blockDim.x + threadIdx.x;  // over B*H
    out[idx]                 = g_h0[idx];   // hT layer 0
    out[BB * HH + idx]       = g_h1[idx];   // hT layer 1
    out[2 * BB * HH + idx]   = g_c0[idx];   // cT layer 0
    out[3 * BB * HH + idx]   = g_c1[idx];   // cT layer 1
}

// ---------------------------------------------------------------------------
// Launch
// ---------------------------------------------------------------------------
extern "C" void kernel_launch(void* const* d_in, const int* in_sizes, int n_in,
                              void* d_out, int out_size)
{
    (void)in_sizes; (void)n_in; (void)out_size;

    const int*   inputs   = (const int*)  d_in[0];
    const float* h0       = (const float*)d_in[1];
    const float* c0       = (const float*)d_in[2];
    const float* contexts = (const float*)d_in[3];
    const float* emb      = (const float*)d_in[4];
    const float* W_ih0    = (const float*)d_in[5];
    const float* W_hh0    = (const float*)d_in[6];
    const float* b_ih0    = (const float*)d_in[7];
    const float* b_hh0    = (const float*)d_in[8];
    const float* W_ih1    = (const float*)d_in[9];
    const float* W_hh1    = (const float*)d_in[10];
    const float* b_ih1    = (const float*)d_in[11];
    const float* b_hh1    = (const float*)d_in[12];
    const float* attW     = (const float*)d_in[13];
    const float* attb     = (const float*)d_in[14];
    const float* outW     = (const float*)d_in[15];
    const float* outb     = (const float*)d_in[16];
    float* out = (float*)d_out;

    static float* p_gin0  = nullptr;
    static float* p_gates = nullptr;
    static float* p_h0    = nullptr;
    static float* p_c0    = nullptr;
    static float* p_h1    = nullptr;
    static float* p_c1    = nullptr;
    static float* p_gamma = nullptr;
    static float* p_ctx   = nullptr;
    if (!p_gin0) {
        cudaGetSymbolAddress((void**)&p_gin0,  g_gin0);
        cudaGetSymbolAddress((void**)&p_gates, g_gates);
        cudaGetSymbolAddress((void**)&p_h0,    g_h0);
        cudaGetSymbolAddress((void**)&p_c0,    g_c0);
        cudaGetSymbolAddress((void**)&p_h1,    g_h1);
        cudaGetSymbolAddress((void**)&p_c1,    g_c1);
        cudaGetSymbolAddress((void**)&p_gamma, g_gamma);
        cudaGetSymbolAddress((void**)&p_ctx,   g_ctx);
    }

    const int BH_BLOCKS = (BB * HH) / 256;  // 512

    // 0) init recurrent state
    init_state_kernel<<<BH_BLOCKS, 256>>>(h0, c0);

    // 1) time-parallel layer-0 input projection:
    //    g_gin0[t*B+b, :] = emb[inputs[t,b]] @ W_ih0^T + b_ih0 + b_hh0
    {
        dim3 grid(FH / 64, (TT * BB) / 64);
        gemm2_kernel<64, 64, 4, 4><<<grid, 256>>>(
            TT * BB, FH,
            emb, EE, W_ih0, EE, EE,
            nullptr, 0, nullptr, 0, 0,
            b_ih0, b_hh0,
            nullptr, 0,
            p_gin0, FH, 0,
            inputs);
    }

    // 2) sequential loop
    for (int t = 0; t < TT; t++) {
        // layer 0: gates = gin0[t] + h0 @ W_hh0^T
        {
            dim3 grid(FH / 64, BB / 32);  // 64 x 4 = 256 blocks
            gemm2_kernel<32, 64, 2, 4><<<grid, 256>>>(
                BB, FH,
                p_h0, HH, W_hh0, HH, HH,
                nullptr, 0, nullptr, 0, 0,
                nullptr, nullptr,
                p_gin0 + (size_t)t * BB * FH, FH,
                p_gates, FH, 0, nullptr);
        }
        lstm_cell_kernel<<<BH_BLOCKS, 256>>>(p_gates, p_h0, p_c0);

        // layer 1: gates = h0_new @ W_ih1^T + h1 @ W_hh1^T + b_ih1 + b_hh1
        {
            dim3 grid(FH / 64, BB / 32);
            gemm2_kernel<32, 64, 2, 4><<<grid, 256>>>(
                BB, FH,
                p_h0, HH, W_ih1, HH, HH,
                p_h1, HH, W_hh1, HH, HH,
                b_ih1, b_hh1,
                nullptr, 0,
                p_gates, FH, 0, nullptr);
        }
        lstm_cell_kernel<<<BH_BLOCKS, 256>>>(p_gates, p_h1, p_c1);

        // attention-in: gamma = h1 @ attW^T + attb
        {
            dim3 grid(HH / 64, BB / 16);  // 16 x 8 = 128 blocks
            gemm2_kernel<16, 64, 1, 4><<<grid, 256>>>(
                BB, HH,
                p_h1, HH, attW, HH, HH,
                nullptr, 0, nullptr, 0, 0,
                attb, nullptr,
                nullptr, 0,
                p_gamma, HH, 0, nullptr);
        }

        // scores + softmax + context
        attention_kernel<<<BB, 256>>>(contexts, p_gamma, p_ctx);

        // out[t] = tanh([ctx, h1] @ outW^T + outb)  (dual-source, no concat)
        {
            dim3 grid(HH / 64, BB / 16);
            gemm2_kernel<16, 64, 1, 4><<<grid, 256>>>(
                BB, HH,
                p_ctx, HH, outW, 2 * HH, HH,
                p_h1,  HH, outW + HH, 2 * HH, HH,
                outb, nullptr,
                nullptr, 0,
                out + (size_t)t * BB * HH, HH, 1, nullptr);
        }
    }

    // 3) final hT / cT
    write_final_kernel<<<BH_BLOCKS, 256>>>(out + (size_t)TT * BB * HH);
}

// round 4
// speedup vs baseline: 1.5331x; 1.5331x over previous
#include <cuda_runtime.h>
#include <math.h>
#include <stdint.h>

// Problem dims (fixed by reference)
#define TT 128
#define BB 128
#define SS 128
#define HH 1024
#define EE 512
#define FH 4096   // 4*H

// ---------------------------------------------------------------------------
// Scratch (device globals: allocation-free contract)
// ---------------------------------------------------------------------------
__device__ float g_gin0[(size_t)TT * BB * FH];   // precomputed layer-0 input proj (256 MB)
__device__ float g_gates[BB * FH];
__device__ float g_h0[BB * HH];
__device__ float g_c0[BB * HH];
__device__ float g_h1[BB * HH];
__device__ float g_c1[BB * HH];
__device__ float g_gamma[BB * HH];
__device__ float g_ctx[BB * HH];

__device__ __forceinline__ float sigmoidf_(float x) {
    return 1.0f / (1.0f + __expf(-x));
}

__device__ __forceinline__ uint32_t f2tf32(float f) {
    uint32_t u;
    asm("cvt.rna.tf32.f32 %0, %1;" : "=r"(u) : "f"(f));
    return u;
}

__device__ __forceinline__ void mma_tf32(float* d, const uint32_t* a, const uint32_t* b) {
    asm volatile(
        "mma.sync.aligned.m16n8k8.row.col.f32.tf32.tf32.f32 "
        "{%0,%1,%2,%3}, {%4,%5,%6,%7}, {%8,%9}, {%0,%1,%2,%3};\n"
        : "+f"(d[0]), "+f"(d[1]), "+f"(d[2]), "+f"(d[3])
        : "r"(a[0]), "r"(a[1]), "r"(a[2]), "r"(a[3]), "r"(b[0]), "r"(b[1]));
}

// ---------------------------------------------------------------------------
// Tensor-core dual-source NT GEMM with error-free 3xTF32 split:
//   C[m,n] = sum_k A1[m,k]*B1[n,k]  (+ sum_k A2[m,k]*B2[n,k])
//            (+ bias1[n]) (+ bias2[n]) (+ Cadd[m,n]) ; optional tanh
// A rows optionally gathered through gidx (source-0 only).
// M % BM == 0, N % BN == 0, K % 16 == 0 required (true for this problem).
// ---------------------------------------------------------------------------
template <int BM, int BN, int WARPS_M, int WARPS_N>
__global__ __launch_bounds__(WARPS_M * WARPS_N * 32)
void mma_gemm_kernel(
    const float* __restrict__ A1, int lda1,
    const float* __restrict__ B1, int ldb1, int K1,
    const float* __restrict__ A2, int lda2,
    const float* __restrict__ B2, int ldb2, int K2,
    const float* __restrict__ bias1,
    const float* __restrict__ bias2,
    const float* __restrict__ Cadd, int ldadd,
    float* __restrict__ C, int ldc,
    int act,
    const int* __restrict__ gidx)
{
    constexpr int BK = 16;
    constexpr int NT = WARPS_M * WARPS_N * 32;
    constexpr int WM = BM / WARPS_M;
    constexpr int WN = BN / WARPS_N;
    constexpr int RM = WM / 16;
    constexpr int RN = WN / 8;
    constexpr int AV = (BM * BK) / (4 * NT);   // float4 loads per thread (A tile)
    constexpr int BV = (BN * BK) / (4 * NT);
    constexpr int LD = BK + 1;                 // padded smem row (conflict-free)

    __shared__ uint32_t sAh[BM][LD];
    __shared__ uint32_t sAl[BM][LD];
    __shared__ uint32_t sBh[BN][LD];
    __shared__ uint32_t sBl[BN][LD];

    const int tid  = threadIdx.x;
    const int lane = tid & 31;
    const int warp = tid >> 5;
    const int wm = (warp / WARPS_N) * WM;
    const int wn = (warp % WARPS_N) * WN;
    const int row0 = blockIdx.y * BM;
    const int col0 = blockIdx.x * BN;

    float acc[RM][RN][4];
#pragma unroll
    for (int mi = 0; mi < RM; mi++)
#pragma unroll
        for (int ni = 0; ni < RN; ni++)
#pragma unroll
            for (int q = 0; q < 4; q++) acc[mi][ni][q] = 0.0f;

    for (int src = 0; src < 2; ++src) {
        const float* A  = src ? A2 : A1;
        if (A == nullptr) continue;
        const float* Bm = src ? B2 : B1;
        const int lda   = src ? lda2 : lda1;
        const int ldb   = src ? ldb2 : ldb1;
        const int K     = src ? K2 : K1;
        const bool use_gidx = (src == 0) && (gidx != nullptr);
        const int niter = K / BK;

        float4 va[AV], vb[BV];

        // prefetch tile 0
#pragma unroll
        for (int i = 0; i < AV; i++) {
            const int s = tid + i * NT;
            const int m = s / (BK / 4), kq = s % (BK / 4);
            size_t ro = use_gidx ? (size_t)gidx[row0 + m] * (size_t)lda
                                 : (size_t)(row0 + m) * (size_t)lda;
            va[i] = *reinterpret_cast<const float4*>(&A[ro + kq * 4]);
        }
#pragma unroll
        for (int i = 0; i < BV; i++) {
            const int s = tid + i * NT;
            const int n = s / (BK / 4), kq = s % (BK / 4);
            vb[i] = *reinterpret_cast<const float4*>(&Bm[(size_t)(col0 + n) * (size_t)ldb + kq * 4]);
        }

        for (int it = 0; it < niter; ++it) {
            // split + store current tile
#pragma unroll
            for (int i = 0; i < AV; i++) {
                const int s = tid + i * NT;
                const int m = s / (BK / 4), kq = s % (BK / 4);
                const float f[4] = { va[i].x, va[i].y, va[i].z, va[i].w };
#pragma unroll
                for (int j = 0; j < 4; j++) {
                    const uint32_t h = f2tf32(f[j]);
                    sAh[m][kq * 4 + j] = h;
                    sAl[m][kq * 4 + j] = f2tf32(f[j] - __uint_as_float(h));
                }
            }
#pragma unroll
            for (int i = 0; i < BV; i++) {
                const int s = tid + i * NT;
                const int n = s / (BK / 4), kq = s % (BK / 4);
                const float f[4] = { vb[i].x, vb[i].y, vb[i].z, vb[i].w };
#pragma unroll
                for (int j = 0; j < 4; j++) {
                    const uint32_t h = f2tf32(f[j]);
                    sBh[n][kq * 4 + j] = h;
                    sBl[n][kq * 4 + j] = f2tf32(f[j] - __uint_as_float(h));
                }
            }
            __syncthreads();

            // prefetch next tile (LDG latency overlapped with mma section)
            if (it + 1 < niter) {
                const int k0 = (it + 1) * BK;
#pragma unroll
                for (int i = 0; i < AV; i++) {
                    const int s = tid + i * NT;
                    const int m = s / (BK / 4), kq = s % (BK / 4);
                    size_t ro = use_gidx ? (size_t)gidx[row0 + m] * (size_t)lda
                                         : (size_t)(row0 + m) * (size_t)lda;
                    va[i] = *reinterpret_cast<const float4*>(&A[ro + k0 + kq * 4]);
                }
#pragma unroll
                for (int i = 0; i < BV; i++) {
                    const int s = tid + i * NT;
                    const int n = s / (BK / 4), kq = s % (BK / 4);
                    vb[i] = *reinterpret_cast<const float4*>(
                        &Bm[(size_t)(col0 + n) * (size_t)ldb + k0 + kq * 4]);
                }
            }

            // mma over the BK=16 tile (two k=8 atoms), 3xTF32 split
#pragma unroll
            for (int kq = 0; kq < 2; kq++) {
                uint32_t ah[RM][4], al[RM][4], bh[RN][2], bl[RN][2];
                const int kb = kq * 8 + (lane & 3);
#pragma unroll
                for (int mi = 0; mi < RM; mi++) {
                    const int r = wm + mi * 16 + (lane >> 2);
                    ah[mi][0] = sAh[r][kb];     ah[mi][1] = sAh[r + 8][kb];
                    ah[mi][2] = sAh[r][kb + 4]; ah[mi][3] = sAh[r + 8][kb + 4];
                    al[mi][0] = sAl[r][kb];     al[mi][1] = sAl[r + 8][kb];
                    al[mi][2] = sAl[r][kb + 4]; al[mi][3] = sAl[r + 8][kb + 4];
                }
#pragma unroll
                for (int ni = 0; ni < RN; ni++) {
                    const int cn = wn + ni * 8 + (lane >> 2);
                    bh[ni][0] = sBh[cn][kb]; bh[ni][1] = sBh[cn][kb + 4];
                    bl[ni][0] = sBl[cn][kb]; bl[ni][1] = sBl[cn][kb + 4];
                }
#pragma unroll
                for (int mi = 0; mi < RM; mi++)
#pragma unroll
                    for (int ni = 0; ni < RN; ni++) {
                        mma_tf32(acc[mi][ni], ah[mi], bh[ni]);  // hi*hi
                        mma_tf32(acc[mi][ni], ah[mi], bl[ni]);  // hi*lo
                        mma_tf32(acc[mi][ni], al[mi], bh[ni]);  // lo*hi
                    }
            }
            __syncthreads();
        }
    }

    // Epilogue: fragment layout c0,c1 = (row, 2*(lane%4)+{0,1}), c2,c3 = row+8
#pragma unroll
    for (int mi = 0; mi < RM; mi++) {
#pragma unroll
        for (int ni = 0; ni < RN; ni++) {
            const int c = col0 + wn + ni * 8 + 2 * (lane & 3);
#pragma unroll
            for (int hrow = 0; hrow < 2; hrow++) {
                const int r = row0 + wm + mi * 16 + (lane >> 2) + 8 * hrow;
                float v0 = acc[mi][ni][2 * hrow + 0];
                float v1 = acc[mi][ni][2 * hrow + 1];
                if (bias1) { v0 += bias1[c]; v1 += bias1[c + 1]; }
                if (bias2) { v0 += bias2[c]; v1 += bias2[c + 1]; }
                if (Cadd) {
                    v0 += Cadd[(size_t)r * (size_t)ldadd + c];
                    v1 += Cadd[(size_t)r * (size_t)ldadd + c + 1];
                }
                if (act == 1) { v0 = tanhf(v0); v1 = tanhf(v1); }
                *reinterpret_cast<float2*>(&C[(size_t)r * (size_t)ldc + c]) =
                    make_float2(v0, v1);
            }
        }
    }
}

// ---------------------------------------------------------------------------
// LSTM cell elementwise: gates layout [B, 4H] in (i,f,g,o) blocks.
// ---------------------------------------------------------------------------
__global__ void lstm_cell_kernel(const float* __restrict__ gates,
                                 float* __restrict__ h,
                                 float* __restrict__ c)
{
    const int idx = blockIdx.x * blockDim.x + threadIdx.x;  // over B*H
    const int b = idx / HH;
    const int j = idx - b * HH;
    const float* g = gates + (size_t)b * FH;
    const float ig = sigmoidf_(g[j]);
    const float fg = sigmoidf_(g[HH + j]);
    const float gg = tanhf(g[2 * HH + j]);
    const float og = sigmoidf_(g[3 * HH + j]);
    const float cn = fg * c[idx] + ig * gg;
    c[idx] = cn;
    h[idx] = og * tanhf(cn);
}

// ---------------------------------------------------------------------------
// Fused Luong attention: scores -> softmax -> weighted context.
// One block per batch element. contexts is L2-resident (64 MB).
// ---------------------------------------------------------------------------
__global__ void attention_kernel(const float* __restrict__ contexts,
                                 const float* __restrict__ gamma,
                                 float* __restrict__ ctx_out)
{
    __shared__ float sg[HH];
    __shared__ float sw[SS];
    __shared__ float red[8];
    __shared__ float s_stat;

    const int b    = blockIdx.x;
    const int tid  = threadIdx.x;   // 256 threads
    const int lane = tid & 31;
    const int warp = tid >> 5;
    const float* cb = contexts + (size_t)b * SS * HH;

    for (int j = tid; j < HH; j += 256) sg[j] = gamma[(size_t)b * HH + j];
    __syncthreads();

    // scores[s] = dot(contexts[b,s,:], gamma[b,:]), one warp per s
    for (int s = warp; s < SS; s += 8) {
        const float* cr = cb + (size_t)s * HH;
        float sum = 0.0f;
#pragma unroll 4
        for (int j = lane * 4; j < HH; j += 128) {
            float4 v = *reinterpret_cast<const float4*>(&cr[j]);
            sum = fmaf(v.x, sg[j], sum);
            sum = fmaf(v.y, sg[j + 1], sum);
            sum = fmaf(v.z, sg[j + 2], sum);
            sum = fmaf(v.w, sg[j + 3], sum);
        }
#pragma unroll
        for (int off = 16; off; off >>= 1)
            sum += __shfl_xor_sync(0xffffffffu, sum, off);
        if (lane == 0) sw[s] = sum;
    }
    __syncthreads();

    // softmax over S=128
    const float v = (tid < SS) ? sw[tid] : -3.4e38f;
    float m = v;
#pragma unroll
    for (int off = 16; off; off >>= 1)
        m = fmaxf(m, __shfl_xor_sync(0xffffffffu, m, off));
    if (lane == 0) red[warp] = m;
    __syncthreads();
    if (tid == 0) {
        float mm = red[0];
        for (int w2 = 1; w2 < 8; w2++) mm = fmaxf(mm, red[w2]);
        s_stat = mm;
    }
    __syncthreads();
    const float bm = s_stat;
    const float e = (tid < SS) ? __expf(v - bm) : 0.0f;
    float s2 = e;
#pragma unroll
    for (int off = 16; off; off >>= 1)
        s2 += __shfl_xor_sync(0xffffffffu, s2, off);
    if (lane == 0) red[warp] = s2;
    __syncthreads();
    if (tid == 0) {
        float t = 0.0f;
        for (int w2 = 0; w2 < 8; w2++) t += red[w2];
        s_stat = 1.0f / t;
    }
    __syncthreads();
    if (tid < SS) sw[tid] = e * s_stat;
    __syncthreads();

    // ctx[j] = sum_s w[s] * contexts[b,s,j]
    float acc[4] = {0.0f, 0.0f, 0.0f, 0.0f};
    for (int s = 0; s < SS; s++) {
        const float w = sw[s];
        const float* cr = cb + (size_t)s * HH;
#pragma unroll
        for (int q = 0; q < 4; q++)
            acc[q] = fmaf(w, cr[tid + q * 256], acc[q]);
    }
#pragma unroll
    for (int q = 0; q < 4; q++)
        ctx_out[(size_t)b * HH + tid + q * 256] = acc[q];
}

// ---------------------------------------------------------------------------
// State init / final writeback
// ---------------------------------------------------------------------------
__global__ void init_state_kernel(const float* __restrict__ h0,
                                  const float* __restrict__ c0)
{
    const int idx = blockIdx.x * blockDim.x + threadIdx.x;  // over B*H
    g_h0[idx] = h0[idx];
    g_c0[idx] = c0[idx];
    g_h1[idx] = h0[BB * HH + idx];
    g_c1[idx] = c0[BB * HH + idx];
}

__global__ void write_final_kernel(float* __restrict__ out)
{
    const int idx = blockIdx.x * blockDim.x + threadIdx.x;  // over B*H
    out[idx]                 = g_h0[idx];   // hT layer 0
    out[BB * HH + idx]       = g_h1[idx];   // hT layer 1
    out[2 * BB * HH + idx]   = g_c0[idx];   // cT layer 0
    out[3 * BB * HH + idx]   = g_c1[idx];   // cT layer 1
}

// ---------------------------------------------------------------------------
// Launch
// ---------------------------------------------------------------------------
extern "C" void kernel_launch(void* const* d_in, const int* in_sizes, int n_in,
                              void* d_out, int out_size)
{
    (void)in_sizes; (void)n_in; (void)out_size;

    const int*   inputs   = (const int*)  d_in[0];
    const float* h0       = (const float*)d_in[1];
    const float* c0       = (const float*)d_in[2];
    const float* contexts = (const float*)d_in[3];
    const float* emb      = (const float*)d_in[4];
    const float* W_ih0    = (const float*)d_in[5];
    const float* W_hh0    = (const float*)d_in[6];
    const float* b_ih0    = (const float*)d_in[7];
    const float* b_hh0    = (const float*)d_in[8];
    const float* W_ih1    = (const float*)d_in[9];
    const float* W_hh1    = (const float*)d_in[10];
    const float* b_ih1    = (const float*)d_in[11];
    const float* b_hh1    = (const float*)d_in[12];
    const float* attW     = (const float*)d_in[13];
    const float* attb     = (const float*)d_in[14];
    const float* outW     = (const float*)d_in[15];
    const float* outb     = (const float*)d_in[16];
    float* out = (float*)d_out;

    static float* p_gin0  = nullptr;
    static float* p_gates = nullptr;
    static float* p_h0    = nullptr;
    static float* p_c0    = nullptr;
    static float* p_h1    = nullptr;
    static float* p_c1    = nullptr;
    static float* p_gamma = nullptr;
    static float* p_ctx   = nullptr;
    if (!p_gin0) {
        cudaGetSymbolAddress((void**)&p_gin0,  g_gin0);
        cudaGetSymbolAddress((void**)&p_gates, g_gates);
        cudaGetSymbolAddress((void**)&p_h0,    g_h0);
        cudaGetSymbolAddress((void**)&p_c0,    g_c0);
        cudaGetSymbolAddress((void**)&p_h1,    g_h1);
        cudaGetSymbolAddress((void**)&p_c1,    g_c1);
        cudaGetSymbolAddress((void**)&p_gamma, g_gamma);
        cudaGetSymbolAddress((void**)&p_ctx,   g_ctx);
    }

    const int BH_BLOCKS = (BB * HH) / 256;  // 512

    // 0) init recurrent state
    init_state_kernel<<<BH_BLOCKS, 256>>>(h0, c0);

    // 1) time-parallel layer-0 input projection (gathered through inputs):
    //    g_gin0[t*B+b, :] = emb[inputs[t,b]] @ W_ih0^T + b_ih0 + b_hh0
    {
        dim3 grid(FH / 64, (TT * BB) / 64);
        mma_gemm_kernel<64, 64, 2, 2><<<grid, 128>>>(
            emb, EE, W_ih0, EE, EE,
            nullptr, 0, nullptr, 0, 0,
            b_ih0, b_hh0,
            nullptr, 0,
            p_gin0, FH, 0,
            inputs);
    }

    // 2) sequential loop
    for (int t = 0; t < TT; t++) {
        // layer 0: gates = gin0[t] + h0 @ W_hh0^T
        {
            dim3 grid(FH / 64, BB / 64);  // 64 x 2 = 128 blocks
            mma_gemm_kernel<64, 64, 2, 2><<<grid, 128>>>(
                p_h0, HH, W_hh0, HH, HH,
                nullptr, 0, nullptr, 0, 0,
                nullptr, nullptr,
                p_gin0 + (size_t)t * BB * FH, FH,
                p_gates, FH, 0, nullptr);
        }
        lstm_cell_kernel<<<BH_BLOCKS, 256>>>(p_gates, p_h0, p_c0);

        // layer 1: gates = h0_new @ W_ih1^T + h1 @ W_hh1^T + biases
        {
            dim3 grid(FH / 64, BB / 64);
            mma_gemm_kernel<64, 64, 2, 2><<<grid, 128>>>(
                p_h0, HH, W_ih1, HH, HH,
                p_h1, HH, W_hh1, HH, HH,
                b_ih1, b_hh1,
                nullptr, 0,
                p_gates, FH, 0, nullptr);
        }
        lstm_cell_kernel<<<BH_BLOCKS, 256>>>(p_gates, p_h1, p_c1);

        // attention-in: gamma = h1 @ attW^T + attb
        {
            dim3 grid(HH / 32, BB / 32);  // 32 x 4 = 128 blocks
            mma_gemm_kernel<32, 32, 2, 2><<<grid, 128>>>(
                p_h1, HH, attW, HH, HH,
                nullptr, 0, nullptr, 0, 0,
                attb, nullptr,
                nullptr, 0,
                p_gamma, HH, 0, nullptr);
        }

        // scores + softmax + context
        attention_kernel<<<BB, 256>>>(contexts, p_gamma, p_ctx);

        // out[t] = tanh([ctx, h1] @ outW^T + outb)  (dual-source, no concat)
        {
            dim3 grid(HH / 32, BB / 32);
            mma_gemm_kernel<32, 32, 2, 2><<<grid, 128>>>(
                p_ctx, HH, outW, 2 * HH, HH,
                p_h1,  HH, outW + HH, 2 * HH, HH,
                outb, nullptr,
                nullptr, 0,
                out + (size_t)t * BB * HH, HH, 1, nullptr);
        }
    }

    // 3) final hT / cT
    write_final_kernel<<<BH_BLOCKS, 256>>>(out + (size_t)TT * BB * HH);
}

// round 5
// speedup vs baseline: 1.6425x; 1.0713x over previous
#include <cuda_runtime.h>
#include <math.h>
#include <stdint.h>

// Problem dims (fixed by reference)
#define TT 128
#define BB 128
#define SS 128
#define HH 1024
#define EE 512
#define FH 4096   // 4*H
#define VV 32000

// ---------------------------------------------------------------------------
// Scratch (device globals: allocation-free contract)
// ---------------------------------------------------------------------------
__device__ float g_gin0[(size_t)TT * BB * FH];   // layer-0 input proj (fp32, 256 MB)
__device__ float g_gates[BB * FH];
__device__ float g_h0[BB * HH];
__device__ float g_c0[BB * HH];
__device__ float g_h1[BB * HH];
__device__ float g_c1[BB * HH];
__device__ float g_gamma[BB * HH];

// tf32 (hi,lo) pair buffers — x=hi bits, y=lo bits
__device__ uint2 g_embp [(size_t)VV * EE];
__device__ uint2 g_Wih0p[(size_t)FH * EE];
__device__ uint2 g_Whh0p[(size_t)FH * HH];
__device__ uint2 g_Wih1p[(size_t)FH * HH];
__device__ uint2 g_Whh1p[(size_t)FH * HH];
__device__ uint2 g_attWp[(size_t)HH * HH];
__device__ uint2 g_outWp[(size_t)HH * 2 * HH];
__device__ uint2 g_h0p[BB * HH];
__device__ uint2 g_h1p[BB * HH];
__device__ uint2 g_ctxp[BB * HH];

__device__ __forceinline__ float sigmoidf_(float x) {
    return 1.0f / (1.0f + __expf(-x));
}

__device__ __forceinline__ uint32_t f2tf32(float f) {
    uint32_t u;
    asm("cvt.rna.tf32.f32 %0, %1;" : "=r"(u) : "f"(f));
    return u;
}

__device__ __forceinline__ uint2 splitp(float f) {
    const uint32_t h = f2tf32(f);
    return make_uint2(h, f2tf32(f - __uint_as_float(h)));
}

__device__ __forceinline__ void mma_tf32(float* d, const uint32_t* a, const uint32_t* b) {
    asm volatile(
        "mma.sync.aligned.m16n8k8.row.col.f32.tf32.tf32.f32 "
        "{%0,%1,%2,%3}, {%4,%5,%6,%7}, {%8,%9}, {%0,%1,%2,%3};\n"
        : "+f"(d[0]), "+f"(d[1]), "+f"(d[2]), "+f"(d[3])
        : "r"(a[0]), "r"(a[1]), "r"(a[2]), "r"(a[3]), "r"(b[0]), "r"(b[1]));
}

__device__ __forceinline__ void cp16(void* smem, const void* gmem) {
    uint32_t s;
    asm("{ .reg .u64 t; cvta.to.shared.u64 t, %1; cvt.u32.u64 %0, t; }"
        : "=r"(s) : "l"(smem));
    asm volatile("cp.async.ca.shared.global [%0], [%1], 16;" :: "r"(s), "l"(gmem));
}

// ---------------------------------------------------------------------------
// Pre-split: fp32 -> interleaved tf32 (hi,lo) pairs
// ---------------------------------------------------------------------------
__global__ void split_kernel(const float* __restrict__ src,
                             uint2* __restrict__ dst, int n)
{
    for (int i = blockIdx.x * blockDim.x + threadIdx.x; i < n;
         i += gridDim.x * blockDim.x)
        dst[i] = splitp(src[i]);
}

// ---------------------------------------------------------------------------
// Tensor-core dual-source NT GEMM, pre-split tf32 pairs, cp.async 2-stage:
//   C[m,n] = sum_k A1[m,k]*B1[n,k] (+ sum_k A2[m,k]*B2[n,k])
//            (+bias1[n]) (+bias2[n]) (+Cadd[m,n]) ; optional tanh
// gidx gathers A1 rows (embedding lookup). 128 threads, warps 2x2.
// Smem swizzle: pair k of row n stored at slot k ^ ((n&3)<<2)  (conflict-free).
// ---------------------------------------------------------------------------
template <int BM, int BN>
__global__ __launch_bounds__(128)
void mma_gemm3(
    const uint2* __restrict__ A1, int lda1,
    const uint2* __restrict__ B1, int ldb1, int K1,
    const uint2* __restrict__ A2, int lda2,
    const uint2* __restrict__ B2, int ldb2, int K2,
    const float* __restrict__ bias1,
    const float* __restrict__ bias2,
    const float* __restrict__ Cadd, int ldadd,
    float* __restrict__ C, int ldc,
    int act,
    const int* __restrict__ gidx)
{
    constexpr int WM = BM / 2;
    constexpr int WN = BN / 2;
    constexpr int RM = WM / 16;
    constexpr int RN = WN / 8;
    constexpr int ACH = BM * 8 / 128;   // 16B chunks per thread per A tile
    constexpr int BCH = BN * 8 / 128;

    __shared__ __align__(16) uint2 sA[2][BM][16];
    __shared__ __align__(16) uint2 sB[2][BN][16];

    const int tid  = threadIdx.x;
    const int lane = tid & 31;
    const int warp = tid >> 5;
    const int wm = (warp >> 1) * WM;
    const int wn = (warp & 1) * WN;
    const int row0 = blockIdx.y * BM;
    const int col0 = blockIdx.x * BN;

    float acc[RM][RN][4];
#pragma unroll
    for (int mi = 0; mi < RM; mi++)
#pragma unroll
        for (int ni = 0; ni < RN; ni++)
#pragma unroll
            for (int q = 0; q < 4; q++) acc[mi][ni][q] = 0.0f;

#define LOAD_TILE(buf_, k0_)                                                     \
    do {                                                                         \
        _Pragma("unroll")                                                        \
        for (int i = 0; i < ACH; i++) {                                          \
            const int cch = tid + i * 128;                                       \
            const int n = cch >> 3, j = cch & 7;                                 \
            size_t ro = ug ? (size_t)gidx[row0 + n] * (size_t)lda                \
                           : (size_t)(row0 + n) * (size_t)lda;                   \
            cp16(&sA[buf_][n][(2 * j) ^ ((n & 3) << 2)], A + ro + (k0_) + 2 * j);\
        }                                                                        \
        _Pragma("unroll")                                                        \
        for (int i = 0; i < BCH; i++) {                                          \
            const int cch = tid + i * 128;                                       \
            const int n = cch >> 3, j = cch & 7;                                 \
            cp16(&sB[buf_][n][(2 * j) ^ ((n & 3) << 2)],                         \
                 B + (size_t)(col0 + n) * (size_t)ldb + (k0_) + 2 * j);          \
        }                                                                        \
    } while (0)

    for (int s = 0; s < 2; ++s) {
        const uint2* A = s ? A2 : A1;
        if (A == nullptr) continue;
        const uint2* B = s ? B2 : B1;
        const int lda  = s ? lda2 : lda1;
        const int ldb  = s ? ldb2 : ldb1;
        const int K    = s ? K2 : K1;
        const bool ug  = (s == 0) && (gidx != nullptr);
        const int niter = K >> 4;

        LOAD_TILE(0, 0);
        asm volatile("cp.async.commit_group;");

        for (int it = 0; it < niter; ++it) {
            if (it + 1 < niter) {
                LOAD_TILE((it + 1) & 1, (it + 1) << 4);
                asm volatile("cp.async.commit_group;");
                asm volatile("cp.async.wait_group 1;");
            } else {
                asm volatile("cp.async.wait_group 0;");
            }
            __syncthreads();

            const int buf = it & 1;
#pragma unroll
            for (int kq = 0; kq < 2; kq++) {
                const int kb = kq * 8 + (lane & 3);
                uint32_t ah[RM][4], al[RM][4], bh[RN][2], bl[RN][2];
#pragma unroll
                for (int mi = 0; mi < RM; mi++) {
                    const int r0 = wm + mi * 16 + (lane >> 2);
                    const int r1 = r0 + 8;
                    const int sw = (r0 & 3) << 2;   // r1&3 == r0&3
                    uint2 p0 = sA[buf][r0][kb ^ sw];
                    uint2 p1 = sA[buf][r1][kb ^ sw];
                    uint2 p2 = sA[buf][r0][(kb + 4) ^ sw];
                    uint2 p3 = sA[buf][r1][(kb + 4) ^ sw];
                    ah[mi][0] = p0.x; ah[mi][1] = p1.x; ah[mi][2] = p2.x; ah[mi][3] = p3.x;
                    al[mi][0] = p0.y; al[mi][1] = p1.y; al[mi][2] = p2.y; al[mi][3] = p3.y;
                }
#pragma unroll
                for (int ni = 0; ni < RN; ni++) {
                    const int cn = wn + ni * 8 + (lane >> 2);
                    const int sw = (cn & 3) << 2;
                    uint2 q0 = sB[buf][cn][kb ^ sw];
                    uint2 q1 = sB[buf][cn][(kb + 4) ^ sw];
                    bh[ni][0] = q0.x; bh[ni][1] = q1.x;
                    bl[ni][0] = q0.y; bl[ni][1] = q1.y;
                }
#pragma unroll
                for (int mi = 0; mi < RM; mi++)
#pragma unroll
                    for (int ni = 0; ni < RN; ni++) {
                        mma_tf32(acc[mi][ni], ah[mi], bh[ni]);  // hi*hi
                        mma_tf32(acc[mi][ni], ah[mi], bl[ni]);  // hi*lo
                        mma_tf32(acc[mi][ni], al[mi], bh[ni]);  // lo*hi
                    }
            }
            __syncthreads();
        }
    }
#undef LOAD_TILE

    // Epilogue: fragment layout c0,c1 = (row, 2*(lane%4)+{0,1}), c2,c3 = row+8
#pragma unroll
    for (int mi = 0; mi < RM; mi++) {
#pragma unroll
        for (int ni = 0; ni < RN; ni++) {
            const int c = col0 + wn + ni * 8 + 2 * (lane & 3);
#pragma unroll
            for (int hrow = 0; hrow < 2; hrow++) {
                const int r = row0 + wm + mi * 16 + (lane >> 2) + 8 * hrow;
                float v0 = acc[mi][ni][2 * hrow + 0];
                float v1 = acc[mi][ni][2 * hrow + 1];
                if (bias1) { v0 += bias1[c]; v1 += bias1[c + 1]; }
                if (bias2) { v0 += bias2[c]; v1 += bias2[c + 1]; }
                if (Cadd) {
                    v0 += Cadd[(size_t)r * (size_t)ldadd + c];
                    v1 += Cadd[(size_t)r * (size_t)ldadd + c + 1];
                }
                if (act == 1) { v0 = tanhf(v0); v1 = tanhf(v1); }
                *reinterpret_cast<float2*>(&C[(size_t)r * (size_t)ldc + c]) =
                    make_float2(v0, v1);
            }
        }
    }
}

// ---------------------------------------------------------------------------
// LSTM cell, float4-vectorized; writes h fp32 + h split pairs.
// gates layout [B, 4H] in (i,f,g,o) blocks.
// ---------------------------------------------------------------------------
__global__ void lstm_cell_kernel(const float* __restrict__ gates,
                                 float* __restrict__ h,
                                 float* __restrict__ c,
                                 uint2* __restrict__ hp)
{
    const int t4 = blockIdx.x * blockDim.x + threadIdx.x;   // over B*H/4
    const int b = t4 / (HH / 4);
    const int q = t4 - b * (HH / 4);
    const float* g = gates + (size_t)b * FH + q * 4;
    const float4 gi = *reinterpret_cast<const float4*>(g);
    const float4 gf = *reinterpret_cast<const float4*>(g + HH);
    const float4 gg = *reinterpret_cast<const float4*>(g + 2 * HH);
    const float4 go = *reinterpret_cast<const float4*>(g + 3 * HH);
    const float4 cc = *reinterpret_cast<const float4*>(c + (size_t)t4 * 4);
    float4 cn, hn;
    cn.x = sigmoidf_(gf.x) * cc.x + sigmoidf_(gi.x) * tanhf(gg.x);
    cn.y = sigmoidf_(gf.y) * cc.y + sigmoidf_(gi.y) * tanhf(gg.y);
    cn.z = sigmoidf_(gf.z) * cc.z + sigmoidf_(gi.z) * tanhf(gg.z);
    cn.w = sigmoidf_(gf.w) * cc.w + sigmoidf_(gi.w) * tanhf(gg.w);
    hn.x = sigmoidf_(go.x) * tanhf(cn.x);
    hn.y = sigmoidf_(go.y) * tanhf(cn.y);
    hn.z = sigmoidf_(go.z) * tanhf(cn.z);
    hn.w = sigmoidf_(go.w) * tanhf(cn.w);
    *reinterpret_cast<float4*>(c + (size_t)t4 * 4) = cn;
    *reinterpret_cast<float4*>(h + (size_t)t4 * 4) = hn;
    uint2* hpp = hp + (size_t)t4 * 4;
    hpp[0] = splitp(hn.x);
    hpp[1] = splitp(hn.y);
    hpp[2] = splitp(hn.z);
    hpp[3] = splitp(hn.w);
}

// ---------------------------------------------------------------------------
// Fused Luong attention: scores -> softmax -> weighted context (split out).
// ---------------------------------------------------------------------------
__global__ void attention_kernel(const float* __restrict__ contexts,
                                 const float* __restrict__ gamma,
                                 uint2* __restrict__ ctxp)
{
    __shared__ float sg[HH];
    __shared__ float sw[SS];
    __shared__ float red[8];
    __shared__ float s_stat;

    const int b    = blockIdx.x;
    const int tid  = threadIdx.x;   // 256 threads
    const int lane = tid & 31;
    const int warp = tid >> 5;
    const float* cb = contexts + (size_t)b * SS * HH;

    for (int j = tid; j < HH; j += 256) sg[j] = gamma[(size_t)b * HH + j];
    __syncthreads();

    for (int s = warp; s < SS; s += 8) {
        const float* cr = cb + (size_t)s * HH;
        float sum = 0.0f;
#pragma unroll 4
        for (int j = lane * 4; j < HH; j += 128) {
            float4 v = *reinterpret_cast<const float4*>(&cr[j]);
            sum = fmaf(v.x, sg[j], sum);
            sum = fmaf(v.y, sg[j + 1], sum);
            sum = fmaf(v.z, sg[j + 2], sum);
            sum = fmaf(v.w, sg[j + 3], sum);
        }
#pragma unroll
        for (int off = 16; off; off >>= 1)
            sum += __shfl_xor_sync(0xffffffffu, sum, off);
        if (lane == 0) sw[s] = sum;
    }
    __syncthreads();

    const float v = (tid < SS) ? sw[tid] : -3.4e38f;
    float m = v;
#pragma unroll
    for (int off = 16; off; off >>= 1)
        m = fmaxf(m, __shfl_xor_sync(0xffffffffu, m, off));
    if (lane == 0) red[warp] = m;
    __syncthreads();
    if (tid == 0) {
        float mm = red[0];
        for (int w2 = 1; w2 < 8; w2++) mm = fmaxf(mm, red[w2]);
        s_stat = mm;
    }
    __syncthreads();
    const float bm = s_stat;
    const float e = (tid < SS) ? __expf(v - bm) : 0.0f;
    float s2 = e;
#pragma unroll
    for (int off = 16; off; off >>= 1)
        s2 += __shfl_xor_sync(0xffffffffu, s2, off);
    if (lane == 0) red[warp] = s2;
    __syncthreads();
    if (tid == 0) {
        float t = 0.0f;
        for (int w2 = 0; w2 < 8; w2++) t += red[w2];
        s_stat = 1.0f / t;
    }
    __syncthreads();
    if (tid < SS) sw[tid] = e * s_stat;
    __syncthreads();

    float acc[4] = {0.0f, 0.0f, 0.0f, 0.0f};
    for (int s = 0; s < SS; s++) {
        const float w = sw[s];
        const float* cr = cb + (size_t)s * HH;
#pragma unroll
        for (int q = 0; q < 4; q++)
            acc[q] = fmaf(w, cr[tid + q * 256], acc[q]);
    }
#pragma unroll
    for (int q = 0; q < 4; q++)
        ctxp[(size_t)b * HH + tid + q * 256] = splitp(acc[q]);
}

// ---------------------------------------------------------------------------
// State init / final writeback
// ---------------------------------------------------------------------------
__global__ void init_state_kernel(const float* __restrict__ h0,
                                  const float* __restrict__ c0)
{
    const int idx = blockIdx.x * blockDim.x + threadIdx.x;  // over B*H
    const float a  = h0[idx];
    const float b2 = h0[BB * HH + idx];
    g_h0[idx] = a;
    g_h1[idx] = b2;
    g_c0[idx] = c0[idx];
    g_c1[idx] = c0[BB * HH + idx];
    g_h0p[idx] = splitp(a);
    g_h1p[idx] = splitp(b2);
}

__global__ void write_final_kernel(float* __restrict__ out)
{
    const int idx = blockIdx.x * blockDim.x + threadIdx.x;  // over B*H
    out[idx]               = g_h0[idx];
    out[BB * HH + idx]     = g_h1[idx];
    out[2 * BB * HH + idx] = g_c0[idx];
    out[3 * BB * HH + idx] = g_c1[idx];
}

// ---------------------------------------------------------------------------
// Launch
// ---------------------------------------------------------------------------
extern "C" void kernel_launch(void* const* d_in, const int* in_sizes, int n_in,
                              void* d_out, int out_size)
{
    (void)in_sizes; (void)n_in; (void)out_size;

    const int*   inputs   = (const int*)  d_in[0];
    const float* h0       = (const float*)d_in[1];
    const float* c0       = (const float*)d_in[2];
    const float* contexts = (const float*)d_in[3];
    const float* emb      = (const float*)d_in[4];
    const float* W_ih0    = (const float*)d_in[5];
    const float* W_hh0    = (const float*)d_in[6];
    const float* b_ih0    = (const float*)d_in[7];
    const float* b_hh0    = (const float*)d_in[8];
    const float* W_ih1    = (const float*)d_in[9];
    const float* W_hh1    = (const float*)d_in[10];
    const float* b_ih1    = (const float*)d_in[11];
    const float* b_hh1    = (const float*)d_in[12];
    const float* attW     = (const float*)d_in[13];
    const float* attb     = (const float*)d_in[14];
    const float* outW     = (const float*)d_in[15];
    const float* outb     = (const float*)d_in[16];
    float* out = (float*)d_out;

    static float* p_gin0  = nullptr;
    static float* p_gates = nullptr;
    static float* p_h0    = nullptr;
    static float* p_c0    = nullptr;
    static float* p_h1    = nullptr;
    static float* p_c1    = nullptr;
    static float* p_gamma = nullptr;
    static uint2* p_embp = nullptr, *p_Wih0p = nullptr, *p_Whh0p = nullptr;
    static uint2* p_Wih1p = nullptr, *p_Whh1p = nullptr, *p_attWp = nullptr;
    static uint2* p_outWp = nullptr, *p_h0p = nullptr, *p_h1p = nullptr, *p_ctxp = nullptr;
    if (!p_gin0) {
        cudaGetSymbolAddress((void**)&p_gin0,  g_gin0);
        cudaGetSymbolAddress((void**)&p_gates, g_gates);
        cudaGetSymbolAddress((void**)&p_h0,    g_h0);
        cudaGetSymbolAddress((void**)&p_c0,    g_c0);
        cudaGetSymbolAddress((void**)&p_h1,    g_h1);
        cudaGetSymbolAddress((void**)&p_c1,    g_c1);
        cudaGetSymbolAddress((void**)&p_gamma, g_gamma);
        cudaGetSymbolAddress((void**)&p_embp,  g_embp);
        cudaGetSymbolAddress((void**)&p_Wih0p, g_Wih0p);
        cudaGetSymbolAddress((void**)&p_Whh0p, g_Whh0p);
        cudaGetSymbolAddress((void**)&p_Wih1p, g_Wih1p);
        cudaGetSymbolAddress((void**)&p_Whh1p, g_Whh1p);
        cudaGetSymbolAddress((void**)&p_attWp, g_attWp);
        cudaGetSymbolAddress((void**)&p_outWp, g_outWp);
        cudaGetSymbolAddress((void**)&p_h0p,   g_h0p);
        cudaGetSymbolAddress((void**)&p_h1p,   g_h1p);
        cudaGetSymbolAddress((void**)&p_ctxp,  g_ctxp);
    }

    // 0) pre-split weights + emb into tf32 pair buffers
    split_kernel<<<592, 256>>>(emb,   p_embp,  VV * EE);
    split_kernel<<<592, 256>>>(W_ih0, p_Wih0p, FH * EE);
    split_kernel<<<592, 256>>>(W_hh0, p_Whh0p, FH * HH);
    split_kernel<<<592, 256>>>(W_ih1, p_Wih1p, FH * HH);
    split_kernel<<<592, 256>>>(W_hh1, p_Whh1p, FH * HH);
    split_kernel<<<592, 256>>>(attW,  p_attWp, HH * HH);
    split_kernel<<<592, 256>>>(outW,  p_outWp, HH * 2 * HH);

    // init recurrent state (fp32 + pairs)
    init_state_kernel<<<(BB * HH) / 256, 256>>>(h0, c0);

    // 1) time-parallel layer-0 input projection:
    //    gin0[t*B+b, :] = emb[inputs[t,b]] @ W_ih0^T + b_ih0 + b_hh0
    {
        dim3 grid(FH / 64, (TT * BB) / 64);
        mma_gemm3<64, 64><<<grid, 128>>>(
            p_embp, EE, p_Wih0p, EE, EE,
            nullptr, 0, nullptr, 0, 0,
            b_ih0, b_hh0, nullptr, 0,
            p_gin0, FH, 0, inputs);
    }

    const int CELL_BLOCKS = (BB * HH / 4) / 256;  // 128

    // 2) sequential loop
    for (int t = 0; t < TT; t++) {
        // layer 0: gates = gin0[t] + h0 @ W_hh0^T
        {
            dim3 grid(FH / 64, BB / 64);
            mma_gemm3<64, 64><<<grid, 128>>>(
                p_h0p, HH, p_Whh0p, HH, HH,
                nullptr, 0, nullptr, 0, 0,
                nullptr, nullptr,
                p_gin0 + (size_t)t * BB * FH, FH,
                p_gates, FH, 0, nullptr);
        }
        lstm_cell_kernel<<<CELL_BLOCKS, 256>>>(p_gates, p_h0, p_c0, p_h0p);

        // layer 1: gates = h0_new @ W_ih1^T + h1 @ W_hh1^T + biases
        {
            dim3 grid(FH / 64, BB / 64);
            mma_gemm3<64, 64><<<grid, 128>>>(
                p_h0p, HH, p_Wih1p, HH, HH,
                p_h1p, HH, p_Whh1p, HH, HH,
                b_ih1, b_hh1, nullptr, 0,
                p_gates, FH, 0, nullptr);
        }
        lstm_cell_kernel<<<CELL_BLOCKS, 256>>>(p_gates, p_h1, p_c1, p_h1p);

        // attention-in: gamma = h1 @ attW^T + attb
        {
            dim3 grid(HH / 32, BB / 32);
            mma_gemm3<32, 32><<<grid, 128>>>(
                p_h1p, HH, p_attWp, HH, HH,
                nullptr, 0, nullptr, 0, 0,
                attb, nullptr, nullptr, 0,
                p_gamma, HH, 0, nullptr);
        }

        // scores + softmax + context (split output)
        attention_kernel<<<BB, 256>>>(contexts, p_gamma, p_ctxp);

        // out[t] = tanh([ctx, h1] @ outW^T + outb)
        {
            dim3 grid(HH / 32, BB / 32);
            mma_gemm3<32, 32><<<grid, 128>>>(
                p_ctxp, HH, p_outWp, 2 * HH, HH,
                p_h1p,  HH, p_outWp + HH, 2 * HH, HH,
                outb, nullptr, nullptr, 0,
                out + (size_t)t * BB * HH, HH, 1, nullptr);
        }
    }

    // 3) final hT / cT
    write_final_kernel<<<(BB * HH) / 256, 256>>>(out + (size_t)TT * BB * HH);
}

// round 6
// speedup vs baseline: 1.8714x; 1.1393x over previous
#include <cuda_runtime.h>
#include <math.h>
#include <stdint.h>

// Problem dims (fixed by reference)
#define TT 128
#define BB 128
#define SS 128
#define HH 1024
#define EE 512
#define FH 4096   // 4*H
#define VV 32000

// ---------------------------------------------------------------------------
// Scratch (device globals: allocation-free contract)
// ---------------------------------------------------------------------------
__device__ float g_gin0[(size_t)TT * BB * FH];   // layer-0 input proj (fp32, 256 MB)
__device__ float g_gates[BB * FH];
__device__ float g_h0[BB * HH];
__device__ float g_c0[BB * HH];
__device__ float g_h1[BB * HH];
__device__ float g_c1[BB * HH];
__device__ float g_gamma[BB * HH];

// tf32 (hi,lo) pair buffers — x=hi bits, y=lo bits
__device__ uint2 g_embp [(size_t)VV * EE];
__device__ uint2 g_Wih0p[(size_t)FH * EE];
__device__ uint2 g_Whh0p[(size_t)FH * HH];
__device__ uint2 g_Wih1p[(size_t)FH * HH];
__device__ uint2 g_Whh1p[(size_t)FH * HH];
__device__ uint2 g_attWp[(size_t)HH * HH];
__device__ uint2 g_outWp[(size_t)HH * 2 * HH];
__device__ uint2 g_h0p[BB * HH];
__device__ uint2 g_h1p[BB * HH];
__device__ uint2 g_ctxp[BB * HH];

__device__ __forceinline__ float sigmoidf_(float x) {
    return 1.0f / (1.0f + __expf(-x));
}

__device__ __forceinline__ uint32_t f2tf32(float f) {
    uint32_t u;
    asm("cvt.rna.tf32.f32 %0, %1;" : "=r"(u) : "f"(f));
    return u;
}

__device__ __forceinline__ uint2 splitp(float f) {
    const uint32_t h = f2tf32(f);
    return make_uint2(h, f2tf32(f - __uint_as_float(h)));
}

__device__ __forceinline__ void mma_tf32(float* d, const uint32_t* a, const uint32_t* b) {
    asm volatile(
        "mma.sync.aligned.m16n8k8.row.col.f32.tf32.tf32.f32 "
        "{%0,%1,%2,%3}, {%4,%5,%6,%7}, {%8,%9}, {%0,%1,%2,%3};\n"
        : "+f"(d[0]), "+f"(d[1]), "+f"(d[2]), "+f"(d[3])
        : "r"(a[0]), "r"(a[1]), "r"(a[2]), "r"(a[3]), "r"(b[0]), "r"(b[1]));
}

__device__ __forceinline__ void cp16(void* smem, const void* gmem) {
    uint32_t s;
    asm("{ .reg .u64 t; cvta.to.shared.u64 t, %1; cvt.u32.u64 %0, t; }"
        : "=r"(s) : "l"(smem));
    asm volatile("cp.async.ca.shared.global [%0], [%1], 16;" :: "r"(s), "l"(gmem));
}

// ---------------------------------------------------------------------------
// Pre-split: fp32 -> interleaved tf32 (hi,lo) pairs
// ---------------------------------------------------------------------------
__global__ void split_kernel(const float* __restrict__ src,
                             uint2* __restrict__ dst, int n)
{
    for (int i = blockIdx.x * blockDim.x + threadIdx.x; i < n;
         i += gridDim.x * blockDim.x)
        dst[i] = splitp(src[i]);
}

// ---------------------------------------------------------------------------
// Tensor-core dual-source NT GEMM, pre-split tf32 pairs, 4-stage cp.async:
//   C[m,n] = sum_k A1[m,k]*B1[n,k] (+ sum_k A2[m,k]*B2[n,k])
//            (+bias1[n]) (+bias2[n]) (+Cadd[m,n]) ; optional tanh
// gidx gathers A1 rows (embedding lookup). 128 threads, warps 2x2.
// Smem swizzle: pair k of row n stored at slot k ^ ((n&3)<<2)  (conflict-free).
// ---------------------------------------------------------------------------
template <int BM, int BN>
__global__ __launch_bounds__(128)
void mma_gemm4(
    const uint2* __restrict__ A1, int lda1,
    const uint2* __restrict__ B1, int ldb1, int K1,
    const uint2* __restrict__ A2, int lda2,
    const uint2* __restrict__ B2, int ldb2, int K2,
    const float* __restrict__ bias1,
    const float* __restrict__ bias2,
    const float* __restrict__ Cadd, int ldadd,
    float* __restrict__ C, int ldc,
    int act,
    const int* __restrict__ gidx)
{
    constexpr int STAGES = 4;
    constexpr int WM = BM / 2;
    constexpr int WN = BN / 2;
    constexpr int RM = WM / 16;
    constexpr int RN = WN / 8;
    constexpr int ACH = BM / 16;   // 16B chunks per thread per A tile
    constexpr int BCH = BN / 16;

    __shared__ __align__(16) uint2 sA[STAGES][BM][16];
    __shared__ __align__(16) uint2 sB[STAGES][BN][16];

    const int tid  = threadIdx.x;
    const int lane = tid & 31;
    const int warp = tid >> 5;
    const int wm = (warp >> 1) * WM;
    const int wn = (warp & 1) * WN;
    const int row0 = blockIdx.y * BM;
    const int col0 = blockIdx.x * BN;

    float acc[RM][RN][4];
#pragma unroll
    for (int mi = 0; mi < RM; mi++)
#pragma unroll
        for (int ni = 0; ni < RN; ni++)
#pragma unroll
            for (int q = 0; q < 4; q++) acc[mi][ni][q] = 0.0f;

#define LOAD_TILE(buf_, k0_)                                                     \
    do {                                                                         \
        _Pragma("unroll")                                                        \
        for (int i = 0; i < ACH; i++) {                                          \
            const int cch = tid + i * 128;                                       \
            const int n = cch >> 3, j = cch & 7;                                 \
            size_t ro = ug ? (size_t)gidx[row0 + n] * (size_t)lda                \
                           : (size_t)(row0 + n) * (size_t)lda;                   \
            cp16(&sA[buf_][n][(2 * j) ^ ((n & 3) << 2)], A + ro + (k0_) + 2 * j);\
        }                                                                        \
        _Pragma("unroll")                                                        \
        for (int i = 0; i < BCH; i++) {                                          \
            const int cch = tid + i * 128;                                       \
            const int n = cch >> 3, j = cch & 7;                                 \
            cp16(&sB[buf_][n][(2 * j) ^ ((n & 3) << 2)],                         \
                 B + (size_t)(col0 + n) * (size_t)ldb + (k0_) + 2 * j);          \
        }                                                                        \
    } while (0)

    for (int s = 0; s < 2; ++s) {
        const uint2* A = s ? A2 : A1;
        if (A == nullptr) continue;
        const uint2* B = s ? B2 : B1;
        const int lda  = s ? lda2 : lda1;
        const int ldb  = s ? ldb2 : ldb1;
        const int K    = s ? K2 : K1;
        const bool ug  = (s == 0) && (gidx != nullptr);
        const int niter = K >> 4;   // >= STAGES-1 for all call sites (K >= 512)

        // prologue: fill STAGES-1 stages
#pragma unroll
        for (int p = 0; p < STAGES - 1; ++p) {
            LOAD_TILE(p, p << 4);
            asm volatile("cp.async.commit_group;");
        }

        for (int it = 0; it < niter; ++it) {
            const int nx = it + STAGES - 1;
            if (nx < niter) LOAD_TILE(nx % STAGES, nx << 4);
            asm volatile("cp.async.commit_group;");
            // <= STAGES-1 groups pending => group for tile `it` complete
            asm volatile("cp.async.wait_group %0;" :: "n"(STAGES - 1));
            __syncthreads();

            const int buf = it % STAGES;
#pragma unroll
            for (int kq = 0; kq < 2; kq++) {
                const int kb = kq * 8 + (lane & 3);
                uint32_t ah[RM][4], al[RM][4], bh[RN][2], bl[RN][2];
#pragma unroll
                for (int mi = 0; mi < RM; mi++) {
                    const int r0 = wm + mi * 16 + (lane >> 2);
                    const int r1 = r0 + 8;
                    const int sw = (r0 & 3) << 2;   // r1&3 == r0&3
                    uint2 p0 = sA[buf][r0][kb ^ sw];
                    uint2 p1 = sA[buf][r1][kb ^ sw];
                    uint2 p2 = sA[buf][r0][(kb + 4) ^ sw];
                    uint2 p3 = sA[buf][r1][(kb + 4) ^ sw];
                    ah[mi][0] = p0.x; ah[mi][1] = p1.x; ah[mi][2] = p2.x; ah[mi][3] = p3.x;
                    al[mi][0] = p0.y; al[mi][1] = p1.y; al[mi][2] = p2.y; al[mi][3] = p3.y;
                }
#pragma unroll
                for (int ni = 0; ni < RN; ni++) {
                    const int cn = wn + ni * 8 + (lane >> 2);
                    const int sw = (cn & 3) << 2;
                    uint2 q0 = sB[buf][cn][kb ^ sw];
                    uint2 q1 = sB[buf][cn][(kb + 4) ^ sw];
                    bh[ni][0] = q0.x; bh[ni][1] = q1.x;
                    bl[ni][0] = q0.y; bl[ni][1] = q1.y;
                }
#pragma unroll
                for (int mi = 0; mi < RM; mi++)
#pragma unroll
                    for (int ni = 0; ni < RN; ni++) {
                        mma_tf32(acc[mi][ni], ah[mi], bh[ni]);  // hi*hi
                        mma_tf32(acc[mi][ni], ah[mi], bl[ni]);  // hi*lo
                        mma_tf32(acc[mi][ni], al[mi], bh[ni]);  // lo*hi
                    }
            }
            __syncthreads();
        }
    }
#undef LOAD_TILE

    // Epilogue: fragment layout c0,c1 = (row, 2*(lane%4)+{0,1}), c2,c3 = row+8
#pragma unroll
    for (int mi = 0; mi < RM; mi++) {
#pragma unroll
        for (int ni = 0; ni < RN; ni++) {
            const int c = col0 + wn + ni * 8 + 2 * (lane & 3);
#pragma unroll
            for (int hrow = 0; hrow < 2; hrow++) {
                const int r = row0 + wm + mi * 16 + (lane >> 2) + 8 * hrow;
                float v0 = acc[mi][ni][2 * hrow + 0];
                float v1 = acc[mi][ni][2 * hrow + 1];
                if (bias1) { v0 += bias1[c]; v1 += bias1[c + 1]; }
                if (bias2) { v0 += bias2[c]; v1 += bias2[c + 1]; }
                if (Cadd) {
                    v0 += Cadd[(size_t)r * (size_t)ldadd + c];
                    v1 += Cadd[(size_t)r * (size_t)ldadd + c + 1];
                }
                if (act == 1) { v0 = tanhf(v0); v1 = tanhf(v1); }
                *reinterpret_cast<float2*>(&C[(size_t)r * (size_t)ldc + c]) =
                    make_float2(v0, v1);
            }
        }
    }
}

// ---------------------------------------------------------------------------
// LSTM cell, float4-vectorized; writes h fp32 + h split pairs.
// gates layout [B, 4H] in (i,f,g,o) blocks.
// ---------------------------------------------------------------------------
__global__ void lstm_cell_kernel(const float* __restrict__ gates,
                                 float* __restrict__ h,
                                 float* __restrict__ c,
                                 uint2* __restrict__ hp)
{
    const int t4 = blockIdx.x * blockDim.x + threadIdx.x;   // over B*H/4
    const int b = t4 / (HH / 4);
    const int q = t4 - b * (HH / 4);
    const float* g = gates + (size_t)b * FH + q * 4;
    const float4 gi = *reinterpret_cast<const float4*>(g);
    const float4 gf = *reinterpret_cast<const float4*>(g + HH);
    const float4 gg = *reinterpret_cast<const float4*>(g + 2 * HH);
    const float4 go = *reinterpret_cast<const float4*>(g + 3 * HH);
    const float4 cc = *reinterpret_cast<const float4*>(c + (size_t)t4 * 4);
    float4 cn, hn;
    cn.x = sigmoidf_(gf.x) * cc.x + sigmoidf_(gi.x) * tanhf(gg.x);
    cn.y = sigmoidf_(gf.y) * cc.y + sigmoidf_(gi.y) * tanhf(gg.y);
    cn.z = sigmoidf_(gf.z) * cc.z + sigmoidf_(gi.z) * tanhf(gg.z);
    cn.w = sigmoidf_(gf.w) * cc.w + sigmoidf_(gi.w) * tanhf(gg.w);
    hn.x = sigmoidf_(go.x) * tanhf(cn.x);
    hn.y = sigmoidf_(go.y) * tanhf(cn.y);
    hn.z = sigmoidf_(go.z) * tanhf(cn.z);
    hn.w = sigmoidf_(go.w) * tanhf(cn.w);
    *reinterpret_cast<float4*>(c + (size_t)t4 * 4) = cn;
    *reinterpret_cast<float4*>(h + (size_t)t4 * 4) = hn;
    uint2* hpp = hp + (size_t)t4 * 4;
    hpp[0] = splitp(hn.x);
    hpp[1] = splitp(hn.y);
    hpp[2] = splitp(hn.z);
    hpp[3] = splitp(hn.w);
}

// ---------------------------------------------------------------------------
// Fused Luong attention: scores -> softmax -> weighted context (split out).
// ---------------------------------------------------------------------------
__global__ void attention_kernel(const float* __restrict__ contexts,
                                 const float* __restrict__ gamma,
                                 uint2* __restrict__ ctxp)
{
    __shared__ float sg[HH];
    __shared__ float sw[SS];
    __shared__ float red[8];
    __shared__ float s_stat;

    const int b    = blockIdx.x;
    const int tid  = threadIdx.x;   // 256 threads
    const int lane = tid & 31;
    const int warp = tid >> 5;
    const float* cb = contexts + (size_t)b * SS * HH;

    for (int j = tid; j < HH; j += 256) sg[j] = gamma[(size_t)b * HH + j];
    __syncthreads();

    for (int s = warp; s < SS; s += 8) {
        const float* cr = cb + (size_t)s * HH;
        float sum = 0.0f;
#pragma unroll 4
        for (int j = lane * 4; j < HH; j += 128) {
            float4 v = *reinterpret_cast<const float4*>(&cr[j]);
            sum = fmaf(v.x, sg[j], sum);
            sum = fmaf(v.y, sg[j + 1], sum);
            sum = fmaf(v.z, sg[j + 2], sum);
            sum = fmaf(v.w, sg[j + 3], sum);
        }
#pragma unroll
        for (int off = 16; off; off >>= 1)
            sum += __shfl_xor_sync(0xffffffffu, sum, off);
        if (lane == 0) sw[s] = sum;
    }
    __syncthreads();

    const float v = (tid < SS) ? sw[tid] : -3.4e38f;
    float m = v;
#pragma unroll
    for (int off = 16; off; off >>= 1)
        m = fmaxf(m, __shfl_xor_sync(0xffffffffu, m, off));
    if (lane == 0) red[warp] = m;
    __syncthreads();
    if (tid == 0) {
        float mm = red[0];
        for (int w2 = 1; w2 < 8; w2++) mm = fmaxf(mm, red[w2]);
        s_stat = mm;
    }
    __syncthreads();
    const float bm = s_stat;
    const float e = (tid < SS) ? __expf(v - bm) : 0.0f;
    float s2 = e;
#pragma unroll
    for (int off = 16; off; off >>= 1)
        s2 += __shfl_xor_sync(0xffffffffu, s2, off);
    if (lane == 0) red[warp] = s2;
    __syncthreads();
    if (tid == 0) {
        float t = 0.0f;
        for (int w2 = 0; w2 < 8; w2++) t += red[w2];
        s_stat = 1.0f / t;
    }
    __syncthreads();
    if (tid < SS) sw[tid] = e * s_stat;
    __syncthreads();

    float acc[4] = {0.0f, 0.0f, 0.0f, 0.0f};
    for (int s = 0; s < SS; s++) {
        const float w = sw[s];
        const float* cr = cb + (size_t)s * HH;
#pragma unroll
        for (int q = 0; q < 4; q++)
            acc[q] = fmaf(w, cr[tid + q * 256], acc[q]);
    }
#pragma unroll
    for (int q = 0; q < 4; q++)
        ctxp[(size_t)b * HH + tid + q * 256] = splitp(acc[q]);
}

// ---------------------------------------------------------------------------
// State init / final writeback
// ---------------------------------------------------------------------------
__global__ void init_state_kernel(const float* __restrict__ h0,
                                  const float* __restrict__ c0)
{
    const int idx = blockIdx.x * blockDim.x + threadIdx.x;  // over B*H
    const float a  = h0[idx];
    const float b2 = h0[BB * HH + idx];
    g_h0[idx] = a;
    g_h1[idx] = b2;
    g_c0[idx] = c0[idx];
    g_c1[idx] = c0[BB * HH + idx];
    g_h0p[idx] = splitp(a);
    g_h1p[idx] = splitp(b2);
}

__global__ void write_final_kernel(float* __restrict__ out)
{
    const int idx = blockIdx.x * blockDim.x + threadIdx.x;  // over B*H
    out[idx]               = g_h0[idx];
    out[BB * HH + idx]     = g_h1[idx];
    out[2 * BB * HH + idx] = g_c0[idx];
    out[3 * BB * HH + idx] = g_c1[idx];
}

// ---------------------------------------------------------------------------
// Launch
// ---------------------------------------------------------------------------
extern "C" void kernel_launch(void* const* d_in, const int* in_sizes, int n_in,
                              void* d_out, int out_size)
{
    (void)in_sizes; (void)n_in; (void)out_size;

    const int*   inputs   = (const int*)  d_in[0];
    const float* h0       = (const float*)d_in[1];
    const float* c0       = (const float*)d_in[2];
    const float* contexts = (const float*)d_in[3];
    const float* emb      = (const float*)d_in[4];
    const float* W_ih0    = (const float*)d_in[5];
    const float* W_hh0    = (const float*)d_in[6];
    const float* b_ih0    = (const float*)d_in[7];
    const float* b_hh0    = (const float*)d_in[8];
    const float* W_ih1    = (const float*)d_in[9];
    const float* W_hh1    = (const float*)d_in[10];
    const float* b_ih1    = (const float*)d_in[11];
    const float* b_hh1    = (const float*)d_in[12];
    const float* attW     = (const float*)d_in[13];
    const float* attb     = (const float*)d_in[14];
    const float* outW     = (const float*)d_in[15];
    const float* outb     = (const float*)d_in[16];
    float* out = (float*)d_out;

    static float* p_gin0  = nullptr;
    static float* p_gates = nullptr;
    static float* p_h0    = nullptr;
    static float* p_c0    = nullptr;
    static float* p_h1    = nullptr;
    static float* p_c1    = nullptr;
    static float* p_gamma = nullptr;
    static uint2* p_embp = nullptr, *p_Wih0p = nullptr, *p_Whh0p = nullptr;
    static uint2* p_Wih1p = nullptr, *p_Whh1p = nullptr, *p_attWp = nullptr;
    static uint2* p_outWp = nullptr, *p_h0p = nullptr, *p_h1p = nullptr, *p_ctxp = nullptr;
    if (!p_gin0) {
        cudaGetSymbolAddress((void**)&p_gin0,  g_gin0);
        cudaGetSymbolAddress((void**)&p_gates, g_gates);
        cudaGetSymbolAddress((void**)&p_h0,    g_h0);
        cudaGetSymbolAddress((void**)&p_c0,    g_c0);
        cudaGetSymbolAddress((void**)&p_h1,    g_h1);
        cudaGetSymbolAddress((void**)&p_c1,    g_c1);
        cudaGetSymbolAddress((void**)&p_gamma, g_gamma);
        cudaGetSymbolAddress((void**)&p_embp,  g_embp);
        cudaGetSymbolAddress((void**)&p_Wih0p, g_Wih0p);
        cudaGetSymbolAddress((void**)&p_Whh0p, g_Whh0p);
        cudaGetSymbolAddress((void**)&p_Wih1p, g_Wih1p);
        cudaGetSymbolAddress((void**)&p_Whh1p, g_Whh1p);
        cudaGetSymbolAddress((void**)&p_attWp, g_attWp);
        cudaGetSymbolAddress((void**)&p_outWp, g_outWp);
        cudaGetSymbolAddress((void**)&p_h0p,   g_h0p);
        cudaGetSymbolAddress((void**)&p_h1p,   g_h1p);
        cudaGetSymbolAddress((void**)&p_ctxp,  g_ctxp);
    }

    // 0) pre-split weights + emb into tf32 pair buffers
    split_kernel<<<592, 256>>>(emb,   p_embp,  VV * EE);
    split_kernel<<<592, 256>>>(W_ih0, p_Wih0p, FH * EE);
    split_kernel<<<592, 256>>>(W_hh0, p_Whh0p, FH * HH);
    split_kernel<<<592, 256>>>(W_ih1, p_Wih1p, FH * HH);
    split_kernel<<<592, 256>>>(W_hh1, p_Whh1p, FH * HH);
    split_kernel<<<592, 256>>>(attW,  p_attWp, HH * HH);
    split_kernel<<<592, 256>>>(outW,  p_outWp, HH * 2 * HH);

    // init recurrent state (fp32 + pairs)
    init_state_kernel<<<(BB * HH) / 256, 256>>>(h0, c0);

    // 1) time-parallel layer-0 input projection:
    //    gin0[t*B+b, :] = emb[inputs[t,b]] @ W_ih0^T + b_ih0 + b_hh0
    {
        dim3 grid(FH / 32, (TT * BB) / 64);
        mma_gemm4<64, 32><<<grid, 128>>>(
            p_embp, EE, p_Wih0p, EE, EE,
            nullptr, 0, nullptr, 0, 0,
            b_ih0, b_hh0, nullptr, 0,
            p_gin0, FH, 0, inputs);
    }

    const int CELL_BLOCKS = (BB * HH / 4) / 256;  // 128

    // 2) sequential loop
    for (int t = 0; t < TT; t++) {
        // layer 0: gates = gin0[t] + h0 @ W_hh0^T   (grid 128x2 = 256 blocks)
        {
            dim3 grid(FH / 32, BB / 64);
            mma_gemm4<64, 32><<<grid, 128>>>(
                p_h0p, HH, p_Whh0p, HH, HH,
                nullptr, 0, nullptr, 0, 0,
                nullptr, nullptr,
                p_gin0 + (size_t)t * BB * FH, FH,
                p_gates, FH, 0, nullptr);
        }
        lstm_cell_kernel<<<CELL_BLOCKS, 256>>>(p_gates, p_h0, p_c0, p_h0p);

        // layer 1: gates = h0_new @ W_ih1^T + h1 @ W_hh1^T + biases
        {
            dim3 grid(FH / 32, BB / 64);
            mma_gemm4<64, 32><<<grid, 128>>>(
                p_h0p, HH, p_Wih1p, HH, HH,
                p_h1p, HH, p_Whh1p, HH, HH,
                b_ih1, b_hh1, nullptr, 0,
                p_gates, FH, 0, nullptr);
        }
        lstm_cell_kernel<<<CELL_BLOCKS, 256>>>(p_gates, p_h1, p_c1, p_h1p);

        // attention-in: gamma = h1 @ attW^T + attb   (grid 32x4 = 128 blocks)
        {
            dim3 grid(HH / 32, BB / 32);
            mma_gemm4<32, 32><<<grid, 128>>>(
                p_h1p, HH, p_attWp, HH, HH,
                nullptr, 0, nullptr, 0, 0,
                attb, nullptr, nullptr, 0,
                p_gamma, HH, 0, nullptr);
        }

        // scores + softmax + context (split output)
        attention_kernel<<<BB, 256>>>(contexts, p_gamma, p_ctxp);

        // out[t] = tanh([ctx, h1] @ outW^T + outb)
        {
            dim3 grid(HH / 32, BB / 32);
            mma_gemm4<32, 32><<<grid, 128>>>(
                p_ctxp, HH, p_outWp, 2 * HH, HH,
                p_h1p,  HH, p_outWp + HH, 2 * HH, HH,
                outb, nullptr, nullptr, 0,
                out + (size_t)t * BB * HH, HH, 1, nullptr);
        }
    }

    // 3) final hT / cT
    write_final_kernel<<<(BB * HH) / 256, 256>>>(out + (size_t)TT * BB * HH);
}

// round 7
// speedup vs baseline: 1.9716x; 1.0536x over previous
#include <cuda_runtime.h>
#include <math.h>
#include <stdint.h>

// Problem dims (fixed by reference)
#define TT 128
#define BB 128
#define SS 128
#define HH 1024
#define EE 512
#define FH 4096   // 4*H
#define VV 32000

// ---------------------------------------------------------------------------
// Scratch (device globals: allocation-free contract)
// ---------------------------------------------------------------------------
__device__ float g_gin0[(size_t)TT * BB * FH];   // layer-0 input proj (fp32, 256 MB)
__device__ float g_h0[BB * HH];
__device__ float g_c0[BB * HH];
__device__ float g_h1[BB * HH];
__device__ float g_c1[BB * HH];
__device__ float g_gamma[BB * HH];

// tf32 (hi,lo) pair buffers — x=hi bits, y=lo bits
__device__ uint2 g_embp [(size_t)VV * EE];
__device__ uint2 g_Wih0p[(size_t)FH * EE];
__device__ uint2 g_Whh0p[(size_t)FH * HH];
__device__ uint2 g_Wih1p[(size_t)FH * HH];
__device__ uint2 g_Whh1p[(size_t)FH * HH];
__device__ uint2 g_attWp[(size_t)HH * HH];
__device__ uint2 g_outWp[(size_t)HH * 2 * HH];
__device__ uint2 g_h0p[BB * HH];
__device__ uint2 g_h1p[BB * HH];
__device__ uint2 g_ctxp[BB * HH];

__device__ __forceinline__ float sigmoidf_(float x) {
    return 1.0f / (1.0f + __expf(-x));
}

__device__ __forceinline__ uint32_t f2tf32(float f) {
    uint32_t u;
    asm("cvt.rna.tf32.f32 %0, %1;" : "=r"(u) : "f"(f));
    return u;
}

__device__ __forceinline__ uint2 splitp(float f) {
    const uint32_t h = f2tf32(f);
    return make_uint2(h, f2tf32(f - __uint_as_float(h)));
}

__device__ __forceinline__ void mma_tf32(float* d, const uint32_t* a, const uint32_t* b) {
    asm volatile(
        "mma.sync.aligned.m16n8k8.row.col.f32.tf32.tf32.f32 "
        "{%0,%1,%2,%3}, {%4,%5,%6,%7}, {%8,%9}, {%0,%1,%2,%3};\n"
        : "+f"(d[0]), "+f"(d[1]), "+f"(d[2]), "+f"(d[3])
        : "r"(a[0]), "r"(a[1]), "r"(a[2]), "r"(a[3]), "r"(b[0]), "r"(b[1]));
}

__device__ __forceinline__ void cp16(void* smem, const void* gmem) {
    uint32_t s;
    asm("{ .reg .u64 t; cvta.to.shared.u64 t, %1; cvt.u32.u64 %0, t; }"
        : "=r"(s) : "l"(smem));
    asm volatile("cp.async.ca.shared.global [%0], [%1], 16;" :: "r"(s), "l"(gmem));
}

// ---------------------------------------------------------------------------
// Pre-split kernels: fp32 -> interleaved tf32 (hi,lo) pairs.
// Kept to exactly TWO prologue launches so ncu (-s 5) lands on the fused
// layer-1 GEMM (launch order: splitE, splitW, init, gin0, L0f, L1f <- #5).
// ---------------------------------------------------------------------------
__global__ void split_emb_kernel(const float* __restrict__ src,
                                 uint2* __restrict__ dst, int n)
{
    for (int i = blockIdx.x * blockDim.x + threadIdx.x; i < n;
         i += gridDim.x * blockDim.x)
        dst[i] = splitp(src[i]);
}

__global__ void split6_kernel(const float* __restrict__ s0, uint2* __restrict__ d0,
                              const float* __restrict__ s1, uint2* __restrict__ d1,
                              const float* __restrict__ s2, uint2* __restrict__ d2,
                              const float* __restrict__ s3, uint2* __restrict__ d3,
                              const float* __restrict__ s4, uint2* __restrict__ d4,
                              const float* __restrict__ s5, uint2* __restrict__ d5)
{
    const int n0 = FH * EE, n1 = FH * HH, n2 = FH * HH, n3 = FH * HH;
    const int n4 = HH * HH, n5 = HH * 2 * HH;
    const int total = n0 + n1 + n2 + n3 + n4 + n5;
    for (int i = blockIdx.x * blockDim.x + threadIdx.x; i < total;
         i += gridDim.x * blockDim.x) {
        int j = i;
        if (j < n0) { d0[j] = splitp(s0[j]); continue; } j -= n0;
        if (j < n1) { d1[j] = splitp(s1[j]); continue; } j -= n1;
        if (j < n2) { d2[j] = splitp(s2[j]); continue; } j -= n2;
        if (j < n3) { d3[j] = splitp(s3[j]); continue; } j -= n3;
        if (j < n4) { d4[j] = splitp(s4[j]); continue; } j -= n4;
        d5[j] = splitp(s5[j]);
    }
}

// ---------------------------------------------------------------------------
// Generic tensor-core dual-source NT GEMM (pre-split pairs, 4-stage cp.async).
// Used for gin0 / att-in / out GEMMs. 128 threads, warps 2x2.
// ---------------------------------------------------------------------------
template <int BM, int BN>
__global__ __launch_bounds__(128)
void mma_gemm4(
    const uint2* __restrict__ A1, int lda1,
    const uint2* __restrict__ B1, int ldb1, int K1,
    const uint2* __restrict__ A2, int lda2,
    const uint2* __restrict__ B2, int ldb2, int K2,
    const float* __restrict__ bias1,
    const float* __restrict__ bias2,
    const float* __restrict__ Cadd, int ldadd,
    float* __restrict__ C, int ldc,
    int act,
    const int* __restrict__ gidx)
{
    constexpr int STAGES = 4;
    constexpr int WM = BM / 2;
    constexpr int WN = BN / 2;
    constexpr int RM = WM / 16;
    constexpr int RN = WN / 8;
    constexpr int ACH = BM / 16;
    constexpr int BCH = BN / 16;

    __shared__ __align__(16) uint2 sA[STAGES][BM][16];
    __shared__ __align__(16) uint2 sB[STAGES][BN][16];

    const int tid  = threadIdx.x;
    const int lane = tid & 31;
    const int warp = tid >> 5;
    const int wm = (warp >> 1) * WM;
    const int wn = (warp & 1) * WN;
    const int row0 = blockIdx.y * BM;
    const int col0 = blockIdx.x * BN;

    float acc[RM][RN][4];
#pragma unroll
    for (int mi = 0; mi < RM; mi++)
#pragma unroll
        for (int ni = 0; ni < RN; ni++)
#pragma unroll
            for (int q = 0; q < 4; q++) acc[mi][ni][q] = 0.0f;

#define LOAD_TILE(buf_, k0_)                                                     \
    do {                                                                         \
        _Pragma("unroll")                                                        \
        for (int i = 0; i < ACH; i++) {                                          \
            const int cch = tid + i * 128;                                       \
            const int n = cch >> 3, j = cch & 7;                                 \
            size_t ro = ug ? (size_t)gidx[row0 + n] * (size_t)lda                \
                           : (size_t)(row0 + n) * (size_t)lda;                   \
            cp16(&sA[buf_][n][(2 * j) ^ ((n & 3) << 2)], A + ro + (k0_) + 2 * j);\
        }                                                                        \
        _Pragma("unroll")                                                        \
        for (int i = 0; i < BCH; i++) {                                          \
            const int cch = tid + i * 128;                                       \
            const int n = cch >> 3, j = cch & 7;                                 \
            cp16(&sB[buf_][n][(2 * j) ^ ((n & 3) << 2)],                         \
                 B + (size_t)(col0 + n) * (size_t)ldb + (k0_) + 2 * j);          \
        }                                                                        \
    } while (0)

    for (int s = 0; s < 2; ++s) {
        const uint2* A = s ? A2 : A1;
        if (A == nullptr) continue;
        const uint2* B = s ? B2 : B1;
        const int lda  = s ? lda2 : lda1;
        const int ldb  = s ? ldb2 : ldb1;
        const int K    = s ? K2 : K1;
        const bool ug  = (s == 0) && (gidx != nullptr);
        const int niter = K >> 4;

#pragma unroll
        for (int p = 0; p < STAGES - 1; ++p) {
            LOAD_TILE(p, p << 4);
            asm volatile("cp.async.commit_group;");
        }

        for (int it = 0; it < niter; ++it) {
            const int nx = it + STAGES - 1;
            if (nx < niter) LOAD_TILE(nx % STAGES, nx << 4);
            asm volatile("cp.async.commit_group;");
            asm volatile("cp.async.wait_group %0;" :: "n"(STAGES - 1));
            __syncthreads();

            const int buf = it % STAGES;
#pragma unroll
            for (int kq = 0; kq < 2; kq++) {
                const int kb = kq * 8 + (lane & 3);
                uint32_t ah[RM][4], al[RM][4], bh[RN][2], bl[RN][2];
#pragma unroll
                for (int mi = 0; mi < RM; mi++) {
                    const int r0 = wm + mi * 16 + (lane >> 2);
                    const int r1 = r0 + 8;
                    const int sw = (r0 & 3) << 2;
                    uint2 p0 = sA[buf][r0][kb ^ sw];
                    uint2 p1 = sA[buf][r1][kb ^ sw];
                    uint2 p2 = sA[buf][r0][(kb + 4) ^ sw];
                    uint2 p3 = sA[buf][r1][(kb + 4) ^ sw];
                    ah[mi][0] = p0.x; ah[mi][1] = p1.x; ah[mi][2] = p2.x; ah[mi][3] = p3.x;
                    al[mi][0] = p0.y; al[mi][1] = p1.y; al[mi][2] = p2.y; al[mi][3] = p3.y;
                }
#pragma unroll
                for (int ni = 0; ni < RN; ni++) {
                    const int cn = wn + ni * 8 + (lane >> 2);
                    const int sw = (cn & 3) << 2;
                    uint2 q0 = sB[buf][cn][kb ^ sw];
                    uint2 q1 = sB[buf][cn][(kb + 4) ^ sw];
                    bh[ni][0] = q0.x; bh[ni][1] = q1.x;
                    bl[ni][0] = q0.y; bl[ni][1] = q1.y;
                }
#pragma unroll
                for (int mi = 0; mi < RM; mi++)
#pragma unroll
                    for (int ni = 0; ni < RN; ni++) {
                        mma_tf32(acc[mi][ni], ah[mi], bh[ni]);
                        mma_tf32(acc[mi][ni], ah[mi], bl[ni]);
                        mma_tf32(acc[mi][ni], al[mi], bh[ni]);
                    }
            }
            __syncthreads();
        }
    }
#undef LOAD_TILE

#pragma unroll
    for (int mi = 0; mi < RM; mi++) {
#pragma unroll
        for (int ni = 0; ni < RN; ni++) {
            const int c = col0 + wn + ni * 8 + 2 * (lane & 3);
#pragma unroll
            for (int hrow = 0; hrow < 2; hrow++) {
                const int r = row0 + wm + mi * 16 + (lane >> 2) + 8 * hrow;
                float v0 = acc[mi][ni][2 * hrow + 0];
                float v1 = acc[mi][ni][2 * hrow + 1];
                if (bias1) { v0 += bias1[c]; v1 += bias1[c + 1]; }
                if (bias2) { v0 += bias2[c]; v1 += bias2[c + 1]; }
                if (Cadd) {
                    v0 += Cadd[(size_t)r * (size_t)ldadd + c];
                    v1 += Cadd[(size_t)r * (size_t)ldadd + c + 1];
                }
                if (act == 1) { v0 = tanhf(v0); v1 = tanhf(v1); }
                *reinterpret_cast<float2*>(&C[(size_t)r * (size_t)ldc + c]) =
                    make_float2(v0, v1);
            }
        }
    }
}

// ---------------------------------------------------------------------------
// FUSED gates-GEMM + LSTM cell.
//   gates[b, g*H + j] = sum_k A1[b,k]*W1[g*H+j, k] (+ A2*W2) (+bias) (+gin0)
//   then c' = sig(f)*c + sig(i)*tanh(g); h' = sig(o)*tanh(c')
// Grid: HH/8 = 128 blocks; block covers BM=128 batch rows x 32 cols
// (4 gates x 8 j-columns at j0 = blockIdx.x*8). 256 threads, 8 warps (8x1):
// WM=16 (RM=1), WN=32 (RN=4) -> thread holds i,f,g,o for its (row, j) pair.
// Dynamic smem: 4 stages x (128+32) rows x 16 pairs = 80 KB.
// ---------------------------------------------------------------------------
__global__ __launch_bounds__(256)
void gates_cell_kernel(
    const uint2* __restrict__ A1,                   // [B, K1] pairs, ld=K1
    const uint2* __restrict__ W1, int K1,           // [4H, K1] pairs
    const uint2* __restrict__ A2,                   // optional
    const uint2* __restrict__ W2, int K2,
    const float* __restrict__ bias1,                // [4H] or null
    const float* __restrict__ bias2,
    const float* __restrict__ gin,                  // [B, 4H] or null
    float* __restrict__ h,
    float* __restrict__ c,
    uint2* __restrict__ hp)
{
    constexpr int STAGES = 4;
    extern __shared__ __align__(16) uint2 dsm[];
    // layout: sA[STAGES][128][16] then sB[STAGES][32][16]
    uint2 (*sA)[128][16] = reinterpret_cast<uint2 (*)[128][16]>(dsm);
    uint2 (*sB)[32][16]  = reinterpret_cast<uint2 (*)[32][16]>(dsm + STAGES * 128 * 16);

    const int tid  = threadIdx.x;
    const int lane = tid & 31;
    const int warp = tid >> 5;
    const int wm   = warp * 16;
    const int j0   = blockIdx.x * 8;

    float acc[4][4];
#pragma unroll
    for (int ni = 0; ni < 4; ni++)
#pragma unroll
        for (int q = 0; q < 4; q++) acc[ni][q] = 0.0f;

#define GLOAD_TILE(buf_, k0_)                                                     \
    do {                                                                          \
        _Pragma("unroll")                                                         \
        for (int i = 0; i < 4; i++) {   /* A: 128x16 pairs, 4 chunks/thread */    \
            const int cch = tid + i * 256;                                        \
            const int n = cch >> 3, j = cch & 7;                                  \
            cp16(&sA[buf_][n][(2 * j) ^ ((n & 3) << 2)],                          \
                 A + (size_t)n * (size_t)K + (k0_) + 2 * j);                      \
        }                                                                         \
        {   /* B: 32x16 pairs, 1 chunk/thread; row = gate*HH + j0 + jloc */       \
            const int n = tid >> 3, j = tid & 7;                                  \
            const int wrow = (n >> 3) * HH + j0 + (n & 7);                        \
            cp16(&sB[buf_][n][(2 * j) ^ ((n & 3) << 2)],                          \
                 W + (size_t)wrow * (size_t)K + (k0_) + 2 * j);                   \
        }                                                                         \
    } while (0)

    for (int s = 0; s < 2; ++s) {
        const uint2* A = s ? A2 : A1;
        if (A == nullptr) continue;
        const uint2* W = s ? W2 : W1;
        const int K    = s ? K2 : K1;
        const int niter = K >> 4;

#pragma unroll
        for (int p = 0; p < STAGES - 1; ++p) {
            GLOAD_TILE(p, p << 4);
            asm volatile("cp.async.commit_group;");
        }

        for (int it = 0; it < niter; ++it) {
            const int nx = it + STAGES - 1;
            if (nx < niter) GLOAD_TILE(nx % STAGES, nx << 4);
            asm volatile("cp.async.commit_group;");
            asm volatile("cp.async.wait_group %0;" :: "n"(STAGES - 1));
            __syncthreads();

            const int buf = it % STAGES;
#pragma unroll
            for (int kq = 0; kq < 2; kq++) {
                const int kb = kq * 8 + (lane & 3);
                uint32_t ah[4], al[4], bh[4][2], bl[4][2];
                {
                    const int r0 = wm + (lane >> 2);
                    const int r1 = r0 + 8;
                    const int sw = (r0 & 3) << 2;
                    uint2 p0 = sA[buf][r0][kb ^ sw];
                    uint2 p1 = sA[buf][r1][kb ^ sw];
                    uint2 p2 = sA[buf][r0][(kb + 4) ^ sw];
                    uint2 p3 = sA[buf][r1][(kb + 4) ^ sw];
                    ah[0] = p0.x; ah[1] = p1.x; ah[2] = p2.x; ah[3] = p3.x;
                    al[0] = p0.y; al[1] = p1.y; al[2] = p2.y; al[3] = p3.y;
                }
#pragma unroll
                for (int ni = 0; ni < 4; ni++) {
                    const int cn = ni * 8 + (lane >> 2);
                    const int sw = (cn & 3) << 2;
                    uint2 q0 = sB[buf][cn][kb ^ sw];
                    uint2 q1 = sB[buf][cn][(kb + 4) ^ sw];
                    bh[ni][0] = q0.x; bh[ni][1] = q1.x;
                    bl[ni][0] = q0.y; bl[ni][1] = q1.y;
                }
#pragma unroll
                for (int ni = 0; ni < 4; ni++) {
                    mma_tf32(acc[ni], ah, bh[ni]);
                    mma_tf32(acc[ni], ah, bl[ni]);
                    mma_tf32(acc[ni], al, bh[ni]);
                }
            }
            __syncthreads();
        }
    }
#undef GLOAD_TILE

    // Fused cell epilogue. Fragment q: {0,1}->row r0 cols j,j+1; {2,3}->r0+8.
    const int jl = 2 * (lane & 3);
#pragma unroll
    for (int half = 0; half < 2; half++) {
        const int r = wm + (lane >> 2) + 8 * half;
#pragma unroll
        for (int e = 0; e < 2; e++) {
            const int q  = 2 * half + e;
            const int jg = j0 + jl + e;            // global j in [0,H)
            float gi = acc[0][q], gf = acc[1][q], gg = acc[2][q], go = acc[3][q];
            if (bias1) {
                gi += bias1[jg];            gf += bias1[HH + jg];
                gg += bias1[2 * HH + jg];   go += bias1[3 * HH + jg];
            }
            if (bias2) {
                gi += bias2[jg];            gf += bias2[HH + jg];
                gg += bias2[2 * HH + jg];   go += bias2[3 * HH + jg];
            }
            if (gin) {
                const float* gr = gin + (size_t)r * FH;
                gi += gr[jg];          gf += gr[HH + jg];
                gg += gr[2 * HH + jg]; go += gr[3 * HH + jg];
            }
            const int idx = r * HH + jg;
            const float cn = sigmoidf_(gf) * c[idx] + sigmoidf_(gi) * tanhf(gg);
            const float hn = sigmoidf_(go) * tanhf(cn);
            c[idx]  = cn;
            h[idx]  = hn;
            hp[idx] = splitp(hn);
        }
    }
}

// ---------------------------------------------------------------------------
// Fused Luong attention: scores -> softmax -> weighted context (split out).
// ---------------------------------------------------------------------------
__global__ void attention_kernel(const float* __restrict__ contexts,
                                 const float* __restrict__ gamma,
                                 uint2* __restrict__ ctxp)
{
    __shared__ float sg[HH];
    __shared__ float sw[SS];
    __shared__ float red[8];
    __shared__ float s_stat;

    const int b    = blockIdx.x;
    const int tid  = threadIdx.x;   // 256 threads
    const int lane = tid & 31;
    const int warp = tid >> 5;
    const float* cb = contexts + (size_t)b * SS * HH;

    for (int j = tid; j < HH; j += 256) sg[j] = gamma[(size_t)b * HH + j];
    __syncthreads();

    for (int s = warp; s < SS; s += 8) {
        const float* cr = cb + (size_t)s * HH;
        float sum = 0.0f;
#pragma unroll 4
        for (int j = lane * 4; j < HH; j += 128) {
            float4 v = *reinterpret_cast<const float4*>(&cr[j]);
            sum = fmaf(v.x, sg[j], sum);
            sum = fmaf(v.y, sg[j + 1], sum);
            sum = fmaf(v.z, sg[j + 2], sum);
            sum = fmaf(v.w, sg[j + 3], sum);
        }
#pragma unroll
        for (int off = 16; off; off >>= 1)
            sum += __shfl_xor_sync(0xffffffffu, sum, off);
        if (lane == 0) sw[s] = sum;
    }
    __syncthreads();

    const float v = (tid < SS) ? sw[tid] : -3.4e38f;
    float m = v;
#pragma unroll
    for (int off = 16; off; off >>= 1)
        m = fmaxf(m, __shfl_xor_sync(0xffffffffu, m, off));
    if (lane == 0) red[warp] = m;
    __syncthreads();
    if (tid == 0) {
        float mm = red[0];
        for (int w2 = 1; w2 < 8; w2++) mm = fmaxf(mm, red[w2]);
        s_stat = mm;
    }
    __syncthreads();
    const float bm = s_stat;
    const float e = (tid < SS) ? __expf(v - bm) : 0.0f;
    float s2 = e;
#pragma unroll
    for (int off = 16; off; off >>= 1)
        s2 += __shfl_xor_sync(0xffffffffu, s2, off);
    if (lane == 0) red[warp] = s2;
    __syncthreads();
    if (tid == 0) {
        float t = 0.0f;
        for (int w2 = 0; w2 < 8; w2++) t += red[w2];
        s_stat = 1.0f / t;
    }
    __syncthreads();
    if (tid < SS) sw[tid] = e * s_stat;
    __syncthreads();

    float acc[4] = {0.0f, 0.0f, 0.0f, 0.0f};
    for (int s = 0; s < SS; s++) {
        const float w = sw[s];
        const float* cr = cb + (size_t)s * HH;
#pragma unroll
        for (int q = 0; q < 4; q++)
            acc[q] = fmaf(w, cr[tid + q * 256], acc[q]);
    }
#pragma unroll
    for (int q = 0; q < 4; q++)
        ctxp[(size_t)b * HH + tid + q * 256] = splitp(acc[q]);
}

// ---------------------------------------------------------------------------
// State init / final writeback
// ---------------------------------------------------------------------------
__global__ void init_state_kernel(const float* __restrict__ h0,
                                  const float* __restrict__ c0)
{
    const int idx = blockIdx.x * blockDim.x + threadIdx.x;  // over B*H
    const float a  = h0[idx];
    const float b2 = h0[BB * HH + idx];
    g_h0[idx] = a;
    g_h1[idx] = b2;
    g_c0[idx] = c0[idx];
    g_c1[idx] = c0[BB * HH + idx];
    g_h0p[idx] = splitp(a);
    g_h1p[idx] = splitp(b2);
}

__global__ void write_final_kernel(float* __restrict__ out)
{
    const int idx = blockIdx.x * blockDim.x + threadIdx.x;  // over B*H
    out[idx]               = g_h0[idx];
    out[BB * HH + idx]     = g_h1[idx];
    out[2 * BB * HH + idx] = g_c0[idx];
    out[3 * BB * HH + idx] = g_c1[idx];
}

// ---------------------------------------------------------------------------
// Launch
// ---------------------------------------------------------------------------
extern "C" void kernel_launch(void* const* d_in, const int* in_sizes, int n_in,
                              void* d_out, int out_size)
{
    (void)in_sizes; (void)n_in; (void)out_size;

    const int*   inputs   = (const int*)  d_in[0];
    const float* h0       = (const float*)d_in[1];
    const float* c0       = (const float*)d_in[2];
    const float* contexts = (const float*)d_in[3];
    const float* emb      = (const float*)d_in[4];
    const float* W_ih0    = (const float*)d_in[5];
    const float* W_hh0    = (const float*)d_in[6];
    const float* b_ih0    = (const float*)d_in[7];
    const float* b_hh0    = (const float*)d_in[8];
    const float* W_ih1    = (const float*)d_in[9];
    const float* W_hh1    = (const float*)d_in[10];
    const float* b_ih1    = (const float*)d_in[11];
    const float* b_hh1    = (const float*)d_in[12];
    const float* attW     = (const float*)d_in[13];
    const float* attb     = (const float*)d_in[14];
    const float* outW     = (const float*)d_in[15];
    const float* outb     = (const float*)d_in[16];
    float* out = (float*)d_out;

    static float* p_gin0  = nullptr;
    static float* p_h0    = nullptr;
    static float* p_c0    = nullptr;
    static float* p_h1    = nullptr;
    static float* p_c1    = nullptr;
    static float* p_gamma = nullptr;
    static uint2* p_embp = nullptr, *p_Wih0p = nullptr, *p_Whh0p = nullptr;
    static uint2* p_Wih1p = nullptr, *p_Whh1p = nullptr, *p_attWp = nullptr;
    static uint2* p_outWp = nullptr, *p_h0p = nullptr, *p_h1p = nullptr, *p_ctxp = nullptr;
    if (!p_gin0) {
        cudaGetSymbolAddress((void**)&p_gin0,  g_gin0);
        cudaGetSymbolAddress((void**)&p_h0,    g_h0);
        cudaGetSymbolAddress((void**)&p_c0,    g_c0);
        cudaGetSymbolAddress((void**)&p_h1,    g_h1);
        cudaGetSymbolAddress((void**)&p_c1,    g_c1);
        cudaGetSymbolAddress((void**)&p_gamma, g_gamma);
        cudaGetSymbolAddress((void**)&p_embp,  g_embp);
        cudaGetSymbolAddress((void**)&p_Wih0p, g_Wih0p);
        cudaGetSymbolAddress((void**)&p_Whh0p, g_Whh0p);
        cudaGetSymbolAddress((void**)&p_Wih1p, g_Wih1p);
        cudaGetSymbolAddress((void**)&p_Whh1p, g_Whh1p);
        cudaGetSymbolAddress((void**)&p_attWp, g_attWp);
        cudaGetSymbolAddress((void**)&p_outWp, g_outWp);
        cudaGetSymbolAddress((void**)&p_h0p,   g_h0p);
        cudaGetSymbolAddress((void**)&p_h1p,   g_h1p);
        cudaGetSymbolAddress((void**)&p_ctxp,  g_ctxp);
    }

    // fused kernel needs 80 KB dynamic smem (unconditional: cheap + capture-safe)
    constexpr int GSMEM = 4 * (128 + 32) * 16 * sizeof(uint2);   // 81920
    cudaFuncSetAttribute(gates_cell_kernel,
                         cudaFuncAttributeMaxDynamicSharedMemorySize, GSMEM);

    // Launch order matters for ncu -s 5:
    //   0 splitE, 1 splitW, 2 init, 3 gin0, 4 L0f(t0), 5 L1f(t0) <- profiled
    split_emb_kernel<<<592, 256>>>(emb, p_embp, VV * EE);
    split6_kernel<<<592, 256>>>(W_ih0, p_Wih0p, W_hh0, p_Whh0p,
                                W_ih1, p_Wih1p, W_hh1, p_Whh1p,
                                attW,  p_attWp, outW,  p_outWp);
    init_state_kernel<<<(BB * HH) / 256, 256>>>(h0, c0);

    // time-parallel layer-0 input projection (biases folded in):
    {
        dim3 grid(FH / 32, (TT * BB) / 64);
        mma_gemm4<64, 32><<<grid, 128>>>(
            p_embp, EE, p_Wih0p, EE, EE,
            nullptr, 0, nullptr, 0, 0,
            b_ih0, b_hh0, nullptr, 0,
            p_gin0, FH, 0, inputs);
    }

    // sequential loop: 5 kernels/step
    for (int t = 0; t < TT; t++) {
        // layer 0 fused: gates = gin0[t] + h0 @ W_hh0^T ; cell -> h0,c0,h0p
        gates_cell_kernel<<<HH / 8, 256, GSMEM>>>(
            p_h0p, p_Whh0p, HH,
            nullptr, nullptr, 0,
            nullptr, nullptr,
            p_gin0 + (size_t)t * BB * FH,
            p_h0, p_c0, p_h0p);

        // layer 1 fused: gates = h0 @ W_ih1^T + h1 @ W_hh1^T + biases ; cell
        gates_cell_kernel<<<HH / 8, 256, GSMEM>>>(
            p_h0p, p_Wih1p, HH,
            p_h1p, p_Whh1p, HH,
            b_ih1, b_hh1,
            nullptr,
            p_h1, p_c1, p_h1p);

        // attention-in: gamma = h1 @ attW^T + attb
        {
            dim3 grid(HH / 32, BB / 32);
            mma_gemm4<32, 32><<<grid, 128>>>(
                p_h1p, HH, p_attWp, HH, HH,
                nullptr, 0, nullptr, 0, 0,
                attb, nullptr, nullptr, 0,
                p_gamma, HH, 0, nullptr);
        }

        // scores + softmax + context (split output)
        attention_kernel<<<BB, 256>>>(contexts, p_gamma, p_ctxp);

        // out[t] = tanh([ctx, h1] @ outW^T + outb)
        {
            dim3 grid(HH / 32, BB / 32);
            mma_gemm4<32, 32><<<grid, 128>>>(
                p_ctxp, HH, p_outWp, 2 * HH, HH,
                p_h1p,  HH, p_outWp + HH, 2 * HH, HH,
                outb, nullptr, nullptr, 0,
                out + (size_t)t * BB * HH, HH, 1, nullptr);
        }
    }

    // final hT / cT
    write_final_kernel<<<(BB * HH) / 256, 256>>>(out + (size_t)TT * BB * HH);
}

// round 10
// speedup vs baseline: 2.6233x; 1.3305x over previous
#include <cuda_runtime.h>
#include <math.h>
#include <stdint.h>

// Problem dims (fixed by reference)
#define TT 128
#define BB 128
#define SS 128
#define HH 1024
#define EE 512
#define FH 4096   // 4*H
#define VV 32000

// ---------------------------------------------------------------------------
// Scratch (device globals: allocation-free contract)
// ---------------------------------------------------------------------------
__device__ float g_gin0[(size_t)TT * BB * FH];   // layer-0 input proj (fp32, 256 MB)
__device__ float g_h0[BB * HH];
__device__ float g_c0[BB * HH];
__device__ float g_h1[BB * HH];
__device__ float g_c1[BB * HH];
__device__ float g_gamma[BB * HH];

// tf32 (hi,lo) pair buffers — x=hi bits, y=lo bits
__device__ uint2 g_embp [(size_t)VV * EE];
__device__ uint2 g_Wih0p[(size_t)FH * EE];
__device__ uint2 g_Whh0p[(size_t)FH * HH];
__device__ uint2 g_Wih1p[(size_t)FH * HH];
__device__ uint2 g_Whh1p[(size_t)FH * HH];
__device__ uint2 g_attWp[(size_t)HH * HH];
__device__ uint2 g_outWp[(size_t)HH * 2 * HH];
__device__ uint2 g_h0p[BB * HH];
__device__ uint2 g_h1p[BB * HH];
__device__ uint2 g_ctxp[BB * HH];

__device__ unsigned int g_bar;   // monotonic grid-barrier counter (reset in prologue)

__device__ __forceinline__ float sigmoidf_(float x) {
    return 1.0f / (1.0f + __expf(-x));
}

__device__ __forceinline__ uint32_t f2tf32(float f) {
    uint32_t u;
    asm("cvt.rna.tf32.f32 %0, %1;" : "=r"(u) : "f"(f));
    return u;
}

__device__ __forceinline__ uint2 splitp(float f) {
    const uint32_t h = f2tf32(f);
    return make_uint2(h, f2tf32(f - __uint_as_float(h)));
}

__device__ __forceinline__ void mma_tf32(float* d, const uint32_t* a, const uint32_t* b) {
    asm volatile(
        "mma.sync.aligned.m16n8k8.row.col.f32.tf32.tf32.f32 "
        "{%0,%1,%2,%3}, {%4,%5,%6,%7}, {%8,%9}, {%0,%1,%2,%3};\n"
        : "+f"(d[0]), "+f"(d[1]), "+f"(d[2]), "+f"(d[3])
        : "r"(a[0]), "r"(a[1]), "r"(a[2]), "r"(a[3]), "r"(b[0]), "r"(b[1]));
}

__device__ __forceinline__ void cp16(void* smem, const void* gmem) {   // L1-cached (static data)
    uint32_t s;
    asm("{ .reg .u64 t; cvta.to.shared.u64 t, %1; cvt.u32.u64 %0, t; }"
        : "=r"(s) : "l"(smem));
    asm volatile("cp.async.ca.shared.global [%0], [%1], 16;" :: "r"(s), "l"(gmem));
}

__device__ __forceinline__ void cp16cg(void* smem, const void* gmem) { // L2-only (dynamic data)
    uint32_t s;
    asm("{ .reg .u64 t; cvta.to.shared.u64 t, %1; cvt.u32.u64 %0, t; }"
        : "=r"(s) : "l"(smem));
    asm volatile("cp.async.cg.shared.global [%0], [%1], 16;" :: "r"(s), "l"(gmem));
}

// Grid barrier: all 128 blocks co-resident (grid <= SM count) -> spin is safe.
// target must increase by gridDim.x per barrier; g_bar reset each launch.
__device__ __forceinline__ void grid_sync(unsigned int target) {
    __syncthreads();
    __threadfence();                       // release writes + invalidate own L1
    if (threadIdx.x == 0) {
        atomicAdd(&g_bar, 1u);
        unsigned int v;
        do {
            asm volatile("ld.acquire.gpu.u32 %0, [%1];"
                         : "=r"(v) : "l"(&g_bar) : "memory");
        } while (v < target);
    }
    __syncthreads();
}

// ---------------------------------------------------------------------------
// Prologue kernel: split emb + weights into tf32 pairs, init state, reset bar.
// ---------------------------------------------------------------------------
__global__ void prologue_kernel(
    const float* __restrict__ emb,
    const float* __restrict__ W_ih0, const float* __restrict__ W_hh0,
    const float* __restrict__ W_ih1, const float* __restrict__ W_hh1,
    const float* __restrict__ attW,  const float* __restrict__ outW,
    const float* __restrict__ h0,    const float* __restrict__ c0)
{
    if (blockIdx.x == 0 && threadIdx.x == 0) g_bar = 0u;

    const int nE  = VV * EE;
    const int n0  = FH * EE, n1 = FH * HH, n2 = FH * HH, n3 = FH * HH;
    const int n4  = HH * HH, n5 = HH * 2 * HH;
    const int nS  = BB * HH;
    const long total = (long)nE + n0 + n1 + n2 + n3 + n4 + n5 + nS;
    for (long i = (long)blockIdx.x * blockDim.x + threadIdx.x; i < total;
         i += (long)gridDim.x * blockDim.x) {
        long j = i;
        if (j < nE) { g_embp[j]  = splitp(emb[j]);   continue; } j -= nE;
        if (j < n0) { g_Wih0p[j] = splitp(W_ih0[j]); continue; } j -= n0;
        if (j < n1) { g_Whh0p[j] = splitp(W_hh0[j]); continue; } j -= n1;
        if (j < n2) { g_Wih1p[j] = splitp(W_ih1[j]); continue; } j -= n2;
        if (j < n3) { g_Whh1p[j] = splitp(W_hh1[j]); continue; } j -= n3;
        if (j < n4) { g_attWp[j] = splitp(attW[j]);  continue; } j -= n4;
        if (j < n5) { g_outWp[j] = splitp(outW[j]);  continue; } j -= n5;
        const float a  = h0[j];
        const float b2 = h0[BB * HH + j];
        g_h0[j] = a;  g_h1[j] = b2;
        g_c0[j] = c0[j];  g_c1[j] = c0[BB * HH + j];
        g_h0p[j] = splitp(a);
        g_h1p[j] = splitp(b2);
    }
}

// ---------------------------------------------------------------------------
// Standalone GEMM for the time-parallel gin0 projection (gathered rows).
// 128 threads, warps 2x2, BM=64, BN=32, 4-stage cp.async, stage-unrolled.
// ---------------------------------------------------------------------------
__global__ __launch_bounds__(128)
void gin0_gemm_kernel(const int* __restrict__ gidx,
                      const float* __restrict__ bias1,
                      const float* __restrict__ bias2)
{
    constexpr int BM = 64, BN = 32;
    constexpr int WM = 32, WN = 16;
    constexpr int RM = 2,  RN = 2;

    __shared__ __align__(16) uint2 sA[4][BM][16];
    __shared__ __align__(16) uint2 sB[4][BN][16];

    const int tid  = threadIdx.x;
    const int lane = tid & 31;
    const int warp = tid >> 5;
    const int wm = (warp >> 1) * WM;
    const int wn = (warp & 1) * WN;
    const int row0 = blockIdx.y * BM;
    const int col0 = blockIdx.x * BN;
    const int K = EE;
    const int niter = K >> 4;   // 32

    float acc[RM][RN][4];
#pragma unroll
    for (int mi = 0; mi < RM; mi++)
#pragma unroll
        for (int ni = 0; ni < RN; ni++)
#pragma unroll
            for (int q = 0; q < 4; q++) acc[mi][ni][q] = 0.0f;

#define LOAD_T(buf_, k0_)                                                        \
    do {                                                                         \
        _Pragma("unroll")                                                        \
        for (int i = 0; i < 4; i++) {                                            \
            const int cch = tid + i * 128;                                       \
            const int n = cch >> 3, j = cch & 7;                                 \
            size_t ro = (size_t)gidx[row0 + n] * (size_t)EE;                     \
            cp16(&sA[buf_][n][(2 * j) ^ ((n & 3) << 2)],                         \
                 g_embp + ro + (k0_) + 2 * j);                                   \
        }                                                                        \
        _Pragma("unroll")                                                        \
        for (int i = 0; i < 2; i++) {                                            \
            const int cch = tid + i * 128;                                       \
            const int n = cch >> 3, j = cch & 7;                                 \
            cp16(&sB[buf_][n][(2 * j) ^ ((n & 3) << 2)],                         \
                 g_Wih0p + (size_t)(col0 + n) * (size_t)EE + (k0_) + 2 * j);     \
        }                                                                        \
    } while (0)

#define MMA_T(buf_)                                                              \
    do {                                                                         \
        _Pragma("unroll")                                                        \
        for (int kq = 0; kq < 2; kq++) {                                         \
            const int kb = kq * 8 + (lane & 3);                                  \
            uint32_t ah[RM][4], al[RM][4], bh[RN][2], bl[RN][2];                 \
            _Pragma("unroll")                                                    \
            for (int mi = 0; mi < RM; mi++) {                                    \
                const int r0 = wm + mi * 16 + (lane >> 2);                       \
                const int r1 = r0 + 8;                                           \
                const int sw = (r0 & 3) << 2;                                    \
                uint2 p0 = sA[buf_][r0][kb ^ sw];                                \
                uint2 p1 = sA[buf_][r1][kb ^ sw];                                \
                uint2 p2 = sA[buf_][r0][(kb + 4) ^ sw];                          \
                uint2 p3 = sA[buf_][r1][(kb + 4) ^ sw];                          \
                ah[mi][0] = p0.x; ah[mi][1] = p1.x; ah[mi][2] = p2.x; ah[mi][3] = p3.x; \
                al[mi][0] = p0.y; al[mi][1] = p1.y; al[mi][2] = p2.y; al[mi][3] = p3.y; \
            }                                                                    \
            _Pragma("unroll")                                                    \
            for (int ni = 0; ni < RN; ni++) {                                    \
                const int cn = wn + ni * 8 + (lane >> 2);                        \
                const int sw = (cn & 3) << 2;                                    \
                uint2 q0 = sB[buf_][cn][kb ^ sw];                                \
                uint2 q1 = sB[buf_][cn][(kb + 4) ^ sw];                          \
                bh[ni][0] = q0.x; bh[ni][1] = q1.x;                              \
                bl[ni][0] = q0.y; bl[ni][1] = q1.y;                              \
            }                                                                    \
            _Pragma("unroll")                                                    \
            for (int mi = 0; mi < RM; mi++)                                      \
                _Pragma("unroll")                                                \
                for (int ni = 0; ni < RN; ni++) {                                \
                    mma_tf32(acc[mi][ni], ah[mi], bh[ni]);                       \
                    mma_tf32(acc[mi][ni], ah[mi], bl[ni]);                       \
                    mma_tf32(acc[mi][ni], al[mi], bh[ni]);                       \
                }                                                                \
        }                                                                        \
    } while (0)

#pragma unroll
    for (int p = 0; p < 3; ++p) {
        LOAD_T(p, p << 4);
        asm volatile("cp.async.commit_group;");
    }
    for (int it0 = 0; it0 < niter; it0 += 4) {
#pragma unroll
        for (int sb = 0; sb < 4; sb++) {
            const int it = it0 + sb;
            const int nx = it + 3;
            constexpr int nlut[4] = {3, 0, 1, 2};
            if (nx < niter) LOAD_T(nlut[sb], nx << 4);
            asm volatile("cp.async.commit_group;");
            asm volatile("cp.async.wait_group 3;");
            __syncthreads();
            MMA_T(sb);
            __syncthreads();
        }
    }
#undef LOAD_T
#undef MMA_T

#pragma unroll
    for (int mi = 0; mi < RM; mi++) {
#pragma unroll
        for (int ni = 0; ni < RN; ni++) {
            const int c = col0 + wn + ni * 8 + 2 * (lane & 3);
#pragma unroll
            for (int hrow = 0; hrow < 2; hrow++) {
                const int r = row0 + wm + mi * 16 + (lane >> 2) + 8 * hrow;
                float v0 = acc[mi][ni][2 * hrow + 0] + bias1[c] + bias2[c];
                float v1 = acc[mi][ni][2 * hrow + 1] + bias1[c + 1] + bias2[c + 1];
                *reinterpret_cast<float2*>(&g_gin0[(size_t)r * FH + c]) =
                    make_float2(v0, v1);
            }
        }
    }
}

// ---------------------------------------------------------------------------
// Phase: fused gates-GEMM + LSTM cell (device function, 256 threads).
// Block bid covers BM=128 batch rows x 32 cols (4 gates x 8 j), j0 = bid*8.
// A loads via cp.async.cg (dynamic, cross-block); W loads via .ca (static).
// ---------------------------------------------------------------------------
__device__ void gates_phase(uint2* dsm, int bid,
    const uint2* __restrict__ A1, const uint2* __restrict__ W1, int K1,
    const uint2* __restrict__ A2, const uint2* __restrict__ W2, int K2,
    const float* __restrict__ bias1, const float* __restrict__ bias2,
    const float* __restrict__ gin,
    float* __restrict__ h, float* __restrict__ c, uint2* __restrict__ hp)
{
    uint2 (*sA)[128][16] = reinterpret_cast<uint2 (*)[128][16]>(dsm);
    uint2 (*sB)[32][16]  = reinterpret_cast<uint2 (*)[32][16]>(dsm + 4 * 128 * 16);

    const int tid  = threadIdx.x;
    const int lane = tid & 31;
    const int warp = tid >> 5;
    const int wm   = warp * 16;
    const int j0   = bid * 8;

    float acc[4][4];
#pragma unroll
    for (int ni = 0; ni < 4; ni++)
#pragma unroll
        for (int q = 0; q < 4; q++) acc[ni][q] = 0.0f;

#define GLOAD(buf_, k0_)                                                          \
    do {                                                                          \
        _Pragma("unroll")                                                         \
        for (int i = 0; i < 4; i++) {                                             \
            const int cch = tid + i * 256;                                        \
            const int n = cch >> 3, j = cch & 7;                                  \
            cp16cg(&sA[buf_][n][(2 * j) ^ ((n & 3) << 2)],                        \
                   A + (size_t)n * (size_t)K + (k0_) + 2 * j);                    \
        }                                                                         \
        {                                                                         \
            const int n = tid >> 3, j = tid & 7;                                  \
            const int wrow = (n >> 3) * HH + j0 + (n & 7);                        \
            cp16(&sB[buf_][n][(2 * j) ^ ((n & 3) << 2)],                          \
                 W + (size_t)wrow * (size_t)K + (k0_) + 2 * j);                   \
        }                                                                         \
    } while (0)

#define GMMA(buf_)                                                                \
    do {                                                                          \
        _Pragma("unroll")                                                         \
        for (int kq = 0; kq < 2; kq++) {                                          \
            const int kb = kq * 8 + (lane & 3);                                   \
            uint32_t ah[4], al[4], bh[4][2], bl[4][2];                            \
            {                                                                     \
                const int r0 = wm + (lane >> 2);                                  \
                const int r1 = r0 + 8;                                            \
                const int sw = (r0 & 3) << 2;                                     \
                uint2 p0 = sA[buf_][r0][kb ^ sw];                                 \
                uint2 p1 = sA[buf_][r1][kb ^ sw];                                 \
                uint2 p2 = sA[buf_][r0][(kb + 4) ^ sw];                           \
                uint2 p3 = sA[buf_][r1][(kb + 4) ^ sw];                           \
                ah[0] = p0.x; ah[1] = p1.x; ah[2] = p2.x; ah[3] = p3.x;           \
                al[0] = p0.y; al[1] = p1.y; al[2] = p2.y; al[3] = p3.y;           \
            }                                                                     \
            _Pragma("unroll")                                                     \
            for (int ni = 0; ni < 4; ni++) {                                      \
                const int cn = ni * 8 + (lane >> 2);                              \
                const int sw = (cn & 3) << 2;                                     \
                uint2 q0 = sB[buf_][cn][kb ^ sw];                                 \
                uint2 q1 = sB[buf_][cn][(kb + 4) ^ sw];                           \
                bh[ni][0] = q0.x; bh[ni][1] = q1.x;                               \
                bl[ni][0] = q0.y; bl[ni][1] = q1.y;                               \
            }                                                                     \
            _Pragma("unroll")                                                     \
            for (int ni = 0; ni < 4; ni++) {                                      \
                mma_tf32(acc[ni], ah, bh[ni]);                                    \
                mma_tf32(acc[ni], ah, bl[ni]);                                    \
                mma_tf32(acc[ni], al, bh[ni]);                                    \
            }                                                                     \
        }                                                                         \
    } while (0)

    for (int s = 0; s < 2; ++s) {
        const uint2* A = s ? A2 : A1;
        if (A == nullptr) continue;
        const uint2* W = s ? W2 : W1;
        const int K    = s ? K2 : K1;
        const int niter = K >> 4;   // 64

#pragma unroll
        for (int p = 0; p < 3; ++p) {
            GLOAD(p, p << 4);
            asm volatile("cp.async.commit_group;");
        }
        for (int it0 = 0; it0 < niter; it0 += 4) {
#pragma unroll
            for (int sb = 0; sb < 4; sb++) {
                const int it = it0 + sb;
                const int nx = it + 3;
                constexpr int nlut[4] = {3, 0, 1, 2};
                if (nx < niter) GLOAD(nlut[sb], nx << 4);
                asm volatile("cp.async.commit_group;");
                asm volatile("cp.async.wait_group 3;");
                __syncthreads();
                GMMA(sb);
                __syncthreads();
            }
        }
    }
#undef GLOAD
#undef GMMA

    // Fused cell epilogue
    const int jl = 2 * (lane & 3);
#pragma unroll
    for (int half = 0; half < 2; half++) {
        const int r = wm + (lane >> 2) + 8 * half;
#pragma unroll
        for (int e = 0; e < 2; e++) {
            const int q  = 2 * half + e;
            const int jg = j0 + jl + e;
            float gi = acc[0][q], gf = acc[1][q], gg = acc[2][q], go = acc[3][q];
            if (bias1) {
                gi += bias1[jg];            gf += bias1[HH + jg];
                gg += bias1[2 * HH + jg];   go += bias1[3 * HH + jg];
            }
            if (bias2) {
                gi += bias2[jg];            gf += bias2[HH + jg];
                gg += bias2[2 * HH + jg];   go += bias2[3 * HH + jg];
            }
            if (gin) {
                const float* gr = gin + (size_t)r * FH;
                gi += gr[jg];          gf += gr[HH + jg];
                gg += gr[2 * HH + jg]; go += gr[3 * HH + jg];
            }
            const int idx = r * HH + jg;
            const float cn = sigmoidf_(gf) * c[idx] + sigmoidf_(gi) * tanhf(gg);
            const float hn = sigmoidf_(go) * tanhf(cn);
            c[idx]  = cn;
            h[idx]  = hn;
            hp[idx] = splitp(hn);
        }
    }
}

// ---------------------------------------------------------------------------
// Phase: 32x32-tile GEMM (device function, 256 threads, 8 warps 2x4).
// 128 blocks cover (M=128/32) x (N=1024/32) = 4 x 32 tiles exactly.
// A loads via .cg (dynamic); B (weights) via .ca. Optional 2nd source + tanh.
// ---------------------------------------------------------------------------
__device__ void gemm32_phase(uint2* dsm, int bid,
    const uint2* __restrict__ A1, int lda1,
    const uint2* __restrict__ B1, int ldb1, int K1,
    const uint2* __restrict__ A2, int lda2,
    const uint2* __restrict__ B2, int ldb2, int K2,
    const float* __restrict__ bias,
    float* __restrict__ C, int ldc, int act)
{
    uint2 (*sA)[32][16] = reinterpret_cast<uint2 (*)[32][16]>(dsm);
    uint2 (*sB)[32][16] = reinterpret_cast<uint2 (*)[32][16]>(dsm + 4 * 32 * 16);

    const int tid  = threadIdx.x;
    const int lane = tid & 31;
    const int warp = tid >> 5;
    const int wm = (warp >> 2) * 16;
    const int wn = (warp & 3) * 8;
    const int row0 = (bid >> 5) * 32;
    const int col0 = (bid & 31) * 32;

    float acc[4] = {0.0f, 0.0f, 0.0f, 0.0f};

#define LT32(buf_, k0_)                                                           \
    do {                                                                          \
        const int n = tid >> 3, j = tid & 7;                                      \
        cp16cg(&sA[buf_][n][(2 * j) ^ ((n & 3) << 2)],                            \
               A + (size_t)(row0 + n) * (size_t)lda + (k0_) + 2 * j);             \
        cp16(&sB[buf_][n][(2 * j) ^ ((n & 3) << 2)],                              \
             B + (size_t)(col0 + n) * (size_t)ldb + (k0_) + 2 * j);               \
    } while (0)

#define MS32(buf_)                                                                \
    do {                                                                          \
        _Pragma("unroll")                                                         \
        for (int kq = 0; kq < 2; kq++) {                                          \
            const int kb = kq * 8 + (lane & 3);                                   \
            uint32_t ah[4], al[4], bh[2], bl[2];                                  \
            {                                                                     \
                const int r0 = wm + (lane >> 2);                                  \
                const int r1 = r0 + 8;                                            \
                const int sw = (r0 & 3) << 2;                                     \
                uint2 p0 = sA[buf_][r0][kb ^ sw];                                 \
                uint2 p1 = sA[buf_][r1][kb ^ sw];                                 \
                uint2 p2 = sA[buf_][r0][(kb + 4) ^ sw];                           \
                uint2 p3 = sA[buf_][r1][(kb + 4) ^ sw];                           \
                ah[0] = p0.x; ah[1] = p1.x; ah[2] = p2.x; ah[3] = p3.x;           \
                al[0] = p0.y; al[1] = p1.y; al[2] = p2.y; al[3] = p3.y;           \
            }                                                                     \
            {                                                                     \
                const int cn = wn + (lane >> 2);                                  \
                const int sw = (cn & 3) << 2;                                     \
                uint2 q0 = sB[buf_][cn][kb ^ sw];                                 \
                uint2 q1 = sB[buf_][cn][(kb + 4) ^ sw];                           \
                bh[0] = q0.x; bh[1] = q1.x;                                       \
                bl[0] = q0.y; bl[1] = q1.y;                                       \
            }                                                                     \
            mma_tf32(acc, ah, bh);                                                \
            mma_tf32(acc, ah, bl);                                                \
            mma_tf32(acc, al, bh);                                                \
        }                                                                         \
    } while (0)

    for (int s = 0; s < 2; ++s) {
        const uint2* A = s ? A2 : A1;
        if (A == nullptr) continue;
        const uint2* B = s ? B2 : B1;
        const int lda  = s ? lda2 : lda1;
        const int ldb  = s ? ldb2 : ldb1;
        const int K    = s ? K2 : K1;
        const int niter = K >> 4;   // 64

#pragma unroll
        for (int p = 0; p < 3; ++p) {
            LT32(p, p << 4);
            asm volatile("cp.async.commit_group;");
        }
        for (int it0 = 0; it0 < niter; it0 += 4) {
#pragma unroll
            for (int sb = 0; sb < 4; sb++) {
                const int it = it0 + sb;
                const int nx = it + 3;
                constexpr int nlut[4] = {3, 0, 1, 2};
                if (nx < niter) LT32(nlut[sb], nx << 4);
                asm volatile("cp.async.commit_group;");
                asm volatile("cp.async.wait_group 3;");
                __syncthreads();
                MS32(sb);
                __syncthreads();
            }
        }
    }
#undef LT32
#undef MS32

    const int cc = col0 + wn + 2 * (lane & 3);
#pragma unroll
    for (int half = 0; half < 2; half++) {
        const int r = row0 + wm + (lane >> 2) + 8 * half;
        float v0 = acc[2 * half + 0] + bias[cc];
        float v1 = acc[2 * half + 1] + bias[cc + 1];
        if (act == 1) { v0 = tanhf(v0); v1 = tanhf(v1); }
        *reinterpret_cast<float2*>(&C[(size_t)r * (size_t)ldc + cc]) =
            make_float2(v0, v1);
    }
}

// ---------------------------------------------------------------------------
// Phase: fused Luong attention (device function, 256 threads, block = batch b).
// gamma read via __ldcg (dynamic, cross-block); contexts read-only.
// ---------------------------------------------------------------------------
__device__ void attention_phase(char* dsmc,
                                const float* __restrict__ contexts,
                                const float* __restrict__ gamma,
                                uint2* __restrict__ ctxp, int b)
{
    float* sg     = reinterpret_cast<float*>(dsmc);   // 1024
    float* sw     = sg + HH;                          // 128
    float* red    = sw + SS;                          // 8
    float* s_stat = red + 8;                          // 1

    const int tid  = threadIdx.x;
    const int lane = tid & 31;
    const int warp = tid >> 5;
    const float* cb = contexts + (size_t)b * SS * HH;

    for (int j = tid; j < HH; j += 256) sg[j] = __ldcg(&gamma[(size_t)b * HH + j]);
    __syncthreads();

    for (int s = warp; s < SS; s += 8) {
        const float* cr = cb + (size_t)s * HH;
        float sum = 0.0f;
#pragma unroll 4
        for (int j = lane * 4; j < HH; j += 128) {
            float4 v = *reinterpret_cast<const float4*>(&cr[j]);
            sum = fmaf(v.x, sg[j], sum);
            sum = fmaf(v.y, sg[j + 1], sum);
            sum = fmaf(v.z, sg[j + 2], sum);
            sum = fmaf(v.w, sg[j + 3], sum);
        }
#pragma unroll
        for (int off = 16; off; off >>= 1)
            sum += __shfl_xor_sync(0xffffffffu, sum, off);
        if (lane == 0) sw[s] = sum;
    }
    __syncthreads();

    const float v = (tid < SS) ? sw[tid] : -3.4e38f;
    float m = v;
#pragma unroll
    for (int off = 16; off; off >>= 1)
        m = fmaxf(m, __shfl_xor_sync(0xffffffffu, m, off));
    if (lane == 0) red[warp] = m;
    __syncthreads();
    if (tid == 0) {
        float mm = red[0];
        for (int w2 = 1; w2 < 8; w2++) mm = fmaxf(mm, red[w2]);
        *s_stat = mm;
    }
    __syncthreads();
    const float bm = *s_stat;
    const float e = (tid < SS) ? __expf(v - bm) : 0.0f;
    float s2 = e;
#pragma unroll
    for (int off = 16; off; off >>= 1)
        s2 += __shfl_xor_sync(0xffffffffu, s2, off);
    if (lane == 0) red[warp] = s2;
    __syncthreads();
    if (tid == 0) {
        float t = 0.0f;
        for (int w2 = 0; w2 < 8; w2++) t += red[w2];
        *s_stat = 1.0f / t;
    }
    __syncthreads();
    if (tid < SS) sw[tid] = e * (*s_stat);
    __syncthreads();

    float acc[4] = {0.0f, 0.0f, 0.0f, 0.0f};
    for (int s = 0; s < SS; s++) {
        const float w = sw[s];
        const float* cr = cb + (size_t)s * HH;
#pragma unroll
        for (int q = 0; q < 4; q++)
            acc[q] = fmaf(w, cr[tid + q * 256], acc[q]);
    }
#pragma unroll
    for (int q = 0; q < 4; q++)
        ctxp[(size_t)b * HH + tid + q * 256] = splitp(acc[q]);
}

// ---------------------------------------------------------------------------
// THE persistent kernel: 128 blocks x 256 threads, all steps + phases inside,
// grid barriers between phases. Final hT/cT writeback at the end.
// ---------------------------------------------------------------------------
__global__ __launch_bounds__(256)
void persistent_kernel(const float* __restrict__ b_ih1,
                       const float* __restrict__ b_hh1,
                       const float* __restrict__ attb,
                       const float* __restrict__ outb,
                       const float* __restrict__ contexts,
                       float* __restrict__ out)
{
    extern __shared__ __align__(16) uint2 dsm[];
    const int bid = blockIdx.x;
    unsigned int target = 0;

    for (int t = 0; t < TT; t++) {
        // P1: layer-0 gates + cell
        gates_phase(dsm, bid,
                    g_h0p, g_Whh0p, HH,
                    nullptr, nullptr, 0,
                    nullptr, nullptr,
                    g_gin0 + (size_t)t * BB * FH,
                    g_h0, g_c0, g_h0p);
        target += 128; grid_sync(target);

        // P2: layer-1 gates + cell (dual source)
        gates_phase(dsm, bid,
                    g_h0p, g_Wih1p, HH,
                    g_h1p, g_Whh1p, HH,
                    b_ih1, b_hh1,
                    nullptr,
                    g_h1, g_c1, g_h1p);
        target += 128; grid_sync(target);

        // P3: attention-in GEMM (gamma = h1 @ attW^T + attb)
        gemm32_phase(dsm, bid,
                     g_h1p, HH, g_attWp, HH, HH,
                     nullptr, 0, nullptr, 0, 0,
                     attb, g_gamma, HH, 0);
        target += 128; grid_sync(target);

        // P4: scores + softmax + context
        attention_phase(reinterpret_cast<char*>(dsm), contexts, g_gamma,
                        g_ctxp, bid);
        target += 128; grid_sync(target);

        // P5: out[t] = tanh([ctx, h1] @ outW^T + outb)
        gemm32_phase(dsm, bid,
                     g_ctxp, HH, g_outWp, 2 * HH, HH,
                     g_h1p, HH, g_outWp + HH, 2 * HH, HH,
                     outb, out + (size_t)t * BB * HH, HH, 1);
        target += 128; grid_sync(target);
    }

    // final hT / cT (after last barrier; cross-block reads are fresh)
    float* o2 = out + (size_t)TT * BB * HH;
    for (int idx = bid * 256 + threadIdx.x; idx < BB * HH; idx += 128 * 256) {
        o2[idx]               = g_h0[idx];
        o2[BB * HH + idx]     = g_h1[idx];
        o2[2 * BB * HH + idx] = g_c0[idx];
        o2[3 * BB * HH + idx] = g_c1[idx];
    }
}

// ---------------------------------------------------------------------------
// Launch: 3 kernels total, single stream.
// ---------------------------------------------------------------------------
extern "C" void kernel_launch(void* const* d_in, const int* in_sizes, int n_in,
                              void* d_out, int out_size)
{
    (void)in_sizes; (void)n_in; (void)out_size;

    const int*   inputs   = (const int*)  d_in[0];
    const float* h0       = (const float*)d_in[1];
    const float* c0       = (const float*)d_in[2];
    const float* contexts = (const float*)d_in[3];
    const float* emb      = (const float*)d_in[4];
    const float* W_ih0    = (const float*)d_in[5];
    const float* W_hh0    = (const float*)d_in[6];
    const float* b_ih0    = (const float*)d_in[7];
    const float* b_hh0    = (const float*)d_in[8];
    const float* W_ih1    = (const float*)d_in[9];
    const float* W_hh1    = (const float*)d_in[10];
    const float* b_ih1    = (const float*)d_in[11];
    const float* b_hh1    = (const float*)d_in[12];
    const float* attW     = (const float*)d_in[13];
    const float* attb     = (const float*)d_in[14];
    const float* outW     = (const float*)d_in[15];
    const float* outb     = (const float*)d_in[16];
    float* out = (float*)d_out;

    constexpr int GSMEM = 4 * (128 + 32) * 16 * sizeof(uint2);   // 81920
    static bool init_done = false;
    if (!init_done) {
        cudaFuncSetAttribute(persistent_kernel,
                             cudaFuncAttributeMaxDynamicSharedMemorySize, GSMEM);
        init_done = true;
    }

    // [0] prologue: split weights/emb, init state, reset barrier counter
    prologue_kernel<<<1184, 256>>>(emb, W_ih0, W_hh0, W_ih1, W_hh1,
                                   attW, outW, h0, c0);

    // [1] time-parallel layer-0 input projection into g_gin0
    {
        dim3 grid(FH / 32, (TT * BB) / 64);
        gin0_gemm_kernel<<<grid, 128>>>(inputs, b_ih0, b_hh0);
    }

    // [2] the whole recurrent loop in one persistent kernel
    persistent_kernel<<<128, 256, GSMEM>>>(b_ih1, b_hh1, attb, outb,
                                           contexts, out);
}

// round 11
// speedup vs baseline: 3.1950x; 1.2179x over previous
#include <cuda_runtime.h>
#include <cuda_fp16.h>
#include <math.h>
#include <stdint.h>

// Problem dims (fixed by reference)
#define TT 128
#define BB 128
#define SS 128
#define HH 1024
#define EE 512
#define FH 4096   // 4*H
#define VV 32000

#define INV2048 4.8828125e-4f

// ---------------------------------------------------------------------------
// Scratch (device globals: allocation-free contract)
// ---------------------------------------------------------------------------
__device__ float g_gin0[(size_t)TT * BB * FH];   // layer-0 input proj (fp32, 256 MB)
__device__ float g_h0[BB * HH];
__device__ float g_c0[BB * HH];
__device__ float g_h1[BB * HH];
__device__ float g_c1[BB * HH];
__device__ float g_gamma[BB * HH];

// fp16 split buffers: x = hi + lo/2048  (lo stored pre-scaled by 2048)
__device__ half g_embh [(size_t)VV * EE];
__device__ half g_embl [(size_t)VV * EE];
__device__ half g_Wih0h[(size_t)FH * EE];
__device__ half g_Wih0l[(size_t)FH * EE];
__device__ half g_Whh0h[(size_t)FH * HH];
__device__ half g_Whh0l[(size_t)FH * HH];
__device__ half g_Wih1h[(size_t)FH * HH];
__device__ half g_Wih1l[(size_t)FH * HH];
__device__ half g_Whh1h[(size_t)FH * HH];
__device__ half g_Whh1l[(size_t)FH * HH];
__device__ half g_attWh[(size_t)HH * HH];
__device__ half g_attWl[(size_t)HH * HH];
__device__ half g_outWh[(size_t)HH * 2 * HH];
__device__ half g_outWl[(size_t)HH * 2 * HH];
__device__ half g_h0h[BB * HH];
__device__ half g_h0l[BB * HH];
__device__ half g_h1h[BB * HH];
__device__ half g_h1l[BB * HH];
__device__ half g_ctxh[BB * HH];
__device__ half g_ctxl[BB * HH];

__device__ unsigned int g_bar;   // monotonic grid-barrier counter

__device__ __forceinline__ float sigmoidf_(float x) {
    return 1.0f / (1.0f + __expf(-x));
}

__device__ __forceinline__ void split16(float x, half* h, half* l) {
    const half hh = __float2half_rn(x);
    *h = hh;
    *l = __float2half_rn((x - __half2float(hh)) * 2048.0f);
}

__device__ __forceinline__ uint32_t smem_u32(const void* p) {
    uint32_t a;
    asm("{ .reg .u64 t; cvta.to.shared.u64 t, %1; cvt.u32.u64 %0, t; }"
        : "=r"(a) : "l"(p));
    return a;
}

__device__ __forceinline__ void ldm4(uint32_t* r, uint32_t a) {
    asm volatile("ldmatrix.sync.aligned.m8n8.x4.shared.b16 {%0,%1,%2,%3}, [%4];"
                 : "=r"(r[0]), "=r"(r[1]), "=r"(r[2]), "=r"(r[3]) : "r"(a));
}

__device__ __forceinline__ void ldm2(uint32_t* r, uint32_t a) {
    asm volatile("ldmatrix.sync.aligned.m8n8.x2.shared.b16 {%0,%1}, [%2];"
                 : "=r"(r[0]), "=r"(r[1]) : "r"(a));
}

__device__ __forceinline__ void mma_f16(float* d, const uint32_t* a, const uint32_t* b) {
    asm volatile(
        "mma.sync.aligned.m16n8k16.row.col.f32.f16.f16.f32 "
        "{%0,%1,%2,%3}, {%4,%5,%6,%7}, {%8,%9}, {%0,%1,%2,%3};\n"
        : "+f"(d[0]), "+f"(d[1]), "+f"(d[2]), "+f"(d[3])
        : "r"(a[0]), "r"(a[1]), "r"(a[2]), "r"(a[3]), "r"(b[0]), "r"(b[1]));
}

__device__ __forceinline__ void cp16(void* smem, const void* gmem) {   // L1-cached (static)
    asm volatile("cp.async.ca.shared.global [%0], [%1], 16;"
                 :: "r"(smem_u32(smem)), "l"(gmem));
}

__device__ __forceinline__ void cp16cg(void* smem, const void* gmem) { // L2-only (dynamic)
    asm volatile("cp.async.cg.shared.global [%0], [%1], 16;"
                 :: "r"(smem_u32(smem)), "l"(gmem));
}

// Grid barrier (proven R10 version): all 128 blocks co-resident.
__device__ __forceinline__ void grid_sync(unsigned int target) {
    __syncthreads();
    __threadfence();
    if (threadIdx.x == 0) {
        atomicAdd(&g_bar, 1u);
        unsigned int v;
        do {
            asm volatile("ld.acquire.gpu.u32 %0, [%1];"
                         : "=r"(v) : "l"(&g_bar) : "memory");
        } while (v < target);
    }
    __syncthreads();
}

// Smem tile layout (all GEMMs): rows of 16 halves (32 B), 16B chunk c of row r
// stored at r*32 + ((c ^ ((r>>2)&1))<<4)  -> conflict-free for stores+ldmatrix.
__device__ __forceinline__ uint32_t swz(int row, int c) {
    return (uint32_t)(row * 32 + ((c ^ ((row >> 2) & 1)) << 4));
}

// ---------------------------------------------------------------------------
// Prologue: split emb + weights into fp16 (hi, lo*2048), init state, reset bar.
// ---------------------------------------------------------------------------
__global__ void prologue_kernel(
    const float* __restrict__ emb,
    const float* __restrict__ W_ih0, const float* __restrict__ W_hh0,
    const float* __restrict__ W_ih1, const float* __restrict__ W_hh1,
    const float* __restrict__ attW,  const float* __restrict__ outW,
    const float* __restrict__ h0,    const float* __restrict__ c0)
{
    if (blockIdx.x == 0 && threadIdx.x == 0) g_bar = 0u;

    const long nE = (long)VV * EE;
    const long n0 = (long)FH * EE, n1 = (long)FH * HH;
    const long n4 = (long)HH * HH, n5 = (long)HH * 2 * HH;
    const long nS = BB * HH;
    const long total = nE + n0 + 3 * n1 + n4 + n5 + nS;
    for (long i = (long)blockIdx.x * blockDim.x + threadIdx.x; i < total;
         i += (long)gridDim.x * blockDim.x) {
        long j = i;
        if (j < nE) { split16(emb[j],   &g_embh[j],  &g_embl[j]);  continue; } j -= nE;
        if (j < n0) { split16(W_ih0[j], &g_Wih0h[j], &g_Wih0l[j]); continue; } j -= n0;
        if (j < n1) { split16(W_hh0[j], &g_Whh0h[j], &g_Whh0l[j]); continue; } j -= n1;
        if (j < n1) { split16(W_ih1[j], &g_Wih1h[j], &g_Wih1l[j]); continue; } j -= n1;
        if (j < n1) { split16(W_hh1[j], &g_Whh1h[j], &g_Whh1l[j]); continue; } j -= n1;
        if (j < n4) { split16(attW[j],  &g_attWh[j], &g_attWl[j]); continue; } j -= n4;
        if (j < n5) { split16(outW[j],  &g_outWh[j], &g_outWl[j]); continue; } j -= n5;
        const float a  = h0[j];
        const float b2 = h0[BB * HH + j];
        g_h0[j] = a;  g_h1[j] = b2;
        g_c0[j] = c0[j];  g_c1[j] = c0[BB * HH + j];
        split16(a,  &g_h0h[j], &g_h0l[j]);
        split16(b2, &g_h1h[j], &g_h1l[j]);
    }
}

// ---------------------------------------------------------------------------
// gin0 GEMM: gin0[(t,b), :] = emb[inputs]·W_ih0^T + biases. fp16-split path.
// 128 threads, warps 2x2 (WM=32 -> RM=2 m16-frags; WN=16 -> 2 n8 groups).
// BM=64, BN=32, K=512. Smem/stage: Ah 2048 | Al 2048 | Bh 1024 | Bl 1024.
// ---------------------------------------------------------------------------
__global__ __launch_bounds__(128)
void gin0_gemm_kernel(const int* __restrict__ gidx,
                      const float* __restrict__ bias1,
                      const float* __restrict__ bias2)
{
    constexpr int STRIDE = 6144;
    __shared__ __align__(16) char sm[4 * STRIDE];

    const int tid  = threadIdx.x;
    const int lane = tid & 31;
    const int warp = tid >> 5;
    const int wm = (warp >> 1) * 32;
    const int wn = (warp & 1) * 16;
    const int row0 = blockIdx.y * 64;
    const int col0 = blockIdx.x * 32;
    const uint32_t sbase = smem_u32(sm);

    // ldmatrix lane offsets
    uint32_t aoff[2];
#pragma unroll
    for (int mi = 0; mi < 2; mi++) {
        const int r = wm + mi * 16 + ((lane >> 3) & 1) * 8 + (lane & 7);
        aoff[mi] = swz(r, lane >> 4);
    }
    uint32_t boff;
    {
        const int m = lane >> 3;
        const int n = wn + (m >> 1) * 8 + (lane & 7);
        boff = swz(n, m & 1);
    }

    // cp.async mapping (128 threads): A 128 chunks/comp -> each tid 1 per comp;
    // B 128 chunks total -> each tid 1.
    const int arow = tid >> 1, ac = tid & 1;
    const uint32_t asw = swz(arow, ac);
    const int bcomp = tid >> 6;            // 0=Bh 1=Bl
    const int bn = (tid & 63) >> 1, bc = tid & 1;
    const uint32_t bsw = swz(bn, bc) + (bcomp ? 1024u : 0u);

    float D1[2][2][4], D2[2][2][4];
#pragma unroll
    for (int mi = 0; mi < 2; mi++)
#pragma unroll
        for (int ni = 0; ni < 2; ni++)
#pragma unroll
            for (int q = 0; q < 4; q++) { D1[mi][ni][q] = 0.f; D2[mi][ni][q] = 0.f; }

#define G0LOAD(buf_, k0_)                                                        \
    do {                                                                         \
        const size_t ro = (size_t)gidx[row0 + arow] * EE;                        \
        cp16(sm + (buf_)*STRIDE + asw,        g_embh + ro + (k0_) + ac * 8);     \
        cp16(sm + (buf_)*STRIDE + 2048 + asw, g_embl + ro + (k0_) + ac * 8);     \
        {                                                                        \
            const half* wb = bcomp ? g_Wih0l : g_Wih0h;                          \
            cp16(sm + (buf_)*STRIDE + 4096 + bsw,                                \
                 wb + (size_t)(col0 + bn) * EE + (k0_) + bc * 8);                \
        }                                                                        \
    } while (0)

#define G0MMA(buf_)                                                              \
    do {                                                                         \
        const uint32_t st = sbase + (buf_)*STRIDE;                               \
        uint32_t bhv[4], blv[4];                                                 \
        ldm4(bhv, st + 4096 + boff);                                             \
        ldm4(blv, st + 5120 + boff);                                             \
        _Pragma("unroll")                                                        \
        for (int mi = 0; mi < 2; mi++) {                                         \
            uint32_t ah[4], al_[4];                                              \
            ldm4(ah,  st + aoff[mi]);                                            \
            ldm4(al_, st + 2048 + aoff[mi]);                                     \
            _Pragma("unroll")                                                    \
            for (int ni = 0; ni < 2; ni++) {                                     \
                mma_f16(D1[mi][ni], ah,  bhv + 2 * ni);                          \
                mma_f16(D2[mi][ni], ah,  blv + 2 * ni);                          \
                mma_f16(D2[mi][ni], al_, bhv + 2 * ni);                          \
            }                                                                    \
        }                                                                        \
    } while (0)

    const int niter = EE >> 4;   // 32
#pragma unroll
    for (int p = 0; p < 3; ++p) {
        G0LOAD(p, p << 4);
        asm volatile("cp.async.commit_group;");
    }
    for (int it0 = 0; it0 < niter; it0 += 4) {
#pragma unroll
        for (int sb = 0; sb < 4; sb++) {
            const int it = it0 + sb;
            const int nx = it + 3;
            constexpr int nlut[4] = {3, 0, 1, 2};
            if (nx < niter) G0LOAD(nlut[sb], nx << 4);
            asm volatile("cp.async.commit_group;");
            asm volatile("cp.async.wait_group 3;");
            __syncthreads();
            G0MMA(sb);
            __syncthreads();
        }
    }
#undef G0LOAD
#undef G0MMA

#pragma unroll
    for (int mi = 0; mi < 2; mi++) {
#pragma unroll
        for (int ni = 0; ni < 2; ni++) {
            const int c = col0 + wn + ni * 8 + 2 * (lane & 3);
#pragma unroll
            for (int hr = 0; hr < 2; hr++) {
                const int r = row0 + wm + mi * 16 + (lane >> 2) + 8 * hr;
                float v0 = D1[mi][ni][2*hr+0] + D2[mi][ni][2*hr+0] * INV2048
                           + bias1[c] + bias2[c];
                float v1 = D1[mi][ni][2*hr+1] + D2[mi][ni][2*hr+1] * INV2048
                           + bias1[c+1] + bias2[c+1];
                *reinterpret_cast<float2*>(&g_gin0[(size_t)r * FH + c]) =
                    make_float2(v0, v1);
            }
        }
    }
}

// ---------------------------------------------------------------------------
// Phase: fused gates-GEMM + LSTM cell (256 threads, 8 warps, warp m-slice 16).
// Tile: 128 batch rows x 32 cols (4 gates x 8 j), j0 = bid*8.
// Smem/stage: Ah 4096 | Al 4096 | Bh 1024 | Bl 1024 = 10240; x4 stages.
// ---------------------------------------------------------------------------
__device__ void gates_phase(char* dsm, int bid,
    const half* __restrict__ A1h, const half* __restrict__ A1l,
    const half* __restrict__ W1h, const half* __restrict__ W1l, int K1,
    const half* __restrict__ A2h, const half* __restrict__ A2l,
    const half* __restrict__ W2h, const half* __restrict__ W2l, int K2,
    const float* __restrict__ bias1, const float* __restrict__ bias2,
    const float* __restrict__ gin,
    float* __restrict__ h, float* __restrict__ c,
    half* __restrict__ hph, half* __restrict__ hpl)
{
    constexpr int STRIDE = 10240;
    const int tid  = threadIdx.x;
    const int lane = tid & 31;
    const int warp = tid >> 5;
    const int wm   = warp * 16;
    const int j0   = bid * 8;
    const uint32_t sbase = smem_u32(dsm);

    // ldmatrix lane offsets
    const int ar = wm + ((lane >> 3) & 1) * 8 + (lane & 7);
    const uint32_t aoff = swz(ar, lane >> 4);
    uint32_t boff[2];
#pragma unroll
    for (int p = 0; p < 2; p++) {
        const int m = lane >> 3;
        const int n = (2 * p + (m >> 1)) * 8 + (lane & 7);
        boff[p] = swz(n, m & 1);
    }

    // cp.async mapping: A 256 chunks/comp -> tid covers both comps;
    // B 128 chunks (tid<128): comp=tid>>6, n=(tid&63)>>1, c=tid&1
    const int arow = tid >> 1, ac = tid & 1;
    const uint32_t asw = swz(arow, ac);
    const int bn = (tid & 63) >> 1, bc = tid & 1;
    const int wrow = (bn >> 3) * HH + j0 + (bn & 7);
    const uint32_t bsw = swz(bn, bc) + ((tid & 64) ? 1024u : 0u);

    float D1[4][4], D2[4][4];
#pragma unroll
    for (int ni = 0; ni < 4; ni++)
#pragma unroll
        for (int q = 0; q < 4; q++) { D1[ni][q] = 0.f; D2[ni][q] = 0.f; }

#define GLOAD(buf_, k0_)                                                          \
    do {                                                                          \
        cp16cg(dsm + (buf_)*STRIDE + asw,        Ah_ + (size_t)arow*K + (k0_) + ac*8); \
        cp16cg(dsm + (buf_)*STRIDE + 4096 + asw, Al_ + (size_t)arow*K + (k0_) + ac*8); \
        if (tid < 128) {                                                          \
            const half* wb = (tid & 64) ? Wl_ : Wh_;                              \
            cp16(dsm + (buf_)*STRIDE + 8192 + bsw,                                \
                 wb + (size_t)wrow * K + (k0_) + bc * 8);                         \
        }                                                                         \
    } while (0)

#define GMMA(buf_)                                                               \
    do {                                                                         \
        const uint32_t st = sbase + (buf_)*STRIDE;                               \
        uint32_t ah[4], al_[4], b0h[4], b1h[4], b0l[4], b1l[4];                  \
        ldm4(ah,  st + aoff);                                                    \
        ldm4(al_, st + 4096 + aoff);                                             \
        ldm4(b0h, st + 8192 + boff[0]);                                          \
        ldm4(b1h, st + 8192 + boff[1]);                                          \
        ldm4(b0l, st + 9216 + boff[0]);                                          \
        ldm4(b1l, st + 9216 + boff[1]);                                          \
        mma_f16(D1[0], ah, b0h);     mma_f16(D1[1], ah, b0h + 2);                \
        mma_f16(D1[2], ah, b1h);     mma_f16(D1[3], ah, b1h + 2);                \
        mma_f16(D2[0], ah, b0l);     mma_f16(D2[1], ah, b0l + 2);                \
        mma_f16(D2[2], ah, b1l);     mma_f16(D2[3], ah, b1l + 2);                \
        mma_f16(D2[0], al_, b0h);    mma_f16(D2[1], al_, b0h + 2);               \
        mma_f16(D2[2], al_, b1h);    mma_f16(D2[3], al_, b1h + 2);               \
    } while (0)

    for (int s = 0; s < 2; ++s) {
        const half* Ah_ = s ? A2h : A1h;
        if (Ah_ == nullptr) continue;
        const half* Al_ = s ? A2l : A1l;
        const half* Wh_ = s ? W2h : W1h;
        const half* Wl_ = s ? W2l : W1l;
        const int K     = s ? K2 : K1;
        const int niter = K >> 4;   // 64

#pragma unroll
        for (int p = 0; p < 3; ++p) {
            GLOAD(p, p << 4);
            asm volatile("cp.async.commit_group;");
        }
        for (int it0 = 0; it0 < niter; it0 += 4) {
#pragma unroll
            for (int sb = 0; sb < 4; sb++) {
                const int it = it0 + sb;
                const int nx = it + 3;
                constexpr int nlut[4] = {3, 0, 1, 2};
                if (nx < niter) GLOAD(nlut[sb], nx << 4);
                asm volatile("cp.async.commit_group;");
                asm volatile("cp.async.wait_group 3;");
                __syncthreads();
                GMMA(sb);
                __syncthreads();
            }
        }
    }
#undef GLOAD
#undef GMMA

    // Fused cell epilogue (D layout identical to tf32 path)
    const int jl = 2 * (lane & 3);
#pragma unroll
    for (int hf = 0; hf < 2; hf++) {
        const int r = wm + (lane >> 2) + 8 * hf;
#pragma unroll
        for (int e = 0; e < 2; e++) {
            const int q  = 2 * hf + e;
            const int jg = j0 + jl + e;
            float gi = D1[0][q] + D2[0][q] * INV2048;
            float gf = D1[1][q] + D2[1][q] * INV2048;
            float gg = D1[2][q] + D2[2][q] * INV2048;
            float go = D1[3][q] + D2[3][q] * INV2048;
            if (bias1) {
                gi += bias1[jg];            gf += bias1[HH + jg];
                gg += bias1[2 * HH + jg];   go += bias1[3 * HH + jg];
            }
            if (bias2) {
                gi += bias2[jg];            gf += bias2[HH + jg];
                gg += bias2[2 * HH + jg];   go += bias2[3 * HH + jg];
            }
            if (gin) {
                const float* gr = gin + (size_t)r * FH;
                gi += gr[jg];          gf += gr[HH + jg];
                gg += gr[2 * HH + jg]; go += gr[3 * HH + jg];
            }
            const int idx = r * HH + jg;
            const float cn = sigmoidf_(gf) * c[idx] + sigmoidf_(gi) * tanhf(gg);
            const float hn = sigmoidf_(go) * tanhf(cn);
            c[idx] = cn;
            h[idx] = hn;
            split16(hn, &hph[idx], &hpl[idx]);
        }
    }
}

// ---------------------------------------------------------------------------
// Phase: 32x32-tile GEMM (256 threads, 8 warps 2x4). 128 blocks = 4x32 tiles.
// Smem/stage: Ah 1024 | Al 1024 | Bh 1024 | Bl 1024 = 4096; x4 stages.
// ---------------------------------------------------------------------------
__device__ void gemm32_phase(char* dsm, int bid,
    const half* __restrict__ A1h, const half* __restrict__ A1l, int lda1,
    const half* __restrict__ B1h, const half* __restrict__ B1l, int ldb1, int K1,
    const half* __restrict__ A2h, const half* __restrict__ A2l, int lda2,
    const half* __restrict__ B2h, const half* __restrict__ B2l, int ldb2, int K2,
    const float* __restrict__ bias,
    float* __restrict__ C, int ldc, int act)
{
    constexpr int STRIDE = 4096;
    const int tid  = threadIdx.x;
    const int lane = tid & 31;
    const int warp = tid >> 5;
    const int wm = (warp >> 2) * 16;
    const int wn = (warp & 3) * 8;
    const int row0 = (bid >> 5) * 32;
    const int col0 = (bid & 31) * 32;
    const uint32_t sbase = smem_u32(dsm);

    const int ar = wm + ((lane >> 3) & 1) * 8 + (lane & 7);
    const uint32_t aoff = swz(ar, lane >> 4);
    uint32_t boff;
    {
        const int m = (lane & 15) >> 3;      // lanes >=16 mirror (valid addr)
        const int n = wn + (lane & 7);
        boff = swz(n, m);
    }

    // loads: tid>>6: 0=Ah 1=Al 2=Bh 3=Bl; row=(tid&63)>>1, c=tid&1
    const int reg4 = tid >> 6;
    const int lrow = (tid & 63) >> 1, lc = tid & 1;
    const uint32_t lsw = swz(lrow, lc) + (uint32_t)reg4 * 1024u;

    float D1[4] = {0.f, 0.f, 0.f, 0.f};
    float D2[4] = {0.f, 0.f, 0.f, 0.f};

#define LT32(buf_, k0_)                                                           \
    do {                                                                          \
        if (reg4 < 2) {                                                           \
            const half* ab = reg4 ? Al_ : Ah_;                                    \
            cp16cg(dsm + (buf_)*STRIDE + lsw,                                     \
                   ab + (size_t)(row0 + lrow) * lda + (k0_) + lc * 8);            \
        } else {                                                                  \
            const half* bb = (reg4 == 3) ? Bl_ : Bh_;                             \
            cp16(dsm + (buf_)*STRIDE + lsw,                                       \
                 bb + (size_t)(col0 + lrow) * ldb + (k0_) + lc * 8);              \
        }                                                                         \
    } while (0)

#define MS32(buf_)                                                                \
    do {                                                                          \
        const uint32_t st = sbase + (buf_)*STRIDE;                                \
        uint32_t ah[4], al_[4], bh[2], bl[2];                                     \
        ldm4(ah,  st + aoff);                                                     \
        ldm4(al_, st + 1024 + aoff);                                              \
        ldm2(bh,  st + 2048 + boff);                                              \
        ldm2(bl,  st + 3072 + boff);                                              \
        mma_f16(D1, ah,  bh);                                                     \
        mma_f16(D2, ah,  bl);                                                     \
        mma_f16(D2, al_, bh);                                                     \
    } while (0)

    for (int s = 0; s < 2; ++s) {
        const half* Ah_ = s ? A2h : A1h;
        if (Ah_ == nullptr) continue;
        const half* Al_ = s ? A2l : A1l;
        const half* Bh_ = s ? B2h : B1h;
        const half* Bl_ = s ? B2l : B1l;
        const int lda = s ? lda2 : lda1;
        const int ldb = s ? ldb2 : ldb1;
        const int K   = s ? K2 : K1;
        const int niter = K >> 4;   // 64

#pragma unroll
        for (int p = 0; p < 3; ++p) {
            LT32(p, p << 4);
            asm volatile("cp.async.commit_group;");
        }
        for (int it0 = 0; it0 < niter; it0 += 4) {
#pragma unroll
            for (int sb = 0; sb < 4; sb++) {
                const int it = it0 + sb;
                const int nx = it + 3;
                constexpr int nlut[4] = {3, 0, 1, 2};
                if (nx < niter) LT32(nlut[sb], nx << 4);
                asm volatile("cp.async.commit_group;");
                asm volatile("cp.async.wait_group 3;");
                __syncthreads();
                MS32(sb);
                __syncthreads();
            }
        }
    }
#undef LT32
#undef MS32

    const int cc = col0 + wn + 2 * (lane & 3);
#pragma unroll
    for (int hf = 0; hf < 2; hf++) {
        const int r = row0 + wm + (lane >> 2) + 8 * hf;
        float v0 = D1[2*hf+0] + D2[2*hf+0] * INV2048 + bias[cc];
        float v1 = D1[2*hf+1] + D2[2*hf+1] * INV2048 + bias[cc+1];
        if (act == 1) { v0 = tanhf(v0); v1 = tanhf(v1); }
        *reinterpret_cast<float2*>(&C[(size_t)r * (size_t)ldc + cc]) =
            make_float2(v0, v1);
    }
}

// ---------------------------------------------------------------------------
// Phase: fused Luong attention (256 threads, block = batch b). Split output.
// ---------------------------------------------------------------------------
__device__ void attention_phase(char* dsmc,
                                const float* __restrict__ contexts,
                                const float* __restrict__ gamma,
                                half* __restrict__ ctxh,
                                half* __restrict__ ctxl, int b)
{
    float* sg     = reinterpret_cast<float*>(dsmc);   // 1024
    float* sw     = sg + HH;                          // 128
    float* red    = sw + SS;                          // 8
    float* s_stat = red + 8;                          // 1

    const int tid  = threadIdx.x;
    const int lane = tid & 31;
    const int warp = tid >> 5;
    const float* cb = contexts + (size_t)b * SS * HH;

    for (int j = tid; j < HH; j += 256) sg[j] = __ldcg(&gamma[(size_t)b * HH + j]);
    __syncthreads();

    for (int s = warp; s < SS; s += 8) {
        const float* cr = cb + (size_t)s * HH;
        float sum = 0.0f;
#pragma unroll 4
        for (int j = lane * 4; j < HH; j += 128) {
            float4 v = *reinterpret_cast<const float4*>(&cr[j]);
            sum = fmaf(v.x, sg[j], sum);
            sum = fmaf(v.y, sg[j + 1], sum);
            sum = fmaf(v.z, sg[j + 2], sum);
            sum = fmaf(v.w, sg[j + 3], sum);
        }
#pragma unroll
        for (int off = 16; off; off >>= 1)
            sum += __shfl_xor_sync(0xffffffffu, sum, off);
        if (lane == 0) sw[s] = sum;
    }
    __syncthreads();

    const float v = (tid < SS) ? sw[tid] : -3.4e38f;
    float m = v;
#pragma unroll
    for (int off = 16; off; off >>= 1)
        m = fmaxf(m, __shfl_xor_sync(0xffffffffu, m, off));
    if (lane == 0) red[warp] = m;
    __syncthreads();
    if (tid == 0) {
        float mm = red[0];
        for (int w2 = 1; w2 < 8; w2++) mm = fmaxf(mm, red[w2]);
        *s_stat = mm;
    }
    __syncthreads();
    const float bm = *s_stat;
    const float e = (tid < SS) ? __expf(v - bm) : 0.0f;
    float s2 = e;
#pragma unroll
    for (int off = 16; off; off >>= 1)
        s2 += __shfl_xor_sync(0xffffffffu, s2, off);
    if (lane == 0) red[warp] = s2;
    __syncthreads();
    if (tid == 0) {
        float t = 0.0f;
        for (int w2 = 0; w2 < 8; w2++) t += red[w2];
        *s_stat = 1.0f / t;
    }
    __syncthreads();
    if (tid < SS) sw[tid] = e * (*s_stat);
    __syncthreads();

    float acc[4] = {0.0f, 0.0f, 0.0f, 0.0f};
    for (int s = 0; s < SS; s++) {
        const float w = sw[s];
        const float* cr = cb + (size_t)s * HH;
#pragma unroll
        for (int q = 0; q < 4; q++)
            acc[q] = fmaf(w, cr[tid + q * 256], acc[q]);
    }
#pragma unroll
    for (int q = 0; q < 4; q++) {
        const int idx = b * HH + tid + q * 256;
        split16(acc[q], &ctxh[idx], &ctxl[idx]);
    }
}

// ---------------------------------------------------------------------------
// THE persistent kernel: 128 blocks x 256 threads.
// ---------------------------------------------------------------------------
__global__ __launch_bounds__(256)
void persistent_kernel(const float* __restrict__ b_ih1,
                       const float* __restrict__ b_hh1,
                       const float* __restrict__ attb,
                       const float* __restrict__ outb,
                       const float* __restrict__ contexts,
                       float* __restrict__ out)
{
    extern __shared__ __align__(16) char dsm[];
    const int bid = blockIdx.x;
    unsigned int target = 0;

    for (int t = 0; t < TT; t++) {
        // P1: layer-0 gates + cell
        gates_phase(dsm, bid,
                    g_h0h, g_h0l, g_Whh0h, g_Whh0l, HH,
                    nullptr, nullptr, nullptr, nullptr, 0,
                    nullptr, nullptr,
                    g_gin0 + (size_t)t * BB * FH,
                    g_h0, g_c0, g_h0h, g_h0l);
        target += 128; grid_sync(target);

        // P2: layer-1 gates + cell (dual source)
        gates_phase(dsm, bid,
                    g_h0h, g_h0l, g_Wih1h, g_Wih1l, HH,
                    g_h1h, g_h1l, g_Whh1h, g_Whh1l, HH,
                    b_ih1, b_hh1,
                    nullptr,
                    g_h1, g_c1, g_h1h, g_h1l);
        target += 128; grid_sync(target);

        // P3: gamma = h1 @ attW^T + attb
        gemm32_phase(dsm, bid,
                     g_h1h, g_h1l, HH, g_attWh, g_attWl, HH, HH,
                     nullptr, nullptr, 0, nullptr, nullptr, 0, 0,
                     attb, g_gamma, HH, 0);
        target += 128; grid_sync(target);

        // P4: scores + softmax + context
        attention_phase(dsm, contexts, g_gamma, g_ctxh, g_ctxl, bid);
        target += 128; grid_sync(target);

        // P5: out[t] = tanh([ctx, h1] @ outW^T + outb)
        gemm32_phase(dsm, bid,
                     g_ctxh, g_ctxl, HH, g_outWh, g_outWl, 2 * HH, HH,
                     g_h1h, g_h1l, HH, g_outWh + HH, g_outWl + HH, 2 * HH, HH,
                     outb, out + (size_t)t * BB * HH, HH, 1);
        target += 128; grid_sync(target);
    }

    // final hT / cT
    float* o2 = out + (size_t)TT * BB * HH;
    for (int idx = bid * 256 + threadIdx.x; idx < BB * HH; idx += 128 * 256) {
        o2[idx]               = g_h0[idx];
        o2[BB * HH + idx]     = g_h1[idx];
        o2[2 * BB * HH + idx] = g_c0[idx];
        o2[3 * BB * HH + idx] = g_c1[idx];
    }
}

// ---------------------------------------------------------------------------
// Launch: 3 kernels, single stream.
// ---------------------------------------------------------------------------
extern "C" void kernel_launch(void* const* d_in, const int* in_sizes, int n_in,
                              void* d_out, int out_size)
{
    (void)in_sizes; (void)n_in; (void)out_size;

    const int*   inputs   = (const int*)  d_in[0];
    const float* h0       = (const float*)d_in[1];
    const float* c0       = (const float*)d_in[2];
    const float* contexts = (const float*)d_in[3];
    const float* emb      = (const float*)d_in[4];
    const float* W_ih0    = (const float*)d_in[5];
    const float* W_hh0    = (const float*)d_in[6];
    const float* b_ih0    = (const float*)d_in[7];
    const float* b_hh0    = (const float*)d_in[8];
    const float* W_ih1    = (const float*)d_in[9];
    const float* W_hh1    = (const float*)d_in[10];
    const float* b_ih1    = (const float*)d_in[11];
    const float* b_hh1    = (const float*)d_in[12];
    const float* attW     = (const float*)d_in[13];
    const float* attb     = (const float*)d_in[14];
    const float* outW     = (const float*)d_in[15];
    const float* outb     = (const float*)d_in[16];
    float* out = (float*)d_out;

    constexpr int GSMEM = 4 * 10240;   // 40960 (gates stage stride x 4)
    static bool init_done = false;
    if (!init_done) {
        cudaFuncSetAttribute(persistent_kernel,
                             cudaFuncAttributeMaxDynamicSharedMemorySize, GSMEM);
        init_done = true;
    }

    // [0] prologue: fp16-split weights/emb, init state, reset barrier
    prologue_kernel<<<1184, 256>>>(emb, W_ih0, W_hh0, W_ih1, W_hh1,
                                   attW, outW, h0, c0);

    // [1] time-parallel layer-0 input projection
    {
        dim3 grid(FH / 32, (TT * BB) / 64);
        gin0_gemm_kernel<<<grid, 128>>>(inputs, b_ih0, b_hh0);
    }

    // [2] the whole recurrent loop
    persistent_kernel<<<128, 256, GSMEM>>>(b_ih1, b_hh1, attb, outb,
                                           contexts, out);
}

// round 12
// speedup vs baseline: 3.5271x; 1.1039x over previous
#include <cuda_runtime.h>
#include <cuda_fp16.h>
#include <math.h>
#include <stdint.h>

// Problem dims (fixed by reference)
#define TT 128
#define BB 128
#define SS 128
#define HH 1024
#define EE 512
#define FH 4096   // 4*H
#define VV 32000

#define INV2048 4.8828125e-4f

// ---------------------------------------------------------------------------
// Scratch (device globals: allocation-free contract)
// ---------------------------------------------------------------------------
__device__ float g_gin0[(size_t)TT * BB * FH];
__device__ float g_h0[BB * HH];
__device__ float g_c0[BB * HH];
__device__ float g_h1[BB * HH];
__device__ float g_c1[BB * HH];
__device__ float g_gamma[BB * HH];

// fp16 split buffers: x = hi + lo/2048  (lo stored pre-scaled by 2048)
__device__ half g_embh [(size_t)VV * EE];
__device__ half g_embl [(size_t)VV * EE];
__device__ half g_Wih0h[(size_t)FH * EE];
__device__ half g_Wih0l[(size_t)FH * EE];
__device__ half g_Whh0h[(size_t)FH * HH];
__device__ half g_Whh0l[(size_t)FH * HH];
__device__ half g_Wih1h[(size_t)FH * HH];
__device__ half g_Wih1l[(size_t)FH * HH];
__device__ half g_Whh1h[(size_t)FH * HH];
__device__ half g_Whh1l[(size_t)FH * HH];
__device__ half g_attWh[(size_t)HH * HH];
__device__ half g_attWl[(size_t)HH * HH];
__device__ half g_outWh[(size_t)HH * 2 * HH];
__device__ half g_outWl[(size_t)HH * 2 * HH];
__device__ half g_h0h[BB * HH];
__device__ half g_h0l[BB * HH];
__device__ half g_h1h0[BB * HH];   // h1 pairs, parity 0
__device__ half g_h1l0[BB * HH];
__device__ half g_h1h1[BB * HH];   // h1 pairs, parity 1 (holds initial state)
__device__ half g_h1l1[BB * HH];
__device__ half g_ctxh[BB * HH];
__device__ half g_ctxl[BB * HH];

__device__ unsigned int g_barA;   // group-A barrier counter
__device__ unsigned int g_barB;   // group-B barrier counter
__device__ unsigned int g_cA;     // A progress: += 1 per block after P2(t)
__device__ unsigned int g_cB;     // B progress: += 1 per block after P5(t)

__device__ __forceinline__ float sigmoidf_(float x) {
    return 1.0f / (1.0f + __expf(-x));
}

__device__ __forceinline__ void split16(float x, half* h, half* l) {
    const half hh = __float2half_rn(x);
    *h = hh;
    *l = __float2half_rn((x - __half2float(hh)) * 2048.0f);
}

__device__ __forceinline__ uint32_t smem_u32(const void* p) {
    uint32_t a;
    asm("{ .reg .u64 t; cvta.to.shared.u64 t, %1; cvt.u32.u64 %0, t; }"
        : "=r"(a) : "l"(p));
    return a;
}

__device__ __forceinline__ void ldm4(uint32_t* r, uint32_t a) {
    asm volatile("ldmatrix.sync.aligned.m8n8.x4.shared.b16 {%0,%1,%2,%3}, [%4];"
                 : "=r"(r[0]), "=r"(r[1]), "=r"(r[2]), "=r"(r[3]) : "r"(a));
}

__device__ __forceinline__ void ldm2(uint32_t* r, uint32_t a) {
    asm volatile("ldmatrix.sync.aligned.m8n8.x2.shared.b16 {%0,%1}, [%2];"
                 : "=r"(r[0]), "=r"(r[1]) : "r"(a));
}

__device__ __forceinline__ void mma_f16(float* d, const uint32_t* a, const uint32_t* b) {
    asm volatile(
        "mma.sync.aligned.m16n8k16.row.col.f32.f16.f16.f32 "
        "{%0,%1,%2,%3}, {%4,%5,%6,%7}, {%8,%9}, {%0,%1,%2,%3};\n"
        : "+f"(d[0]), "+f"(d[1]), "+f"(d[2]), "+f"(d[3])
        : "r"(a[0]), "r"(a[1]), "r"(a[2]), "r"(a[3]), "r"(b[0]), "r"(b[1]));
}

__device__ __forceinline__ void cp16(void* smem, const void* gmem) {   // L1 (static)
    asm volatile("cp.async.ca.shared.global [%0], [%1], 16;"
                 :: "r"(smem_u32(smem)), "l"(gmem));
}

__device__ __forceinline__ void cp16cg(void* smem, const void* gmem) { // L2-only (dynamic)
    asm volatile("cp.async.cg.shared.global [%0], [%1], 16;"
                 :: "r"(smem_u32(smem)), "l"(gmem));
}

// Group barrier (R10-proven structure, parameterized counter).
__device__ __forceinline__ void group_sync(unsigned int* bar, unsigned int target) {
    __syncthreads();
    __threadfence();
    if (threadIdx.x == 0) {
        atomicAdd(bar, 1u);
        unsigned int v;
        do {
            asm volatile("ld.acquire.gpu.u32 %0, [%1];"
                         : "=r"(v) : "l"(bar) : "memory");
        } while (v < target);
    }
    __syncthreads();
}

// Wait on a cross-group progress counter (no arrive).
__device__ __forceinline__ void wait_cnt(unsigned int* cnt, unsigned int target) {
    if (threadIdx.x == 0) {
        unsigned int v;
        do {
            asm volatile("ld.acquire.gpu.u32 %0, [%1];"
                         : "=r"(v) : "l"(cnt) : "memory");
        } while (v < target);
    }
    __syncthreads();
}

// Progress bump: make prior writes visible, then count.
__device__ __forceinline__ void bump_cnt(unsigned int* cnt) {
    __syncthreads();
    __threadfence();
    if (threadIdx.x == 0) atomicAdd(cnt, 1u);
}

// Smem tile layout: rows of 16 halves (32 B); chunk c of row r at
// r*32 + ((c ^ ((r>>2)&1))<<4)  -> conflict-free stores + ldmatrix.
__device__ __forceinline__ uint32_t swz(int row, int c) {
    return (uint32_t)(row * 32 + ((c ^ ((row >> 2) & 1)) << 4));
}

// ---------------------------------------------------------------------------
// Prologue: split weights/emb, init state (h1 -> parity-1), reset counters.
// ---------------------------------------------------------------------------
__global__ void prologue_kernel(
    const float* __restrict__ emb,
    const float* __restrict__ W_ih0, const float* __restrict__ W_hh0,
    const float* __restrict__ W_ih1, const float* __restrict__ W_hh1,
    const float* __restrict__ attW,  const float* __restrict__ outW,
    const float* __restrict__ h0,    const float* __restrict__ c0)
{
    if (blockIdx.x == 0 && threadIdx.x == 0) {
        g_barA = 0u; g_barB = 0u; g_cA = 0u; g_cB = 0u;
    }

    const long nE = (long)VV * EE;
    const long n0 = (long)FH * EE, n1 = (long)FH * HH;
    const long n4 = (long)HH * HH, n5 = (long)HH * 2 * HH;
    const long nS = BB * HH;
    const long total = nE + n0 + 3 * n1 + n4 + n5 + nS;
    for (long i = (long)blockIdx.x * blockDim.x + threadIdx.x; i < total;
         i += (long)gridDim.x * blockDim.x) {
        long j = i;
        if (j < nE) { split16(emb[j],   &g_embh[j],  &g_embl[j]);  continue; } j -= nE;
        if (j < n0) { split16(W_ih0[j], &g_Wih0h[j], &g_Wih0l[j]); continue; } j -= n0;
        if (j < n1) { split16(W_hh0[j], &g_Whh0h[j], &g_Whh0l[j]); continue; } j -= n1;
        if (j < n1) { split16(W_ih1[j], &g_Wih1h[j], &g_Wih1l[j]); continue; } j -= n1;
        if (j < n1) { split16(W_hh1[j], &g_Whh1h[j], &g_Whh1l[j]); continue; } j -= n1;
        if (j < n4) { split16(attW[j],  &g_attWh[j], &g_attWl[j]); continue; } j -= n4;
        if (j < n5) { split16(outW[j],  &g_outWh[j], &g_outWl[j]); continue; } j -= n5;
        const float a  = h0[j];
        const float b2 = h0[BB * HH + j];
        g_h0[j] = a;  g_h1[j] = b2;
        g_c0[j] = c0[j];  g_c1[j] = c0[BB * HH + j];
        split16(a,  &g_h0h[j],  &g_h0l[j]);
        split16(b2, &g_h1h1[j], &g_h1l1[j]);   // initial state -> parity 1
    }
}

// ---------------------------------------------------------------------------
// gin0 GEMM (unchanged from R11): emb[inputs]·W_ih0^T + biases.
// ---------------------------------------------------------------------------
__global__ __launch_bounds__(128)
void gin0_gemm_kernel(const int* __restrict__ gidx,
                      const float* __restrict__ bias1,
                      const float* __restrict__ bias2)
{
    constexpr int STRIDE = 6144;
    __shared__ __align__(16) char sm[4 * STRIDE];

    const int tid  = threadIdx.x;
    const int lane = tid & 31;
    const int warp = tid >> 5;
    const int wm = (warp >> 1) * 32;
    const int wn = (warp & 1) * 16;
    const int row0 = blockIdx.y * 64;
    const int col0 = blockIdx.x * 32;
    const uint32_t sbase = smem_u32(sm);

    uint32_t aoff[2];
#pragma unroll
    for (int mi = 0; mi < 2; mi++) {
        const int r = wm + mi * 16 + ((lane >> 3) & 1) * 8 + (lane & 7);
        aoff[mi] = swz(r, lane >> 4);
    }
    uint32_t boff;
    {
        const int m = lane >> 3;
        const int n = wn + (m >> 1) * 8 + (lane & 7);
        boff = swz(n, m & 1);
    }

    const int arow = tid >> 1, ac = tid & 1;
    const uint32_t asw = swz(arow, ac);
    const int bcomp = tid >> 6;
    const int bn = (tid & 63) >> 1, bc = tid & 1;
    const uint32_t bsw = swz(bn, bc) + (bcomp ? 1024u : 0u);

    float D1[2][2][4], D2[2][2][4];
#pragma unroll
    for (int mi = 0; mi < 2; mi++)
#pragma unroll
        for (int ni = 0; ni < 2; ni++)
#pragma unroll
            for (int q = 0; q < 4; q++) { D1[mi][ni][q] = 0.f; D2[mi][ni][q] = 0.f; }

#define G0LOAD(buf_, k0_)                                                        \
    do {                                                                         \
        const size_t ro = (size_t)gidx[row0 + arow] * EE;                        \
        cp16(sm + (buf_)*STRIDE + asw,        g_embh + ro + (k0_) + ac * 8);     \
        cp16(sm + (buf_)*STRIDE + 2048 + asw, g_embl + ro + (k0_) + ac * 8);     \
        {                                                                        \
            const half* wb = bcomp ? g_Wih0l : g_Wih0h;                          \
            cp16(sm + (buf_)*STRIDE + 4096 + bsw,                                \
                 wb + (size_t)(col0 + bn) * EE + (k0_) + bc * 8);                \
        }                                                                        \
    } while (0)

#define G0MMA(buf_)                                                              \
    do {                                                                         \
        const uint32_t st = sbase + (buf_)*STRIDE;                               \
        uint32_t bhv[4], blv[4];                                                 \
        ldm4(bhv, st + 4096 + boff);                                             \
        ldm4(blv, st + 5120 + boff);                                             \
        _Pragma("unroll")                                                        \
        for (int mi = 0; mi < 2; mi++) {                                         \
            uint32_t ah[4], al_[4];                                              \
            ldm4(ah,  st + aoff[mi]);                                            \
            ldm4(al_, st + 2048 + aoff[mi]);                                     \
            _Pragma("unroll")                                                    \
            for (int ni = 0; ni < 2; ni++) {                                     \
                mma_f16(D1[mi][ni], ah,  bhv + 2 * ni);                          \
                mma_f16(D2[mi][ni], ah,  blv + 2 * ni);                          \
                mma_f16(D2[mi][ni], al_, bhv + 2 * ni);                          \
            }                                                                    \
        }                                                                        \
    } while (0)

    const int niter = EE >> 4;
#pragma unroll
    for (int p = 0; p < 3; ++p) {
        G0LOAD(p, p << 4);
        asm volatile("cp.async.commit_group;");
    }
    for (int it0 = 0; it0 < niter; it0 += 4) {
#pragma unroll
        for (int sb = 0; sb < 4; sb++) {
            const int it = it0 + sb;
            const int nx = it + 3;
            constexpr int nlut[4] = {3, 0, 1, 2};
            if (nx < niter) G0LOAD(nlut[sb], nx << 4);
            asm volatile("cp.async.commit_group;");
            asm volatile("cp.async.wait_group 3;");
            __syncthreads();
            G0MMA(sb);
            __syncthreads();
        }
    }
#undef G0LOAD
#undef G0MMA

#pragma unroll
    for (int mi = 0; mi < 2; mi++) {
#pragma unroll
        for (int ni = 0; ni < 2; ni++) {
            const int c = col0 + wn + ni * 8 + 2 * (lane & 3);
#pragma unroll
            for (int hr = 0; hr < 2; hr++) {
                const int r = row0 + wm + mi * 16 + (lane >> 2) + 8 * hr;
                float v0 = D1[mi][ni][2*hr+0] + D2[mi][ni][2*hr+0] * INV2048
                           + bias1[c] + bias2[c];
                float v1 = D1[mi][ni][2*hr+1] + D2[mi][ni][2*hr+1] * INV2048
                           + bias1[c+1] + bias2[c+1];
                *reinterpret_cast<float2*>(&g_gin0[(size_t)r * FH + c]) =
                    make_float2(v0, v1);
            }
        }
    }
}

// ---------------------------------------------------------------------------
// Group-A phase: fused gates-GEMM + cell, BN=64 (16 j-cols x 4 gates).
// 64 blocks, 256 threads; block tile 128 rows x 64 cols; j0 = bidA*16.
// Smem/stage: Ah 4096 | Al 4096 | Bh 2048 | Bl 2048 = 12288; x4 stages.
// ---------------------------------------------------------------------------
__device__ void gates64_phase(char* dsm, int bidA,
    const half* __restrict__ A1h, const half* __restrict__ A1l,
    const half* __restrict__ W1h, const half* __restrict__ W1l, int K1,
    const half* __restrict__ A2h, const half* __restrict__ A2l,
    const half* __restrict__ W2h, const half* __restrict__ W2l, int K2,
    const float* __restrict__ bias1, const float* __restrict__ bias2,
    const float* __restrict__ gin,
    float* __restrict__ h, float* __restrict__ c,
    half* __restrict__ hph, half* __restrict__ hpl)
{
    constexpr int STRIDE = 12288;
    const int tid  = threadIdx.x;
    const int lane = tid & 31;
    const int warp = tid >> 5;
    const int wm   = warp * 16;
    const int j0   = bidA * 16;
    const uint32_t sbase = smem_u32(dsm);

    const int ar = wm + ((lane >> 3) & 1) * 8 + (lane & 7);
    const uint32_t aoff = swz(ar, lane >> 4);
    uint32_t boff[4];
#pragma unroll
    for (int p = 0; p < 4; p++) {
        const int m = lane >> 3;
        const int n = (2 * p + (m >> 1)) * 8 + (lane & 7);
        boff[p] = swz(n, m & 1);
    }

    const int arow = tid >> 1, ac = tid & 1;
    const uint32_t asw = swz(arow, ac);
    const int bcomp = tid >> 7;              // 0=Bh 1=Bl
    const int bn = (tid & 127) >> 1, bc = tid & 1;
    const int wrow = (bn >> 4) * HH + j0 + (bn & 15);
    const uint32_t bsw = swz(bn, bc) + (bcomp ? 2048u : 0u);

    float D1[8][4], D2[8][4];
#pragma unroll
    for (int ni = 0; ni < 8; ni++)
#pragma unroll
        for (int q = 0; q < 4; q++) { D1[ni][q] = 0.f; D2[ni][q] = 0.f; }

#define GLOAD(buf_, k0_)                                                          \
    do {                                                                          \
        cp16cg(dsm + (buf_)*STRIDE + asw,        Ah_ + (size_t)arow*K + (k0_) + ac*8); \
        cp16cg(dsm + (buf_)*STRIDE + 4096 + asw, Al_ + (size_t)arow*K + (k0_) + ac*8); \
        {                                                                         \
            const half* wb = bcomp ? Wl_ : Wh_;                                   \
            cp16(dsm + (buf_)*STRIDE + 8192 + bsw,                                \
                 wb + (size_t)wrow * K + (k0_) + bc * 8);                         \
        }                                                                         \
    } while (0)

#define GMMA(buf_)                                                               \
    do {                                                                         \
        const uint32_t st = sbase + (buf_)*STRIDE;                               \
        uint32_t ah[4], al_[4];                                                  \
        ldm4(ah,  st + aoff);                                                    \
        ldm4(al_, st + 4096 + aoff);                                             \
        _Pragma("unroll")                                                        \
        for (int p = 0; p < 4; p++) {                                            \
            uint32_t bhv[4], blv[4];                                             \
            ldm4(bhv, st + 8192  + boff[p]);                                     \
            ldm4(blv, st + 10240 + boff[p]);                                     \
            _Pragma("unroll")                                                    \
            for (int w2 = 0; w2 < 2; w2++) {                                     \
                const int ni = 2 * p + w2;                                       \
                mma_f16(D1[ni], ah,  bhv + 2 * w2);                              \
                mma_f16(D2[ni], ah,  blv + 2 * w2);                              \
                mma_f16(D2[ni], al_, bhv + 2 * w2);                              \
            }                                                                    \
        }                                                                        \
    } while (0)

    for (int s = 0; s < 2; ++s) {
        const half* Ah_ = s ? A2h : A1h;
        if (Ah_ == nullptr) continue;
        const half* Al_ = s ? A2l : A1l;
        const half* Wh_ = s ? W2h : W1h;
        const half* Wl_ = s ? W2l : W1l;
        const int K     = s ? K2 : K1;
        const int niter = K >> 4;   // 64

#pragma unroll
        for (int p = 0; p < 3; ++p) {
            GLOAD(p, p << 4);
            asm volatile("cp.async.commit_group;");
        }
        for (int it0 = 0; it0 < niter; it0 += 4) {
#pragma unroll
            for (int sb = 0; sb < 4; sb++) {
                const int it = it0 + sb;
                const int nx = it + 3;
                constexpr int nlut[4] = {3, 0, 1, 2};
                if (nx < niter) GLOAD(nlut[sb], nx << 4);
                asm volatile("cp.async.commit_group;");
                asm volatile("cp.async.wait_group 3;");
                __syncthreads();
                GMMA(sb);
                __syncthreads();
            }
        }
    }
#undef GLOAD
#undef GMMA

    // Fused cell epilogue. col = ni*8 + 2*(lane&3) + e ; gate = ni>>1, o = ni&1.
    const int jl2 = 2 * (lane & 3);
#pragma unroll
    for (int hf = 0; hf < 2; hf++) {
        const int r = wm + (lane >> 2) + 8 * hf;
#pragma unroll
        for (int o = 0; o < 2; o++) {
#pragma unroll
            for (int e = 0; e < 2; e++) {
                const int q  = 2 * hf + e;
                const int jg = j0 + 8 * o + jl2 + e;
                float gi = D1[0 + o][q] + D2[0 + o][q] * INV2048;
                float gf = D1[2 + o][q] + D2[2 + o][q] * INV2048;
                float gg = D1[4 + o][q] + D2[4 + o][q] * INV2048;
                float go = D1[6 + o][q] + D2[6 + o][q] * INV2048;
                if (bias1) {
                    gi += bias1[jg];            gf += bias1[HH + jg];
                    gg += bias1[2 * HH + jg];   go += bias1[3 * HH + jg];
                }
                if (bias2) {
                    gi += bias2[jg];            gf += bias2[HH + jg];
                    gg += bias2[2 * HH + jg];   go += bias2[3 * HH + jg];
                }
                if (gin) {
                    const float* gr = gin + (size_t)r * FH;
                    gi += gr[jg];          gf += gr[HH + jg];
                    gg += gr[2 * HH + jg]; go += gr[3 * HH + jg];
                }
                const int idx = r * HH + jg;
                const float cn = sigmoidf_(gf) * c[idx] + sigmoidf_(gi) * tanhf(gg);
                const float hn = sigmoidf_(go) * tanhf(cn);
                c[idx] = cn;
                h[idx] = hn;
                split16(hn, &hph[idx], &hpl[idx]);
            }
        }
    }
}

// ---------------------------------------------------------------------------
// 32x32-tile GEMM phase (tile = explicit index 0..127). R11-proven internals.
// ---------------------------------------------------------------------------
__device__ void gemm32_phase(char* dsm, int tile,
    const half* __restrict__ A1h, const half* __restrict__ A1l, int lda1,
    const half* __restrict__ B1h, const half* __restrict__ B1l, int ldb1, int K1,
    const half* __restrict__ A2h, const half* __restrict__ A2l, int lda2,
    const half* __restrict__ B2h, const half* __restrict__ B2l, int ldb2, int K2,
    const float* __restrict__ bias,
    float* __restrict__ C, int ldc, int act)
{
    constexpr int STRIDE = 4096;
    const int tid  = threadIdx.x;
    const int lane = tid & 31;
    const int warp = tid >> 5;
    const int wm = (warp >> 2) * 16;
    const int wn = (warp & 3) * 8;
    const int row0 = (tile >> 5) * 32;
    const int col0 = (tile & 31) * 32;
    const uint32_t sbase = smem_u32(dsm);

    const int ar = wm + ((lane >> 3) & 1) * 8 + (lane & 7);
    const uint32_t aoff = swz(ar, lane >> 4);
    uint32_t boff;
    {
        const int m = (lane & 15) >> 3;
        const int n = wn + (lane & 7);
        boff = swz(n, m);
    }

    const int reg4 = tid >> 6;
    const int lrow = (tid & 63) >> 1, lc = tid & 1;
    const uint32_t lsw = swz(lrow, lc) + (uint32_t)reg4 * 1024u;

    float D1[4] = {0.f, 0.f, 0.f, 0.f};
    float D2[4] = {0.f, 0.f, 0.f, 0.f};

#define LT32(buf_, k0_)                                                           \
    do {                                                                          \
        if (reg4 < 2) {                                                           \
            const half* ab = reg4 ? Al_ : Ah_;                                    \
            cp16cg(dsm + (buf_)*STRIDE + lsw,                                     \
                   ab + (size_t)(row0 + lrow) * lda + (k0_) + lc * 8);            \
        } else {                                                                  \
            const half* bb = (reg4 == 3) ? Bl_ : Bh_;                             \
            cp16(dsm + (buf_)*STRIDE + lsw,                                       \
                 bb + (size_t)(col0 + lrow) * ldb + (k0_) + lc * 8);              \
        }                                                                         \
    } while (0)

#define MS32(buf_)                                                                \
    do {                                                                          \
        const uint32_t st = sbase + (buf_)*STRIDE;                                \
        uint32_t ah[4], al_[4], bh[2], bl[2];                                     \
        ldm4(ah,  st + aoff);                                                     \
        ldm4(al_, st + 1024 + aoff);                                              \
        ldm2(bh,  st + 2048 + boff);                                              \
        ldm2(bl,  st + 3072 + boff);                                              \
        mma_f16(D1, ah,  bh);                                                     \
        mma_f16(D2, ah,  bl);                                                     \
        mma_f16(D2, al_, bh);                                                     \
    } while (0)

    for (int s = 0; s < 2; ++s) {
        const half* Ah_ = s ? A2h : A1h;
        if (Ah_ == nullptr) continue;
        const half* Al_ = s ? A2l : A1l;
        const half* Bh_ = s ? B2h : B1h;
        const half* Bl_ = s ? B2l : B1l;
        const int lda = s ? lda2 : lda1;
        const int ldb = s ? ldb2 : ldb1;
        const int K   = s ? K2 : K1;
        const int niter = K >> 4;

#pragma unroll
        for (int p = 0; p < 3; ++p) {
            LT32(p, p << 4);
            asm volatile("cp.async.commit_group;");
        }
        for (int it0 = 0; it0 < niter; it0 += 4) {
#pragma unroll
            for (int sb = 0; sb < 4; sb++) {
                const int it = it0 + sb;
                const int nx = it + 3;
                constexpr int nlut[4] = {3, 0, 1, 2};
                if (nx < niter) LT32(nlut[sb], nx << 4);
                asm volatile("cp.async.commit_group;");
                asm volatile("cp.async.wait_group 3;");
                __syncthreads();
                MS32(sb);
                __syncthreads();
            }
        }
    }
#undef LT32
#undef MS32

    const int cc = col0 + wn + 2 * (lane & 3);
#pragma unroll
    for (int hf = 0; hf < 2; hf++) {
        const int r = row0 + wm + (lane >> 2) + 8 * hf;
        float v0 = D1[2*hf+0] + D2[2*hf+0] * INV2048 + bias[cc];
        float v1 = D1[2*hf+1] + D2[2*hf+1] * INV2048 + bias[cc+1];
        if (act == 1) { v0 = tanhf(v0); v1 = tanhf(v1); }
        *reinterpret_cast<float2*>(&C[(size_t)r * (size_t)ldc + cc]) =
            make_float2(v0, v1);
    }
}

// ---------------------------------------------------------------------------
// Attention phase (batch = explicit index). R11-proven internals.
// ---------------------------------------------------------------------------
__device__ void attention_phase(char* dsmc,
                                const float* __restrict__ contexts,
                                const float* __restrict__ gamma,
                                half* __restrict__ ctxh,
                                half* __restrict__ ctxl, int b)
{
    float* sg     = reinterpret_cast<float*>(dsmc);
    float* sw     = sg + HH;
    float* red    = sw + SS;
    float* s_stat = red + 8;

    const int tid  = threadIdx.x;
    const int lane = tid & 31;
    const int warp = tid >> 5;
    const float* cb = contexts + (size_t)b * SS * HH;

    for (int j = tid; j < HH; j += 256) sg[j] = __ldcg(&gamma[(size_t)b * HH + j]);
    __syncthreads();

    for (int s = warp; s < SS; s += 8) {
        const float* cr = cb + (size_t)s * HH;
        float sum = 0.0f;
#pragma unroll 4
        for (int j = lane * 4; j < HH; j += 128) {
            float4 v = *reinterpret_cast<const float4*>(&cr[j]);
            sum = fmaf(v.x, sg[j], sum);
            sum = fmaf(v.y, sg[j + 1], sum);
            sum = fmaf(v.z, sg[j + 2], sum);
            sum = fmaf(v.w, sg[j + 3], sum);
        }
#pragma unroll
        for (int off = 16; off; off >>= 1)
            sum += __shfl_xor_sync(0xffffffffu, sum, off);
        if (lane == 0) sw[s] = sum;
    }
    __syncthreads();

    const float v = (tid < SS) ? sw[tid] : -3.4e38f;
    float m = v;
#pragma unroll
    for (int off = 16; off; off >>= 1)
        m = fmaxf(m, __shfl_xor_sync(0xffffffffu, m, off));
    if (lane == 0) red[warp] = m;
    __syncthreads();
    if (tid == 0) {
        float mm = red[0];
        for (int w2 = 1; w2 < 8; w2++) mm = fmaxf(mm, red[w2]);
        *s_stat = mm;
    }
    __syncthreads();
    const float bm = *s_stat;
    const float e = (tid < SS) ? __expf(v - bm) : 0.0f;
    float s2 = e;
#pragma unroll
    for (int off = 16; off; off >>= 1)
        s2 += __shfl_xor_sync(0xffffffffu, s2, off);
    if (lane == 0) red[warp] = s2;
    __syncthreads();
    if (tid == 0) {
        float t = 0.0f;
        for (int w2 = 0; w2 < 8; w2++) t += red[w2];
        *s_stat = 1.0f / t;
    }
    __syncthreads();
    if (tid < SS) sw[tid] = e * (*s_stat);
    __syncthreads();

    float acc[4] = {0.0f, 0.0f, 0.0f, 0.0f};
    for (int s = 0; s < SS; s++) {
        const float w = sw[s];
        const float* cr = cb + (size_t)s * HH;
#pragma unroll
        for (int q = 0; q < 4; q++)
            acc[q] = fmaf(w, cr[tid + q * 256], acc[q]);
    }
#pragma unroll
    for (int q = 0; q < 4; q++) {
        const int idx = b * HH + tid + q * 256;
        split16(acc[q], &ctxh[idx], &ctxl[idx]);
    }
}

// ---------------------------------------------------------------------------
// Persistent kernel, two async groups:
//  A (blocks 0-63):  P1(t), barA, [wait cB>=64(t-1)], P2(t), barA, bump cA
//  B (blocks 64-127): [wait cA>=64(t+1)], P3 x2, barB, P4 x2, barB, P5 x2, bump cB
// h1 pairs double-buffered by parity; B(t) reads parity t&1, A P2(t) writes it
// (overwrite at t+2 gated by cB). out[] written by B; hT/cT by A.
// ---------------------------------------------------------------------------
__global__ __launch_bounds__(256)
void persistent_kernel(const float* __restrict__ b_ih1,
                       const float* __restrict__ b_hh1,
                       const float* __restrict__ attb,
                       const float* __restrict__ outb,
                       const float* __restrict__ contexts,
                       float* __restrict__ out)
{
    extern __shared__ __align__(16) char dsm[];
    const int bid = blockIdx.x;

    if (bid < 64) {
        // ------------------- Group A: recurrent chain -------------------
        unsigned int tA = 0;
        for (int t = 0; t < TT; t++) {
            // P1: layer-0 gates + cell
            gates64_phase(dsm, bid,
                          g_h0h, g_h0l, g_Whh0h, g_Whh0l, HH,
                          nullptr, nullptr, nullptr, nullptr, 0,
                          nullptr, nullptr,
                          g_gin0 + (size_t)t * BB * FH,
                          g_h0, g_c0, g_h0h, g_h0l);
            tA += 64; group_sync(&g_barA, tA);

            // gate overwrite of h1p[t&1]: B must have finished step t-2
            if (t >= 2) wait_cnt(&g_cB, 64u * (unsigned)(t - 1));

            const int wp = t & 1;          // write parity
            half* wrh = wp ? g_h1h1 : g_h1h0;
            half* wrl = wp ? g_h1l1 : g_h1l0;
            const half* rdh = wp ? g_h1h0 : g_h1h1;   // parity of t-1
            const half* rdl = wp ? g_h1l0 : g_h1l1;

            // P2: layer-1 gates + cell (dual source)
            gates64_phase(dsm, bid,
                          g_h0h, g_h0l, g_Wih1h, g_Wih1l, HH,
                          rdh, rdl, g_Whh1h, g_Whh1l, HH,
                          b_ih1, b_hh1,
                          nullptr,
                          g_h1, g_c1, wrh, wrl);
            tA += 64; group_sync(&g_barA, tA);

            bump_cnt(&g_cA);
        }
        // final hT / cT (A-owned state)
        float* o2 = out + (size_t)TT * BB * FH / 4;   // TT*BB*HH
        for (int idx = bid * 256 + threadIdx.x; idx < BB * HH; idx += 64 * 256) {
            o2[idx]               = g_h0[idx];
            o2[BB * HH + idx]     = g_h1[idx];
            o2[2 * BB * HH + idx] = g_c0[idx];
            o2[3 * BB * HH + idx] = g_c1[idx];
        }
    } else {
        // ------------------- Group B: attention branch -------------------
        const int bb = bid - 64;
        unsigned int tB = 0;
        for (int t = 0; t < TT; t++) {
            wait_cnt(&g_cA, 64u * (unsigned)(t + 1));

            const int wp = t & 1;
            const half* rh = wp ? g_h1h1 : g_h1h0;
            const half* rl = wp ? g_h1l1 : g_h1l0;

            // P3: gamma = h1 @ attW^T + attb  (2 tiles per block)
            gemm32_phase(dsm, bb,
                         rh, rl, HH, g_attWh, g_attWl, HH, HH,
                         nullptr, nullptr, 0, nullptr, nullptr, 0, 0,
                         attb, g_gamma, HH, 0);
            gemm32_phase(dsm, bb + 64,
                         rh, rl, HH, g_attWh, g_attWl, HH, HH,
                         nullptr, nullptr, 0, nullptr, nullptr, 0, 0,
                         attb, g_gamma, HH, 0);
            tB += 64; group_sync(&g_barB, tB);

            // P4: attention (2 batches per block)
            attention_phase(dsm, contexts, g_gamma, g_ctxh, g_ctxl, bb);
            attention_phase(dsm, contexts, g_gamma, g_ctxh, g_ctxl, bb + 64);
            tB += 64; group_sync(&g_barB, tB);

            // P5: out[t] = tanh([ctx, h1] @ outW^T + outb)  (2 tiles)
            gemm32_phase(dsm, bb,
                         g_ctxh, g_ctxl, HH, g_outWh, g_outWl, 2 * HH, HH,
                         rh, rl, HH, g_outWh + HH, g_outWl + HH, 2 * HH, HH,
                         outb, out + (size_t)t * BB * HH, HH, 1);
            gemm32_phase(dsm, bb + 64,
                         g_ctxh, g_ctxl, HH, g_outWh, g_outWl, 2 * HH, HH,
                         rh, rl, HH, g_outWh + HH, g_outWl + HH, 2 * HH, HH,
                         outb, out + (size_t)t * BB * HH, HH, 1);

            bump_cnt(&g_cB);
        }
    }
}

// ---------------------------------------------------------------------------
// Launch: 3 kernels, single stream.
// ---------------------------------------------------------------------------
extern "C" void kernel_launch(void* const* d_in, const int* in_sizes, int n_in,
                              void* d_out, int out_size)
{
    (void)in_sizes; (void)n_in; (void)out_size;

    const int*   inputs   = (const int*)  d_in[0];
    const float* h0       = (const float*)d_in[1];
    const float* c0       = (const float*)d_in[2];
    const float* contexts = (const float*)d_in[3];
    const float* emb      = (const float*)d_in[4];
    const float* W_ih0    = (const float*)d_in[5];
    const float* W_hh0    = (const float*)d_in[6];
    const float* b_ih0    = (const float*)d_in[7];
    const float* b_hh0    = (const float*)d_in[8];
    const float* W_ih1    = (const float*)d_in[9];
    const float* W_hh1    = (const float*)d_in[10];
    const float* b_ih1    = (const float*)d_in[11];
    const float* b_hh1    = (const float*)d_in[12];
    const float* attW     = (const float*)d_in[13];
    const float* attb     = (const float*)d_in[14];
    const float* outW     = (const float*)d_in[15];
    const float* outb     = (const float*)d_in[16];
    float* out = (float*)d_out;

    constexpr int GSMEM = 4 * 12288;   // 49152 (gates64 stride x 4 stages)
    static bool init_done = false;
    if (!init_done) {
        cudaFuncSetAttribute(persistent_kernel,
                             cudaFuncAttributeMaxDynamicSharedMemorySize, GSMEM);
        init_done = true;
    }

    prologue_kernel<<<1184, 256>>>(emb, W_ih0, W_hh0, W_ih1, W_hh1,
                                   attW, outW, h0, c0);
    {
        dim3 grid(FH / 32, (TT * BB) / 64);
        gin0_gemm_kernel<<<grid, 128>>>(inputs, b_ih0, b_hh0);
    }
    persistent_kernel<<<128, 256, GSMEM>>>(b_ih1, b_hh1, attb, outb,
                                           contexts, out);
}